// round 1
// baseline (speedup 1.0000x reference)
#include <cuda_runtime.h>
#include <math.h>

// Fixed problem shape
#define BB 2
#define SEQ 2048
#define DIM 1024
#define NH 16
#define HD 64

// ---------------- scratch (device globals; no allocations allowed) ----------
__device__ float g_q[BB * SEQ * DIM];
__device__ float g_k[BB * SEQ * DIM];
__device__ float g_v[BB * SEQ * DIM];
__device__ float g_g[BB * SEQ * DIM];     // sigmoid gate
__device__ float g_att[BB * SEQ * DIM];   // gated attention output (pre O-proj)
__device__ float g_P[(size_t)BB * NH * SEQ * SEQ]; // scores/probs, 512 MB

// ---------------- generic GEMM: C = A[M,K] @ W[K,N] + bias, opt sigmoid -----
// BM=128, BN=128, BK=16, 256 threads, 8x8 per thread. M%128==0, N%128==0, K%16==0.
__global__ __launch_bounds__(256) void gemm_bias_act(
    const float* __restrict__ A, const float* __restrict__ W,
    const float* __restrict__ bias, float* __restrict__ C,
    int M, int N, int Kdim, int act)
{
    __shared__ float As[16][128];
    __shared__ float Bs[16][128];
    int tid = threadIdx.x;
    int tx = tid & 15, ty = tid >> 4;
    int m0 = blockIdx.y * 128, n0 = blockIdx.x * 128;

    float acc[8][8];
#pragma unroll
    for (int i = 0; i < 8; i++)
#pragma unroll
        for (int j = 0; j < 8; j++) acc[i][j] = 0.f;

    for (int k0 = 0; k0 < Kdim; k0 += 16) {
        // A tile: 128 rows x 16 cols -> As[k][m]
#pragma unroll
        for (int it = 0; it < 2; it++) {
            int idx = tid + 256 * it;        // 0..511
            int row = idx >> 2;              // 0..127
            int c4 = (idx & 3) * 4;          // 0,4,8,12
            float4 v = *reinterpret_cast<const float4*>(
                &A[(size_t)(m0 + row) * Kdim + k0 + c4]);
            As[c4 + 0][row] = v.x; As[c4 + 1][row] = v.y;
            As[c4 + 2][row] = v.z; As[c4 + 3][row] = v.w;
        }
        // W tile: 16 rows x 128 cols -> Bs[k][n]
#pragma unroll
        for (int it = 0; it < 2; it++) {
            int idx = tid + 256 * it;
            int row = idx >> 5;              // 0..15
            int c4 = (idx & 31) * 4;         // 0..124
            float4 v = *reinterpret_cast<const float4*>(
                &W[(size_t)(k0 + row) * N + n0 + c4]);
            *reinterpret_cast<float4*>(&Bs[row][c4]) = v;
        }
        __syncthreads();
#pragma unroll
        for (int k = 0; k < 16; k++) {
            float4 a0 = *reinterpret_cast<const float4*>(&As[k][ty * 8]);
            float4 a1 = *reinterpret_cast<const float4*>(&As[k][ty * 8 + 4]);
            float4 b0 = *reinterpret_cast<const float4*>(&Bs[k][tx * 8]);
            float4 b1 = *reinterpret_cast<const float4*>(&Bs[k][tx * 8 + 4]);
            float a[8] = {a0.x, a0.y, a0.z, a0.w, a1.x, a1.y, a1.z, a1.w};
            float b[8] = {b0.x, b0.y, b0.z, b0.w, b1.x, b1.y, b1.z, b1.w};
#pragma unroll
            for (int i = 0; i < 8; i++)
#pragma unroll
                for (int j = 0; j < 8; j++) acc[i][j] += a[i] * b[j];
        }
        __syncthreads();
    }

#pragma unroll
    for (int i = 0; i < 8; i++) {
        int m = m0 + ty * 8 + i;
#pragma unroll
        for (int j = 0; j < 8; j++) {
            int n = n0 + tx * 8 + j;
            float v = acc[i][j] + bias[n];
            if (act == 1) v = 1.f / (1.f + expf(-v));
            C[(size_t)m * N + n] = v;
        }
    }
}

// ---------------- scores: P[b,h,q,k] = Q.Kt/8 + mask + pad ------------------
__global__ __launch_bounds__(256) void scores_kernel(
    const float* __restrict__ Q, const float* __restrict__ K,
    const float* __restrict__ mask, const unsigned char* __restrict__ pad,
    float* __restrict__ P)
{
    int bh = blockIdx.z;
    int b = bh / NH, h = bh % NH;
    const float* Qb = Q + (size_t)b * SEQ * DIM + h * HD;
    const float* Kb = K + (size_t)b * SEQ * DIM + h * HD;

    __shared__ float Qs[16][128];
    __shared__ float Ks[16][128];
    int tid = threadIdx.x;
    int tx = tid & 15, ty = tid >> 4;
    int q0 = blockIdx.y * 128, kk0 = blockIdx.x * 128;

    float acc[8][8];
#pragma unroll
    for (int i = 0; i < 8; i++)
#pragma unroll
        for (int j = 0; j < 8; j++) acc[i][j] = 0.f;

    for (int e0 = 0; e0 < HD; e0 += 16) {
#pragma unroll
        for (int it = 0; it < 2; it++) {
            int idx = tid + 256 * it;
            int row = idx >> 2;
            int c4 = (idx & 3) * 4;
            float4 v = *reinterpret_cast<const float4*>(
                &Qb[(size_t)(q0 + row) * DIM + e0 + c4]);
            Qs[c4 + 0][row] = v.x; Qs[c4 + 1][row] = v.y;
            Qs[c4 + 2][row] = v.z; Qs[c4 + 3][row] = v.w;
            float4 w = *reinterpret_cast<const float4*>(
                &Kb[(size_t)(kk0 + row) * DIM + e0 + c4]);
            Ks[c4 + 0][row] = w.x; Ks[c4 + 1][row] = w.y;
            Ks[c4 + 2][row] = w.z; Ks[c4 + 3][row] = w.w;
        }
        __syncthreads();
#pragma unroll
        for (int k = 0; k < 16; k++) {
            float4 a0 = *reinterpret_cast<const float4*>(&Qs[k][ty * 8]);
            float4 a1 = *reinterpret_cast<const float4*>(&Qs[k][ty * 8 + 4]);
            float4 b0 = *reinterpret_cast<const float4*>(&Ks[k][tx * 8]);
            float4 b1 = *reinterpret_cast<const float4*>(&Ks[k][tx * 8 + 4]);
            float a[8] = {a0.x, a0.y, a0.z, a0.w, a1.x, a1.y, a1.z, a1.w};
            float bb[8] = {b0.x, b0.y, b0.z, b0.w, b1.x, b1.y, b1.z, b1.w};
#pragma unroll
            for (int i = 0; i < 8; i++)
#pragma unroll
                for (int j = 0; j < 8; j++) acc[i][j] += a[i] * bb[j];
        }
        __syncthreads();
    }

    float* Pb = P + (size_t)bh * SEQ * SEQ;
    const float NEG_INF = __int_as_float(0xff800000);
#pragma unroll
    for (int i = 0; i < 8; i++) {
        int q = q0 + ty * 8 + i;
#pragma unroll
        for (int j = 0; j < 8; j++) {
            int kk = kk0 + tx * 8 + j;
            float v = acc[i][j] * 0.125f + mask[(size_t)q * SEQ + kk];
            if (pad[b * SEQ + kk]) v = NEG_INF;
            Pb[(size_t)q * SEQ + kk] = v;
        }
    }
}

// ---------------- row softmax in place --------------------------------------
__global__ __launch_bounds__(256) void softmax_kernel(float* __restrict__ P)
{
    size_t row = blockIdx.x;
    float* r = P + row * SEQ;
    int tid = threadIdx.x;
    float v[8];
    float mx = -3.4e38f;
#pragma unroll
    for (int i = 0; i < 8; i++) {
        v[i] = r[tid + 256 * i];
        mx = fmaxf(mx, v[i]);
    }
    __shared__ float red[256];
    red[tid] = mx; __syncthreads();
    for (int s = 128; s > 0; s >>= 1) {
        if (tid < s) red[tid] = fmaxf(red[tid], red[tid + s]);
        __syncthreads();
    }
    mx = red[0]; __syncthreads();
    float sum = 0.f;
#pragma unroll
    for (int i = 0; i < 8; i++) { v[i] = expf(v[i] - mx); sum += v[i]; }
    red[tid] = sum; __syncthreads();
    for (int s = 128; s > 0; s >>= 1) {
        if (tid < s) red[tid] += red[tid + s];
        __syncthreads();
    }
    float inv = 1.f / red[0];
#pragma unroll
    for (int i = 0; i < 8; i++) r[tid + 256 * i] = v[i] * inv;
}

// ---------------- avg over heads --------------------------------------------
__global__ __launch_bounds__(256) void avg_kernel(
    const float* __restrict__ P, float* __restrict__ avg)
{
    const size_t quarter = (size_t)SEQ * SEQ / 4;   // f4 per (b)
    size_t i = (size_t)blockIdx.x * blockDim.x + threadIdx.x;
    if (i >= (size_t)BB * quarter) return;
    size_t b = i / quarter;
    size_t rem = i % quarter;
    const float4* base = reinterpret_cast<const float4*>(P) + b * NH * quarter + rem;
    float4 s = {0.f, 0.f, 0.f, 0.f};
#pragma unroll
    for (int h = 0; h < NH; h++) {
        float4 t = base[(size_t)h * quarter];
        s.x += t.x; s.y += t.y; s.z += t.z; s.w += t.w;
    }
    s.x *= 0.0625f; s.y *= 0.0625f; s.z *= 0.0625f; s.w *= 0.0625f;
    reinterpret_cast<float4*>(avg)[i] = s;
}

// ---------------- PV + gate: out[b,s,h*64+e] = (P@V) * gate -----------------
__global__ __launch_bounds__(256) void pv_gate_kernel(
    const float* __restrict__ P, const float* __restrict__ V,
    const float* __restrict__ G, float* __restrict__ out)
{
    int bh = blockIdx.z;
    int b = bh / NH, h = bh % NH;
    const float* Pb = P + (size_t)bh * SEQ * SEQ;
    const float* Vb = V + (size_t)b * SEQ * DIM + h * HD;

    __shared__ float Ps[16][128];
    __shared__ float Vs[16][64];
    int tid = threadIdx.x;
    int tx = tid & 15, ty = tid >> 4;
    int q0 = blockIdx.y * 128;

    float acc[8][4];
#pragma unroll
    for (int i = 0; i < 8; i++)
#pragma unroll
        for (int j = 0; j < 4; j++) acc[i][j] = 0.f;

    for (int k0 = 0; k0 < SEQ; k0 += 16) {
#pragma unroll
        for (int it = 0; it < 2; it++) {
            int idx = tid + 256 * it;
            int row = idx >> 2;
            int c4 = (idx & 3) * 4;
            float4 p4 = *reinterpret_cast<const float4*>(
                &Pb[(size_t)(q0 + row) * SEQ + k0 + c4]);
            Ps[c4 + 0][row] = p4.x; Ps[c4 + 1][row] = p4.y;
            Ps[c4 + 2][row] = p4.z; Ps[c4 + 3][row] = p4.w;
        }
        {
            int row = tid >> 4;          // 0..15
            int c4 = (tid & 15) * 4;     // 0..60
            float4 v4 = *reinterpret_cast<const float4*>(
                &Vb[(size_t)(k0 + row) * DIM + c4]);
            *reinterpret_cast<float4*>(&Vs[row][c4]) = v4;
        }
        __syncthreads();
#pragma unroll
        for (int k = 0; k < 16; k++) {
            float4 a0 = *reinterpret_cast<const float4*>(&Ps[k][ty * 8]);
            float4 a1 = *reinterpret_cast<const float4*>(&Ps[k][ty * 8 + 4]);
            float4 b0 = *reinterpret_cast<const float4*>(&Vs[k][tx * 4]);
            float a[8] = {a0.x, a0.y, a0.z, a0.w, a1.x, a1.y, a1.z, a1.w};
            float bb[4] = {b0.x, b0.y, b0.z, b0.w};
#pragma unroll
            for (int i = 0; i < 8; i++)
#pragma unroll
                for (int j = 0; j < 4; j++) acc[i][j] += a[i] * bb[j];
        }
        __syncthreads();
    }

#pragma unroll
    for (int i = 0; i < 8; i++) {
        int q = q0 + ty * 8 + i;
        size_t base = ((size_t)b * SEQ + q) * DIM + h * HD + tx * 4;
#pragma unroll
        for (int j = 0; j < 4; j++)
            out[base + j] = acc[i][j] * G[base + j];
    }
}

// ---------------- launch -----------------------------------------------------
extern "C" void kernel_launch(void* const* d_in, const int* in_sizes, int n_in,
                              void* d_out, int out_size)
{
    (void)in_sizes; (void)n_in; (void)out_size;
    const float* x    = (const float*)d_in[0];
    const float* mask = (const float*)d_in[1];
    const unsigned char* pad = (const unsigned char*)d_in[2];
    const float* Wq = (const float*)d_in[3];
    const float* bq = (const float*)d_in[4];
    const float* Wk = (const float*)d_in[5];
    const float* bk = (const float*)d_in[6];
    const float* Wv = (const float*)d_in[7];
    const float* bv = (const float*)d_in[8];
    const float* Wg = (const float*)d_in[9];
    const float* bg = (const float*)d_in[10];
    const float* Wo = (const float*)d_in[11];
    const float* bo = (const float*)d_in[12];
    float* out = (float*)d_out;

    float *q, *k, *v, *g, *att, *P;
    cudaGetSymbolAddress((void**)&q, g_q);
    cudaGetSymbolAddress((void**)&k, g_k);
    cudaGetSymbolAddress((void**)&v, g_v);
    cudaGetSymbolAddress((void**)&g, g_g);
    cudaGetSymbolAddress((void**)&att, g_att);
    cudaGetSymbolAddress((void**)&P, g_P);

    const int M = BB * SEQ;                 // 4096
    dim3 gemmGrid(DIM / 128, M / 128);      // (8, 32)

    gemm_bias_act<<<gemmGrid, 256>>>(x, Wq, bq, q, M, DIM, DIM, 0);
    gemm_bias_act<<<gemmGrid, 256>>>(x, Wk, bk, k, M, DIM, DIM, 0);
    gemm_bias_act<<<gemmGrid, 256>>>(x, Wv, bv, v, M, DIM, DIM, 0);
    gemm_bias_act<<<gemmGrid, 256>>>(x, Wg, bg, g, M, DIM, DIM, 1);

    scores_kernel<<<dim3(SEQ / 128, SEQ / 128, BB * NH), 256>>>(q, k, mask, pad, P);
    softmax_kernel<<<BB * NH * SEQ, 256>>>(P);

    avg_kernel<<<(unsigned)((BB * (size_t)SEQ * SEQ / 4 + 255) / 256), 256>>>(
        P, out + (size_t)BB * SEQ * DIM);

    pv_gate_kernel<<<dim3(1, SEQ / 128, BB * NH), 256>>>(P, v, g, att);

    gemm_bias_act<<<gemmGrid, 256>>>(att, Wo, bo, out, M, DIM, DIM, 0);
}

// round 3
// speedup vs baseline: 1.4230x; 1.4230x over previous
#include <cuda_runtime.h>
#include <cuda_bf16.h>
#include <math.h>
#include <stdint.h>

// Fixed problem shape
#define BB 2
#define SEQ 2048
#define DIM 1024
#define NH 16
#define HD 64
#define MTOT (BB * SEQ)            // 4096
#define K3 (3 * DIM)               // 3072 (split-K layout)
#define NSTG 48                    // K3 / 64

// ---------------- scratch (device globals; no allocations allowed) ----------
__device__ float g_qkvg[4ull * MTOT * DIM];            // q,k,v,gate fp32
__device__ float g_att[(size_t)MTOT * DIM];            // gated attn out
__device__ float g_P[(size_t)BB * NH * SEQ * SEQ];     // probs, 512 MB
__device__ __nv_bfloat16 g_a3[(size_t)MTOT * K3];      // [Ah|Ah|Al]
__device__ __nv_bfloat16 g_w3[5ull * DIM * K3];        // per-weight [Wh|Wl|Wh] rows (N-major)

// ======================= helpers ===========================================
__device__ __forceinline__ uint32_t smem_u32(const void* p) {
    uint32_t a;
    asm("{ .reg .u64 t; cvta.to.shared.u64 t, %1; cvt.u32.u64 %0, t; }"
        : "=r"(a) : "l"(p));
    return a;
}
__device__ __forceinline__ uint32_t swz128(uint32_t o) { return o ^ ((o >> 3) & 0x70); }

__device__ __forceinline__ void cp_async16(uint32_t dst, const void* src) {
    asm volatile("cp.async.cg.shared.global [%0], [%1], 16;" :: "r"(dst), "l"(src));
}
#define CP_COMMIT() asm volatile("cp.async.commit_group;" ::: "memory")
#define CP_WAIT(n)  asm volatile("cp.async.wait_group %0;" :: "n"(n) : "memory")

__device__ __forceinline__ void ldmx4(uint32_t* r, uint32_t addr) {
    asm volatile("ldmatrix.sync.aligned.m8n8.x4.shared.b16 {%0,%1,%2,%3}, [%4];"
                 : "=r"(r[0]), "=r"(r[1]), "=r"(r[2]), "=r"(r[3]) : "r"(addr));
}
__device__ __forceinline__ void mma16816(float* c, const uint32_t* a, const uint32_t* b) {
    asm volatile(
        "mma.sync.aligned.m16n8k16.row.col.f32.bf16.bf16.f32 "
        "{%0,%1,%2,%3}, {%4,%5,%6,%7}, {%8,%9}, {%0,%1,%2,%3};"
        : "+f"(c[0]), "+f"(c[1]), "+f"(c[2]), "+f"(c[3])
        : "r"(a[0]), "r"(a[1]), "r"(a[2]), "r"(a[3]), "r"(b[0]), "r"(b[1]));
}

// ======================= split / transpose conversion ======================
// x fp32 [M,DIM] -> A3 bf16 [M,K3] rows = [hi | hi | lo]
__global__ __launch_bounds__(256) void split3_f32(const float* __restrict__ x,
                                                  __nv_bfloat16* __restrict__ A3) {
    size_t i = ((size_t)blockIdx.x * 256 + threadIdx.x) * 4;
    size_t m = i / DIM, k = i % DIM;
    float4 v = *reinterpret_cast<const float4*>(x + i);
    __nv_bfloat16 h0 = __float2bfloat16(v.x), h1 = __float2bfloat16(v.y);
    __nv_bfloat16 h2 = __float2bfloat16(v.z), h3 = __float2bfloat16(v.w);
    __nv_bfloat162 hA(h0, h1), hB(h2, h3);
    __nv_bfloat162 lA(__float2bfloat16(v.x - __bfloat162float(h0)),
                      __float2bfloat16(v.y - __bfloat162float(h1)));
    __nv_bfloat162 lB(__float2bfloat16(v.z - __bfloat162float(h2)),
                      __float2bfloat16(v.w - __bfloat162float(h3)));
    __nv_bfloat16* row = A3 + m * K3;
    *reinterpret_cast<__nv_bfloat162*>(row + k) = hA;
    *reinterpret_cast<__nv_bfloat162*>(row + k + 2) = hB;
    *reinterpret_cast<__nv_bfloat162*>(row + DIM + k) = hA;
    *reinterpret_cast<__nv_bfloat162*>(row + DIM + k + 2) = hB;
    *reinterpret_cast<__nv_bfloat162*>(row + 2 * DIM + k) = lA;
    *reinterpret_cast<__nv_bfloat162*>(row + 2 * DIM + k + 2) = lB;
}

// W[k][n] fp32 -> W3[n] rows (K3) = [hi | lo | hi] of W[:,n]
__global__ __launch_bounds__(1024) void transpose_split3(const float* __restrict__ W,
                                                         __nv_bfloat16* __restrict__ W3) {
    __shared__ float t[32][33];
    int tx = threadIdx.x, ty = threadIdx.y;
    int k0 = blockIdx.y * 32, n0 = blockIdx.x * 32;
    t[ty][tx] = W[(size_t)(k0 + ty) * DIM + n0 + tx];
    __syncthreads();
    float v = t[tx][ty];                       // = W[k0+tx][n0+ty]
    __nv_bfloat16 h = __float2bfloat16(v);
    __nv_bfloat16 l = __float2bfloat16(v - __bfloat162float(h));
    __nv_bfloat16* row = W3 + (size_t)(n0 + ty) * K3;
    row[k0 + tx] = h;
    row[DIM + k0 + tx] = l;
    row[2 * DIM + k0 + tx] = h;
}

// ======================= HMMA split-bf16 GEMM ==============================
// C[z][4096,1024] = A3 @ W3_z^T + bias_z (opt sigmoid). CTA 128x128, BK=64.
#define GEMM_SMEM (64 * 1024)

__global__ __launch_bounds__(256, 2) void gemm_hmma(
    const __nv_bfloat16* __restrict__ A3, const __nv_bfloat16* __restrict__ W3base,
    const float* b0, const float* b1, const float* b2, const float* b3,
    float* __restrict__ outBase, int sigmoidZ)
{
    extern __shared__ char smem[];
    const uint32_t sb = smem_u32(smem);
    const int tid = threadIdx.x;
    const int wid = tid >> 5, lane = tid & 31;
    const int wm = wid & 3, wn = wid >> 2;   // warp tile: rows wm*32, cols wn*64
    const int z = blockIdx.z;
    const int m0 = blockIdx.y * 128, n0 = blockIdx.x * 128;

    const __nv_bfloat16* W3 = W3base + (size_t)z * DIM * K3;
    const float* bias = (z == 0) ? b0 : (z == 1) ? b1 : (z == 2) ? b2 : b3;
    float* out = outBase + (size_t)z * MTOT * DIM;
    const bool doSig = (z == sigmoidZ);

    const char* gA = (const char*)(A3 + (size_t)m0 * K3);
    const char* gB = (const char*)(W3 + (size_t)n0 * K3);

    auto load_stage = [&](int s) {
        const uint32_t base = sb + (s & 1) * 32768;
        const int kb = s * 128;                // byte offset along K3
#pragma unroll
        for (int i = 0; i < 4; i++) {
            int c = tid + 256 * i;
            int row = c >> 3, cb = (c & 7) * 16;
            uint32_t d = swz128(row * 128 + cb);
            size_t src = (size_t)row * (K3 * 2) + kb + cb;
            cp_async16(base + d, gA + src);
            cp_async16(base + 16384 + d, gB + src);
        }
        CP_COMMIT();
    };

    float acc[2][8][4];
#pragma unroll
    for (int mi = 0; mi < 2; mi++)
#pragma unroll
        for (int ni = 0; ni < 8; ni++)
#pragma unroll
            for (int j = 0; j < 4; j++) acc[mi][ni][j] = 0.f;

    load_stage(0);
    load_stage(1);

    for (int s = 0; s < NSTG; s++) {
        if (s == NSTG - 1) { CP_WAIT(0); } else { CP_WAIT(1); }
        __syncthreads();
        const uint32_t abase = sb + (s & 1) * 32768;
        const uint32_t bbase = abase + 16384;
#pragma unroll
        for (int ki = 0; ki < 4; ki++) {
            uint32_t a[2][4];
#pragma unroll
            for (int mi = 0; mi < 2; mi++) {
                int row = wm * 32 + mi * 16 + (lane & 15);
                int kb = ki * 32 + ((lane >> 4) << 4);
                ldmx4(a[mi], abase + swz128(row * 128 + kb));
            }
#pragma unroll
            for (int pi = 0; pi < 4; pi++) {
                int nrow = wn * 64 + pi * 16 + ((lane >> 4) << 3) + (lane & 7);
                int kb = ki * 32 + ((lane >> 3) & 1) * 16;
                uint32_t b[4];
                ldmx4(b, bbase + swz128(nrow * 128 + kb));
#pragma unroll
                for (int mi = 0; mi < 2; mi++) {
                    mma16816(acc[mi][2 * pi], a[mi], b);
                    mma16816(acc[mi][2 * pi + 1], a[mi], b + 2);
                }
            }
        }
        __syncthreads();
        if (s + 2 < NSTG) load_stage(s + 2);
    }

    // ---- epilogue ----
    const int rbase = m0 + wm * 32;
    const int cbase = n0 + wn * 64;
#pragma unroll
    for (int mi = 0; mi < 2; mi++) {
#pragma unroll
        for (int ni = 0; ni < 8; ni++) {
            int row = rbase + mi * 16 + (lane >> 2);
            int col = cbase + ni * 8 + (lane & 3) * 2;
            float bx = bias[col], by = bias[col + 1];
            float2 v0 = {acc[mi][ni][0] + bx, acc[mi][ni][1] + by};
            float2 v1 = {acc[mi][ni][2] + bx, acc[mi][ni][3] + by};
            if (doSig) {
                v0.x = 1.f / (1.f + expf(-v0.x)); v0.y = 1.f / (1.f + expf(-v0.y));
                v1.x = 1.f / (1.f + expf(-v1.x)); v1.y = 1.f / (1.f + expf(-v1.y));
            }
            *reinterpret_cast<float2*>(&out[(size_t)row * DIM + col]) = v0;
            *reinterpret_cast<float2*>(&out[(size_t)(row + 8) * DIM + col]) = v1;
        }
    }
}

// ---------------- scores: P[b,h,q,k] = Q.Kt/8 + mask + pad ------------------
__global__ __launch_bounds__(256) void scores_kernel(
    const float* __restrict__ Q, const float* __restrict__ K,
    const float* __restrict__ mask, const unsigned char* __restrict__ pad,
    float* __restrict__ P)
{
    int bh = blockIdx.z;
    int b = bh / NH, h = bh % NH;
    const float* Qb = Q + (size_t)b * SEQ * DIM + h * HD;
    const float* Kb = K + (size_t)b * SEQ * DIM + h * HD;

    __shared__ float Qs[16][128];
    __shared__ float Ks[16][128];
    int tid = threadIdx.x;
    int tx = tid & 15, ty = tid >> 4;
    int q0 = blockIdx.y * 128, kk0 = blockIdx.x * 128;

    float acc[8][8];
#pragma unroll
    for (int i = 0; i < 8; i++)
#pragma unroll
        for (int j = 0; j < 8; j++) acc[i][j] = 0.f;

    for (int e0 = 0; e0 < HD; e0 += 16) {
#pragma unroll
        for (int it = 0; it < 2; it++) {
            int idx = tid + 256 * it;
            int row = idx >> 2;
            int c4 = (idx & 3) * 4;
            float4 v = *reinterpret_cast<const float4*>(
                &Qb[(size_t)(q0 + row) * DIM + e0 + c4]);
            Qs[c4 + 0][row] = v.x; Qs[c4 + 1][row] = v.y;
            Qs[c4 + 2][row] = v.z; Qs[c4 + 3][row] = v.w;
            float4 w = *reinterpret_cast<const float4*>(
                &Kb[(size_t)(kk0 + row) * DIM + e0 + c4]);
            Ks[c4 + 0][row] = w.x; Ks[c4 + 1][row] = w.y;
            Ks[c4 + 2][row] = w.z; Ks[c4 + 3][row] = w.w;
        }
        __syncthreads();
#pragma unroll
        for (int k = 0; k < 16; k++) {
            float4 a0 = *reinterpret_cast<const float4*>(&Qs[k][ty * 8]);
            float4 a1 = *reinterpret_cast<const float4*>(&Qs[k][ty * 8 + 4]);
            float4 b0 = *reinterpret_cast<const float4*>(&Ks[k][tx * 8]);
            float4 b1 = *reinterpret_cast<const float4*>(&Ks[k][tx * 8 + 4]);
            float a[8] = {a0.x, a0.y, a0.z, a0.w, a1.x, a1.y, a1.z, a1.w};
            float bb[8] = {b0.x, b0.y, b0.z, b0.w, b1.x, b1.y, b1.z, b1.w};
#pragma unroll
            for (int i = 0; i < 8; i++)
#pragma unroll
                for (int j = 0; j < 8; j++) acc[i][j] += a[i] * bb[j];
        }
        __syncthreads();
    }

    float* Pb = P + (size_t)bh * SEQ * SEQ;
    const float NEG_INF = __int_as_float(0xff800000);
#pragma unroll
    for (int i = 0; i < 8; i++) {
        int q = q0 + ty * 8 + i;
#pragma unroll
        for (int j = 0; j < 8; j++) {
            int kk = kk0 + tx * 8 + j;
            float v = acc[i][j] * 0.125f + mask[(size_t)q * SEQ + kk];
            if (pad[b * SEQ + kk]) v = NEG_INF;
            Pb[(size_t)q * SEQ + kk] = v;
        }
    }
}

// ---------------- row softmax in place --------------------------------------
__global__ __launch_bounds__(256) void softmax_kernel(float* __restrict__ P)
{
    size_t row = blockIdx.x;
    float* r = P + row * SEQ;
    int tid = threadIdx.x;
    float v[8];
    float mx = -3.4e38f;
#pragma unroll
    for (int i = 0; i < 8; i++) {
        v[i] = r[tid + 256 * i];
        mx = fmaxf(mx, v[i]);
    }
    __shared__ float red[256];
    red[tid] = mx; __syncthreads();
    for (int s = 128; s > 0; s >>= 1) {
        if (tid < s) red[tid] = fmaxf(red[tid], red[tid + s]);
        __syncthreads();
    }
    mx = red[0]; __syncthreads();
    float sum = 0.f;
#pragma unroll
    for (int i = 0; i < 8; i++) { v[i] = expf(v[i] - mx); sum += v[i]; }
    red[tid] = sum; __syncthreads();
    for (int s = 128; s > 0; s >>= 1) {
        if (tid < s) red[tid] += red[tid + s];
        __syncthreads();
    }
    float inv = 1.f / red[0];
#pragma unroll
    for (int i = 0; i < 8; i++) r[tid + 256 * i] = v[i] * inv;
}

// ---------------- avg over heads --------------------------------------------
__global__ __launch_bounds__(256) void avg_kernel(
    const float* __restrict__ P, float* __restrict__ avg)
{
    const size_t quarter = (size_t)SEQ * SEQ / 4;
    size_t i = (size_t)blockIdx.x * blockDim.x + threadIdx.x;
    if (i >= (size_t)BB * quarter) return;
    size_t b = i / quarter;
    size_t rem = i % quarter;
    const float4* base = reinterpret_cast<const float4*>(P) + b * NH * quarter + rem;
    float4 s = {0.f, 0.f, 0.f, 0.f};
#pragma unroll
    for (int h = 0; h < NH; h++) {
        float4 t = base[(size_t)h * quarter];
        s.x += t.x; s.y += t.y; s.z += t.z; s.w += t.w;
    }
    s.x *= 0.0625f; s.y *= 0.0625f; s.z *= 0.0625f; s.w *= 0.0625f;
    reinterpret_cast<float4*>(avg)[i] = s;
}

// ---------------- PV + gate --------------------------------------------------
__global__ __launch_bounds__(256) void pv_gate_kernel(
    const float* __restrict__ P, const float* __restrict__ V,
    const float* __restrict__ G, float* __restrict__ out)
{
    int bh = blockIdx.z;
    int b = bh / NH, h = bh % NH;
    const float* Pb = P + (size_t)bh * SEQ * SEQ;
    const float* Vb = V + (size_t)b * SEQ * DIM + h * HD;

    __shared__ float Ps[16][128];
    __shared__ float Vs[16][64];
    int tid = threadIdx.x;
    int tx = tid & 15, ty = tid >> 4;
    int q0 = blockIdx.y * 128;

    float acc[8][4];
#pragma unroll
    for (int i = 0; i < 8; i++)
#pragma unroll
        for (int j = 0; j < 4; j++) acc[i][j] = 0.f;

    for (int k0 = 0; k0 < SEQ; k0 += 16) {
#pragma unroll
        for (int it = 0; it < 2; it++) {
            int idx = tid + 256 * it;
            int row = idx >> 2;
            int c4 = (idx & 3) * 4;
            float4 p4 = *reinterpret_cast<const float4*>(
                &Pb[(size_t)(q0 + row) * SEQ + k0 + c4]);
            Ps[c4 + 0][row] = p4.x; Ps[c4 + 1][row] = p4.y;
            Ps[c4 + 2][row] = p4.z; Ps[c4 + 3][row] = p4.w;
        }
        {
            int row = tid >> 4;
            int c4 = (tid & 15) * 4;
            float4 v4 = *reinterpret_cast<const float4*>(
                &Vb[(size_t)(k0 + row) * DIM + c4]);
            *reinterpret_cast<float4*>(&Vs[row][c4]) = v4;
        }
        __syncthreads();
#pragma unroll
        for (int k = 0; k < 16; k++) {
            float4 a0 = *reinterpret_cast<const float4*>(&Ps[k][ty * 8]);
            float4 a1 = *reinterpret_cast<const float4*>(&Ps[k][ty * 8 + 4]);
            float4 b0 = *reinterpret_cast<const float4*>(&Vs[k][tx * 4]);
            float a[8] = {a0.x, a0.y, a0.z, a0.w, a1.x, a1.y, a1.z, a1.w};
            float bb[4] = {b0.x, b0.y, b0.z, b0.w};
#pragma unroll
            for (int i = 0; i < 8; i++)
#pragma unroll
                for (int j = 0; j < 4; j++) acc[i][j] += a[i] * bb[j];
        }
        __syncthreads();
    }

#pragma unroll
    for (int i = 0; i < 8; i++) {
        int q = q0 + ty * 8 + i;
        size_t base = ((size_t)b * SEQ + q) * DIM + h * HD + tx * 4;
#pragma unroll
        for (int j = 0; j < 4; j++)
            out[base + j] = acc[i][j] * G[base + j];
    }
}

// ---------------- launch -----------------------------------------------------
extern "C" void kernel_launch(void* const* d_in, const int* in_sizes, int n_in,
                              void* d_out, int out_size)
{
    (void)in_sizes; (void)n_in; (void)out_size;
    const float* x    = (const float*)d_in[0];
    const float* mask = (const float*)d_in[1];
    const unsigned char* pad = (const unsigned char*)d_in[2];
    const float* Wq = (const float*)d_in[3];
    const float* bq = (const float*)d_in[4];
    const float* Wk = (const float*)d_in[5];
    const float* bk = (const float*)d_in[6];
    const float* Wv = (const float*)d_in[7];
    const float* bv = (const float*)d_in[8];
    const float* Wg = (const float*)d_in[9];
    const float* bg = (const float*)d_in[10];
    const float* Wo = (const float*)d_in[11];
    const float* bo = (const float*)d_in[12];
    float* out = (float*)d_out;

    float *qkvg, *att, *P;
    __nv_bfloat16 *a3, *w3;
    cudaGetSymbolAddress((void**)&qkvg, g_qkvg);
    cudaGetSymbolAddress((void**)&att, g_att);
    cudaGetSymbolAddress((void**)&P, g_P);
    cudaGetSymbolAddress((void**)&a3, g_a3);
    cudaGetSymbolAddress((void**)&w3, g_w3);

    static bool attrSet = false;
    if (!attrSet) {
        cudaFuncSetAttribute(gemm_hmma, cudaFuncAttributeMaxDynamicSharedMemorySize,
                             GEMM_SMEM);
        attrSet = true;
    }

    const float* q = qkvg;
    const float* k = qkvg + 1ull * MTOT * DIM;
    const float* v = qkvg + 2ull * MTOT * DIM;
    const float* g = qkvg + 3ull * MTOT * DIM;

    // 1) split x, transpose+split weights into K3 layout
    split3_f32<<<(MTOT * DIM) / 1024, 256>>>(x, a3);
    dim3 tgrid(DIM / 32, DIM / 32);
    transpose_split3<<<tgrid, dim3(32, 32)>>>(Wq, w3 + 0ull * DIM * K3);
    transpose_split3<<<tgrid, dim3(32, 32)>>>(Wk, w3 + 1ull * DIM * K3);
    transpose_split3<<<tgrid, dim3(32, 32)>>>(Wv, w3 + 2ull * DIM * K3);
    transpose_split3<<<tgrid, dim3(32, 32)>>>(Wg, w3 + 3ull * DIM * K3);
    transpose_split3<<<tgrid, dim3(32, 32)>>>(Wo, w3 + 4ull * DIM * K3);

    // 2) fused q,k,v,gate projections (HMMA)
    gemm_hmma<<<dim3(DIM / 128, MTOT / 128, 4), 256, GEMM_SMEM>>>(
        a3, w3, bq, bk, bv, bg, qkvg, 3);

    // 3) attention core (fp32)
    scores_kernel<<<dim3(SEQ / 128, SEQ / 128, BB * NH), 256>>>(q, k, mask, pad, P);
    softmax_kernel<<<BB * NH * SEQ, 256>>>(P);
    avg_kernel<<<(unsigned)((BB * (size_t)SEQ * SEQ / 4 + 255) / 256), 256>>>(
        P, out + (size_t)MTOT * DIM);
    pv_gate_kernel<<<dim3(1, SEQ / 128, BB * NH), 256>>>(P, v, g, att);

    // 4) O projection (HMMA)
    split3_f32<<<(MTOT * DIM) / 1024, 256>>>(att, a3);
    gemm_hmma<<<dim3(DIM / 128, MTOT / 128, 1), 256, GEMM_SMEM>>>(
        a3, w3 + 4ull * DIM * K3, bo, bo, bo, bo, out, -1);
}

// round 4
// speedup vs baseline: 2.7704x; 1.9469x over previous
#include <cuda_runtime.h>
#include <cuda_bf16.h>
#include <math.h>
#include <stdint.h>

// Fixed problem shape
#define BB 2
#define SEQ 2048
#define DIM 1024
#define NH 16
#define HD 64
#define MTOT (BB * SEQ)            // 4096
#define K3 (3 * DIM)               // 3072 (split-K layout)
#define NSTG 48                    // K3 / 64
#define NBH (BB * NH)              // 32

// ---------------- scratch (device globals; no allocations allowed) ----------
__device__ float g_qkvg[4ull * MTOT * DIM];            // q,k,v,gate fp32
__device__ float g_att[(size_t)MTOT * DIM];            // gated attn out
__device__ float g_P[(size_t)NBH * SEQ * SEQ];         // E = exp(scores), 512 MB
__device__ float g_rinv[(size_t)NBH * SEQ];            // 1/rowsum
__device__ __nv_bfloat16 g_a3[(size_t)MTOT * K3];      // [Ah|Ah|Al]
__device__ __nv_bfloat16 g_w3[5ull * DIM * K3];        // [Wh|Wl|Wh] N-major
__device__ __nv_bfloat16 g_qkh[3ull * 2 * NBH * SEQ * HD]; // q,k,v per-head hi/lo

// ======================= helpers ===========================================
__device__ __forceinline__ uint32_t smem_u32(const void* p) {
    uint32_t a;
    asm("{ .reg .u64 t; cvta.to.shared.u64 t, %1; cvt.u32.u64 %0, t; }"
        : "=r"(a) : "l"(p));
    return a;
}
__device__ __forceinline__ uint32_t swz128(uint32_t o) { return o ^ ((o >> 3) & 0x70); }
__device__ __forceinline__ uint32_t swz256(uint32_t o) { return o ^ ((o >> 4) & 0x70); }

__device__ __forceinline__ void cp_async16(uint32_t dst, const void* src) {
    asm volatile("cp.async.cg.shared.global [%0], [%1], 16;" :: "r"(dst), "l"(src));
}
#define CP_COMMIT() asm volatile("cp.async.commit_group;" ::: "memory")
#define CP_WAIT(n)  asm volatile("cp.async.wait_group %0;" :: "n"(n) : "memory")

__device__ __forceinline__ void ldmx4(uint32_t* r, uint32_t addr) {
    asm volatile("ldmatrix.sync.aligned.m8n8.x4.shared.b16 {%0,%1,%2,%3}, [%4];"
                 : "=r"(r[0]), "=r"(r[1]), "=r"(r[2]), "=r"(r[3]) : "r"(addr));
}
__device__ __forceinline__ void ldmx4t(uint32_t* r, uint32_t addr) {
    asm volatile("ldmatrix.sync.aligned.m8n8.x4.trans.shared.b16 {%0,%1,%2,%3}, [%4];"
                 : "=r"(r[0]), "=r"(r[1]), "=r"(r[2]), "=r"(r[3]) : "r"(addr));
}
__device__ __forceinline__ void mma16816(float* c, const uint32_t* a, const uint32_t* b) {
    asm volatile(
        "mma.sync.aligned.m16n8k16.row.col.f32.bf16.bf16.f32 "
        "{%0,%1,%2,%3}, {%4,%5,%6,%7}, {%8,%9}, {%0,%1,%2,%3};"
        : "+f"(c[0]), "+f"(c[1]), "+f"(c[2]), "+f"(c[3])
        : "r"(a[0]), "r"(a[1]), "r"(a[2]), "r"(a[3]), "r"(b[0]), "r"(b[1]));
}

// ======================= conversions =======================================
// x fp32 [M,DIM] -> A3 bf16 [M,K3] rows = [hi | hi | lo]
__global__ __launch_bounds__(256) void split3_f32(const float* __restrict__ x,
                                                  __nv_bfloat16* __restrict__ A3) {
    size_t i = ((size_t)blockIdx.x * 256 + threadIdx.x) * 4;
    size_t m = i / DIM, k = i % DIM;
    float4 v = *reinterpret_cast<const float4*>(x + i);
    __nv_bfloat16 h0 = __float2bfloat16(v.x), h1 = __float2bfloat16(v.y);
    __nv_bfloat16 h2 = __float2bfloat16(v.z), h3 = __float2bfloat16(v.w);
    __nv_bfloat162 hA(h0, h1), hB(h2, h3);
    __nv_bfloat162 lA(__float2bfloat16(v.x - __bfloat162float(h0)),
                      __float2bfloat16(v.y - __bfloat162float(h1)));
    __nv_bfloat162 lB(__float2bfloat16(v.z - __bfloat162float(h2)),
                      __float2bfloat16(v.w - __bfloat162float(h3)));
    __nv_bfloat16* row = A3 + m * K3;
    *reinterpret_cast<__nv_bfloat162*>(row + k) = hA;
    *reinterpret_cast<__nv_bfloat162*>(row + k + 2) = hB;
    *reinterpret_cast<__nv_bfloat162*>(row + DIM + k) = hA;
    *reinterpret_cast<__nv_bfloat162*>(row + DIM + k + 2) = hB;
    *reinterpret_cast<__nv_bfloat162*>(row + 2 * DIM + k) = lA;
    *reinterpret_cast<__nv_bfloat162*>(row + 2 * DIM + k + 2) = lB;
}

// W[k][n] fp32 -> W3[n] rows (K3) = [hi | lo | hi]
__global__ __launch_bounds__(1024) void transpose_split3(const float* __restrict__ W,
                                                         __nv_bfloat16* __restrict__ W3) {
    __shared__ float t[32][33];
    int tx = threadIdx.x, ty = threadIdx.y;
    int k0 = blockIdx.y * 32, n0 = blockIdx.x * 32;
    t[ty][tx] = W[(size_t)(k0 + ty) * DIM + n0 + tx];
    __syncthreads();
    float v = t[tx][ty];
    __nv_bfloat16 h = __float2bfloat16(v);
    __nv_bfloat16 l = __float2bfloat16(v - __bfloat162float(h));
    __nv_bfloat16* row = W3 + (size_t)(n0 + ty) * K3;
    row[k0 + tx] = h;
    row[DIM + k0 + tx] = l;
    row[2 * DIM + k0 + tx] = h;
}

// qkvg z in {0,1,2} fp32 [b][s][h*64+d] -> g_qkh [z][hi/lo][bh][s][d] bf16
__global__ __launch_bounds__(256) void qkv_split_heads(const float* __restrict__ qkv,
                                                       __nv_bfloat16* __restrict__ outp) {
    size_t i4 = (size_t)blockIdx.x * 256 + threadIdx.x;   // float4 index
    int z = (int)(i4 >> 20);
    size_t r = i4 & 0xFFFFF;
    int m = (int)(r >> 8);            // row in [4096]
    int col4 = (int)(r & 255);
    int h = col4 >> 4, d4 = col4 & 15;
    int b = m >> 11, s = m & 2047;
    int bh = b * NH + h;
    float4 v = *reinterpret_cast<const float4*>(qkv + ((size_t)z * MTOT * DIM) + (size_t)m * DIM + col4 * 4);
    __nv_bfloat16 h0 = __float2bfloat16(v.x), h1 = __float2bfloat16(v.y);
    __nv_bfloat16 h2 = __float2bfloat16(v.z), h3 = __float2bfloat16(v.w);
    __nv_bfloat162 hp0(h0, h1), hp1(h2, h3);
    __nv_bfloat162 lp0(__float2bfloat16(v.x - __bfloat162float(h0)),
                       __float2bfloat16(v.y - __bfloat162float(h1)));
    __nv_bfloat162 lp1(__float2bfloat16(v.z - __bfloat162float(h2)),
                       __float2bfloat16(v.w - __bfloat162float(h3)));
    size_t hiBase = ((((size_t)z * 2 + 0) * NBH + bh) * SEQ + s) * HD + d4 * 4;
    size_t loBase = ((((size_t)z * 2 + 1) * NBH + bh) * SEQ + s) * HD + d4 * 4;
    *reinterpret_cast<__nv_bfloat162*>(outp + hiBase) = hp0;
    *reinterpret_cast<__nv_bfloat162*>(outp + hiBase + 2) = hp1;
    *reinterpret_cast<__nv_bfloat162*>(outp + loBase) = lp0;
    *reinterpret_cast<__nv_bfloat162*>(outp + loBase + 2) = lp1;
}

// ======================= HMMA split-bf16 dense GEMM ========================
#define GEMM_SMEM (64 * 1024)
__global__ __launch_bounds__(256, 2) void gemm_hmma(
    const __nv_bfloat16* __restrict__ A3, const __nv_bfloat16* __restrict__ W3base,
    const float* b0, const float* b1, const float* b2, const float* b3,
    float* __restrict__ outBase, int sigmoidZ)
{
    extern __shared__ char smem[];
    const uint32_t sb = smem_u32(smem);
    const int tid = threadIdx.x;
    const int wid = tid >> 5, lane = tid & 31;
    const int wm = wid & 3, wn = wid >> 2;
    const int z = blockIdx.z;
    const int m0 = blockIdx.y * 128, n0 = blockIdx.x * 128;

    const __nv_bfloat16* W3 = W3base + (size_t)z * DIM * K3;
    const float* bias = (z == 0) ? b0 : (z == 1) ? b1 : (z == 2) ? b2 : b3;
    float* out = outBase + (size_t)z * MTOT * DIM;
    const bool doSig = (z == sigmoidZ);

    const char* gA = (const char*)(A3 + (size_t)m0 * K3);
    const char* gB = (const char*)(W3 + (size_t)n0 * K3);

    auto load_stage = [&](int s) {
        const uint32_t base = sb + (s & 1) * 32768;
        const int kb = s * 128;
#pragma unroll
        for (int i = 0; i < 4; i++) {
            int c = tid + 256 * i;
            int row = c >> 3, cb = (c & 7) * 16;
            uint32_t d = swz128(row * 128 + cb);
            size_t src = (size_t)row * (K3 * 2) + kb + cb;
            cp_async16(base + d, gA + src);
            cp_async16(base + 16384 + d, gB + src);
        }
        CP_COMMIT();
    };

    float acc[2][8][4];
#pragma unroll
    for (int mi = 0; mi < 2; mi++)
#pragma unroll
        for (int ni = 0; ni < 8; ni++)
#pragma unroll
            for (int j = 0; j < 4; j++) acc[mi][ni][j] = 0.f;

    load_stage(0);
    load_stage(1);

    for (int s = 0; s < NSTG; s++) {
        if (s == NSTG - 1) { CP_WAIT(0); } else { CP_WAIT(1); }
        __syncthreads();
        const uint32_t abase = sb + (s & 1) * 32768;
        const uint32_t bbase = abase + 16384;
#pragma unroll
        for (int ki = 0; ki < 4; ki++) {
            uint32_t a[2][4];
#pragma unroll
            for (int mi = 0; mi < 2; mi++) {
                int row = wm * 32 + mi * 16 + (lane & 15);
                int kb = ki * 32 + ((lane >> 4) << 4);
                ldmx4(a[mi], abase + swz128(row * 128 + kb));
            }
#pragma unroll
            for (int pi = 0; pi < 4; pi++) {
                int nrow = wn * 64 + pi * 16 + ((lane >> 4) << 3) + (lane & 7);
                int kb = ki * 32 + ((lane >> 3) & 1) * 16;
                uint32_t b[4];
                ldmx4(b, bbase + swz128(nrow * 128 + kb));
#pragma unroll
                for (int mi = 0; mi < 2; mi++) {
                    mma16816(acc[mi][2 * pi], a[mi], b);
                    mma16816(acc[mi][2 * pi + 1], a[mi], b + 2);
                }
            }
        }
        __syncthreads();
        if (s + 2 < NSTG) load_stage(s + 2);
    }

    const int rbase = m0 + wm * 32;
    const int cbase = n0 + wn * 64;
#pragma unroll
    for (int mi = 0; mi < 2; mi++) {
#pragma unroll
        for (int ni = 0; ni < 8; ni++) {
            int row = rbase + mi * 16 + (lane >> 2);
            int col = cbase + ni * 8 + (lane & 3) * 2;
            float bx = bias[col], by = bias[col + 1];
            float2 v0 = {acc[mi][ni][0] + bx, acc[mi][ni][1] + by};
            float2 v1 = {acc[mi][ni][2] + bx, acc[mi][ni][3] + by};
            if (doSig) {
                v0.x = 1.f / (1.f + expf(-v0.x)); v0.y = 1.f / (1.f + expf(-v0.y));
                v1.x = 1.f / (1.f + expf(-v1.x)); v1.y = 1.f / (1.f + expf(-v1.y));
            }
            *reinterpret_cast<float2*>(&out[(size_t)row * DIM + col]) = v0;
            *reinterpret_cast<float2*>(&out[(size_t)(row + 8) * DIM + col]) = v1;
        }
    }
}

// ======================= fused scores+exp (HMMA) ===========================
// E[bh][q][k] = exp(QK^T/8 + mask) (pad->0), rinv[bh][q] = 1/rowsum
#define SC_SMEM (96 * 1024)
// smem: QH 0, QL 16K, stage0 {KH 32K, KL 48K}, stage1 {KH 64K, KL 80K}
__global__ __launch_bounds__(256, 2) void attn_scores_exp(
    const __nv_bfloat16* __restrict__ qkh,
    const float* __restrict__ mask, const unsigned char* __restrict__ pad,
    float* __restrict__ E, float* __restrict__ rinv)
{
    extern __shared__ char smem[];
    const uint32_t sb = smem_u32(smem);
    const int tid = threadIdx.x;
    const int w = tid >> 5, lane = tid & 31;
    const int bhz = blockIdx.z;          // 0..31
    const int qb = blockIdx.y;           // 0..15
    const int bb = bhz >> 4;

    const __nv_bfloat16* Qh = qkh + ((size_t)(0 * 2 + 0) * NBH + bhz) * SEQ * HD;
    const __nv_bfloat16* Ql = qkh + ((size_t)(0 * 2 + 1) * NBH + bhz) * SEQ * HD;
    const __nv_bfloat16* Kh = qkh + ((size_t)(1 * 2 + 0) * NBH + bhz) * SEQ * HD;
    const __nv_bfloat16* Kl = qkh + ((size_t)(1 * 2 + 1) * NBH + bhz) * SEQ * HD;

    // load Q tiles (128 rows x 128B, hi+lo)
#pragma unroll
    for (int i = 0; i < 4; i++) {
        int c = tid + 256 * i;
        int row = c >> 3, cb = (c & 7) * 16;
        uint32_t d = swz128(row * 128 + cb);
        size_t src = (size_t)(qb * 128 + row) * (HD * 2) + cb;
        cp_async16(sb + d, (const char*)Qh + src);
        cp_async16(sb + 16384 + d, (const char*)Ql + src);
    }
    auto load_k = [&](int kb, int st) {
        const uint32_t base = sb + 32768 + st * 32768;
#pragma unroll
        for (int i = 0; i < 4; i++) {
            int c = tid + 256 * i;
            int row = c >> 3, cb = (c & 7) * 16;
            uint32_t d = swz128(row * 128 + cb);
            size_t src = (size_t)(kb * 128 + row) * (HD * 2) + cb;
            cp_async16(base + d, (const char*)Kh + src);
            cp_async16(base + 16384 + d, (const char*)Kl + src);
        }
        CP_COMMIT();
    };
    load_k(0, 0);
    load_k(1, 1);

    float rs0 = 0.f, rs1 = 0.f;
    const int q_r0 = qb * 128 + w * 16 + (lane >> 2);
    const int q_r1 = q_r0 + 8;

    for (int kb = 0; kb < 16; kb++) {
        if (kb == 15) { CP_WAIT(0); } else { CP_WAIT(1); }
        __syncthreads();
        const uint32_t kbase = sb + 32768 + (kb & 1) * 32768;

        float acc[16][4];
#pragma unroll
        for (int ni = 0; ni < 16; ni++)
#pragma unroll
            for (int j = 0; j < 4; j++) acc[ni][j] = 0.f;

#pragma unroll
        for (int ki = 0; ki < 4; ki++) {
            uint32_t ah[4], al[4];
            {
                int row = w * 16 + (lane & 15);
                int kbyte = ki * 32 + ((lane >> 4) << 4);
                ldmx4(ah, sb + swz128(row * 128 + kbyte));
                ldmx4(al, sb + 16384 + swz128(row * 128 + kbyte));
            }
#pragma unroll
            for (int pi = 0; pi < 8; pi++) {
                int nrow = pi * 16 + ((lane >> 4) << 3) + (lane & 7);
                int kbyte = ki * 32 + ((lane >> 3) & 1) * 16;
                uint32_t bh4[4], bl4[4];
                ldmx4(bh4, kbase + swz128(nrow * 128 + kbyte));
                ldmx4(bl4, kbase + 16384 + swz128(nrow * 128 + kbyte));
                mma16816(acc[2 * pi], ah, bh4);
                mma16816(acc[2 * pi], ah, bl4);
                mma16816(acc[2 * pi], al, bh4);
                mma16816(acc[2 * pi + 1], ah, bh4 + 2);
                mma16816(acc[2 * pi + 1], ah, bl4 + 2);
                mma16816(acc[2 * pi + 1], al, bh4 + 2);
            }
        }

        // epilogue: exp + store
        float* Eb = E + ((size_t)bhz * SEQ) * SEQ;
#pragma unroll
        for (int ni = 0; ni < 16; ni++) {
            int kcol = kb * 128 + ni * 8 + (lane & 3) * 2;
            float2 m0 = *reinterpret_cast<const float2*>(mask + (size_t)q_r0 * SEQ + kcol);
            float2 m1 = *reinterpret_cast<const float2*>(mask + (size_t)q_r1 * SEQ + kcol);
            uchar2 pd = *reinterpret_cast<const uchar2*>(pad + bb * SEQ + kcol);
            float e00 = pd.x ? 0.f : __expf(acc[ni][0] * 0.125f + m0.x);
            float e01 = pd.y ? 0.f : __expf(acc[ni][1] * 0.125f + m0.y);
            float e10 = pd.x ? 0.f : __expf(acc[ni][2] * 0.125f + m1.x);
            float e11 = pd.y ? 0.f : __expf(acc[ni][3] * 0.125f + m1.y);
            float2 s0 = {e00, e01}, s1 = {e10, e11};
            *reinterpret_cast<float2*>(Eb + (size_t)q_r0 * SEQ + kcol) = s0;
            *reinterpret_cast<float2*>(Eb + (size_t)q_r1 * SEQ + kcol) = s1;
            rs0 += e00 + e01;
            rs1 += e10 + e11;
        }
        __syncthreads();
        if (kb + 2 < 16) load_k(kb + 2, kb & 1);
    }

    // reduce row sums across quad lanes
#pragma unroll
    for (int o = 1; o < 4; o <<= 1) {
        rs0 += __shfl_xor_sync(0xffffffffu, rs0, o);
        rs1 += __shfl_xor_sync(0xffffffffu, rs1, o);
    }
    if ((lane & 3) == 0) {
        rinv[(size_t)bhz * SEQ + q_r0] = 1.f / rs0;
        rinv[(size_t)bhz * SEQ + q_r1] = 1.f / rs1;
    }
}

// ======================= avg over heads (normalized) =======================
__global__ __launch_bounds__(512) void avg_kernel(
    const float* __restrict__ E, const float* __restrict__ rinv,
    float* __restrict__ avg)
{
    int bq = blockIdx.x;                  // b*2048 + q
    int b = bq >> 11, q = bq & 2047;
    int k4 = threadIdx.x * 4;
    float ri[NH];
#pragma unroll
    for (int h = 0; h < NH; h++)
        ri[h] = rinv[(size_t)(b * NH + h) * SEQ + q] * (1.f / NH);
    float4 s = {0.f, 0.f, 0.f, 0.f};
#pragma unroll
    for (int h = 0; h < NH; h++) {
        float4 t = *reinterpret_cast<const float4*>(
            E + ((size_t)(b * NH + h) * SEQ + q) * SEQ + k4);
        s.x += t.x * ri[h]; s.y += t.y * ri[h];
        s.z += t.z * ri[h]; s.w += t.w * ri[h];
    }
    *reinterpret_cast<float4*>(avg + (size_t)bq * SEQ + k4) = s;
}

// ======================= PV + gate (HMMA) ==================================
#define PV_SMEM (96 * 1024)
// smem: EH 0 (32K), EL 32K, VH 64K (16K), VL 80K
__global__ __launch_bounds__(256, 2) void pv_gate_hmma(
    const float* __restrict__ E, const __nv_bfloat16* __restrict__ qkh,
    const float* __restrict__ rinv, const float* __restrict__ gate,
    float* __restrict__ att)
{
    extern __shared__ char smem[];
    const uint32_t sb = smem_u32(smem);
    const int tid = threadIdx.x;
    const int w = tid >> 5, lane = tid & 31;
    const int bhz = blockIdx.z, qb = blockIdx.y;
    const int bb = bhz >> 4, hh = bhz & 15;

    const __nv_bfloat16* Vh = qkh + ((size_t)(2 * 2 + 0) * NBH + bhz) * SEQ * HD;
    const __nv_bfloat16* Vl = qkh + ((size_t)(2 * 2 + 1) * NBH + bhz) * SEQ * HD;
    const float* Eb = E + ((size_t)bhz * SEQ + qb * 128) * SEQ;

    float acc[8][4];
#pragma unroll
    for (int ni = 0; ni < 8; ni++)
#pragma unroll
        for (int j = 0; j < 4; j++) acc[ni][j] = 0.f;

    for (int kb = 0; kb < 16; kb++) {
        __syncthreads();   // previous MMA done before smem overwrite
        // convert E tile fp32 -> bf16 hi/lo (swz256)
#pragma unroll
        for (int i = 0; i < 8; i++) {
            int c = tid + 256 * i;
            int row = c >> 4, col8 = (c & 15) * 8;
            const float* src = Eb + (size_t)row * SEQ + kb * 128 + col8;
            float4 v0 = *reinterpret_cast<const float4*>(src);
            float4 v1 = *reinterpret_cast<const float4*>(src + 4);
            __nv_bfloat16 h[8], l[8];
            float vv[8] = {v0.x, v0.y, v0.z, v0.w, v1.x, v1.y, v1.z, v1.w};
#pragma unroll
            for (int j = 0; j < 8; j++) {
                h[j] = __float2bfloat16(vv[j]);
                l[j] = __float2bfloat16(vv[j] - __bfloat162float(h[j]));
            }
            uint32_t d = swz256(row * 256 + col8 * 2);
            *reinterpret_cast<uint4*>(smem + d) = *reinterpret_cast<uint4*>(h);
            *reinterpret_cast<uint4*>(smem + 32768 + d) = *reinterpret_cast<uint4*>(l);
        }
        // V tile via cp.async
#pragma unroll
        for (int i = 0; i < 4; i++) {
            int c = tid + 256 * i;
            int row = c >> 3, cb = (c & 7) * 16;
            uint32_t d = swz128(row * 128 + cb);
            size_t src = (size_t)(kb * 128 + row) * (HD * 2) + cb;
            cp_async16(sb + 65536 + d, (const char*)Vh + src);
            cp_async16(sb + 81920 + d, (const char*)Vl + src);
        }
        CP_COMMIT();
        CP_WAIT(0);
        __syncthreads();

#pragma unroll
        for (int ki = 0; ki < 8; ki++) {
            uint32_t ah[4], al[4];
            {
                int row = w * 16 + (lane & 15);
                int kbyte = ki * 32 + ((lane >> 4) << 4);
                ldmx4(ah, sb + swz256(row * 256 + kbyte));
                ldmx4(al, sb + 32768 + swz256(row * 256 + kbyte));
            }
#pragma unroll
            for (int pi = 0; pi < 4; pi++) {
                int vrow = ki * 16 + (lane & 15);
                int vbyte = pi * 32 + ((lane >> 4) << 4);
                uint32_t bh4[4], bl4[4];
                ldmx4t(bh4, sb + 65536 + swz128(vrow * 128 + vbyte));
                ldmx4t(bl4, sb + 81920 + swz128(vrow * 128 + vbyte));
                mma16816(acc[2 * pi], ah, bh4);
                mma16816(acc[2 * pi], ah, bl4);
                mma16816(acc[2 * pi], al, bh4);
                mma16816(acc[2 * pi + 1], ah, bh4 + 2);
                mma16816(acc[2 * pi + 1], ah, bl4 + 2);
                mma16816(acc[2 * pi + 1], al, bh4 + 2);
            }
        }
    }

    // epilogue: * rinv * gate -> att
    const int r0 = qb * 128 + w * 16 + (lane >> 2);
    const int r1 = r0 + 8;
    float ri0 = rinv[(size_t)bhz * SEQ + r0];
    float ri1 = rinv[(size_t)bhz * SEQ + r1];
#pragma unroll
    for (int ni = 0; ni < 8; ni++) {
        int d = ni * 8 + (lane & 3) * 2;
        size_t i0 = ((size_t)bb * SEQ + r0) * DIM + hh * HD + d;
        size_t i1 = ((size_t)bb * SEQ + r1) * DIM + hh * HD + d;
        float2 g0 = *reinterpret_cast<const float2*>(gate + i0);
        float2 g1 = *reinterpret_cast<const float2*>(gate + i1);
        float2 o0 = {acc[ni][0] * ri0 * g0.x, acc[ni][1] * ri0 * g0.y};
        float2 o1 = {acc[ni][2] * ri1 * g1.x, acc[ni][3] * ri1 * g1.y};
        *reinterpret_cast<float2*>(att + i0) = o0;
        *reinterpret_cast<float2*>(att + i1) = o1;
    }
}

// ---------------- launch -----------------------------------------------------
extern "C" void kernel_launch(void* const* d_in, const int* in_sizes, int n_in,
                              void* d_out, int out_size)
{
    (void)in_sizes; (void)n_in; (void)out_size;
    const float* x    = (const float*)d_in[0];
    const float* mask = (const float*)d_in[1];
    const unsigned char* pad = (const unsigned char*)d_in[2];
    const float* Wq = (const float*)d_in[3];
    const float* bq = (const float*)d_in[4];
    const float* Wk = (const float*)d_in[5];
    const float* bk = (const float*)d_in[6];
    const float* Wv = (const float*)d_in[7];
    const float* bv = (const float*)d_in[8];
    const float* Wg = (const float*)d_in[9];
    const float* bg = (const float*)d_in[10];
    const float* Wo = (const float*)d_in[11];
    const float* bo = (const float*)d_in[12];
    float* out = (float*)d_out;

    float *qkvg, *att, *E, *rinv;
    __nv_bfloat16 *a3, *w3, *qkh;
    cudaGetSymbolAddress((void**)&qkvg, g_qkvg);
    cudaGetSymbolAddress((void**)&att, g_att);
    cudaGetSymbolAddress((void**)&E, g_P);
    cudaGetSymbolAddress((void**)&rinv, g_rinv);
    cudaGetSymbolAddress((void**)&a3, g_a3);
    cudaGetSymbolAddress((void**)&w3, g_w3);
    cudaGetSymbolAddress((void**)&qkh, g_qkh);

    static bool attrSet = false;
    if (!attrSet) {
        cudaFuncSetAttribute(gemm_hmma, cudaFuncAttributeMaxDynamicSharedMemorySize, GEMM_SMEM);
        cudaFuncSetAttribute(attn_scores_exp, cudaFuncAttributeMaxDynamicSharedMemorySize, SC_SMEM);
        cudaFuncSetAttribute(pv_gate_hmma, cudaFuncAttributeMaxDynamicSharedMemorySize, PV_SMEM);
        attrSet = true;
    }

    const float* gate = qkvg + 3ull * MTOT * DIM;

    // 1) split x, transpose+split weights
    split3_f32<<<(MTOT * DIM) / 1024, 256>>>(x, a3);
    dim3 tgrid(DIM / 32, DIM / 32);
    transpose_split3<<<tgrid, dim3(32, 32)>>>(Wq, w3 + 0ull * DIM * K3);
    transpose_split3<<<tgrid, dim3(32, 32)>>>(Wk, w3 + 1ull * DIM * K3);
    transpose_split3<<<tgrid, dim3(32, 32)>>>(Wv, w3 + 2ull * DIM * K3);
    transpose_split3<<<tgrid, dim3(32, 32)>>>(Wg, w3 + 3ull * DIM * K3);
    transpose_split3<<<tgrid, dim3(32, 32)>>>(Wo, w3 + 4ull * DIM * K3);

    // 2) q,k,v,gate projections (HMMA)
    gemm_hmma<<<dim3(DIM / 128, MTOT / 128, 4), 256, GEMM_SMEM>>>(
        a3, w3, bq, bk, bv, bg, qkvg, 3);

    // 3) per-head bf16 hi/lo layout for q,k,v
    qkv_split_heads<<<3 * (MTOT * DIM / 4) / 256, 256>>>(qkvg, qkh);

    // 4) fused scores + exp (unnormalized) + row sums
    attn_scores_exp<<<dim3(1, SEQ / 128, NBH), 256, SC_SMEM>>>(qkh, mask, pad, E, rinv);

    // 5) avg over heads (normalized)
    avg_kernel<<<BB * SEQ, 512>>>(E, rinv, out + (size_t)MTOT * DIM);

    // 6) PV + gate (HMMA)
    pv_gate_hmma<<<dim3(1, SEQ / 128, NBH), 256, PV_SMEM>>>(E, qkh, rinv, gate, att);

    // 7) O projection (HMMA)
    split3_f32<<<(MTOT * DIM) / 1024, 256>>>(att, a3);
    gemm_hmma<<<dim3(DIM / 128, MTOT / 128, 1), 256, GEMM_SMEM>>>(
        a3, w3 + 4ull * DIM * K3, bo, bo, bo, bo, out, -1);
}

// round 5
// speedup vs baseline: 3.0077x; 1.0856x over previous
#include <cuda_runtime.h>
#include <cuda_bf16.h>
#include <cuda_fp16.h>
#include <math.h>
#include <stdint.h>

// Fixed problem shape
#define BB 2
#define SEQ 2048
#define DIM 1024
#define NH 16
#define HD 64
#define MTOT (BB * SEQ)            // 4096
#define K3 (3 * DIM)               // 3072
#define NSTG 48                    // K3 / 64
#define NBH (BB * NH)              // 32

// ---------------- scratch ----------------------------------------------------
__device__ float g_qkvg[4ull * MTOT * DIM];            // q,k,v,gate fp32
__device__ float g_att[(size_t)MTOT * DIM];            // gated attn out
__device__ __half g_E[(size_t)NBH * SEQ * SEQ];        // unnormalized exp, fp16
__device__ float g_rinv[(size_t)NBH * SEQ];            // 1/rowsum
__device__ __nv_bfloat16 g_a3[(size_t)MTOT * K3];      // [Ah|Ah|Al]
__device__ __nv_bfloat16 g_w3[5ull * DIM * K3];        // [Wh|Wl|Wh] N-major
__device__ __half g_qkh[3ull * 2 * NBH * SEQ * HD];    // q,k,v per-head hi/lo fp16

// ======================= helpers ===========================================
__device__ __forceinline__ uint32_t smem_u32(const void* p) {
    uint32_t a;
    asm("{ .reg .u64 t; cvta.to.shared.u64 t, %1; cvt.u32.u64 %0, t; }"
        : "=r"(a) : "l"(p));
    return a;
}
__device__ __forceinline__ uint32_t swz128(uint32_t o) { return o ^ ((o >> 3) & 0x70); }

__device__ __forceinline__ void cp_async16(uint32_t dst, const void* src) {
    asm volatile("cp.async.cg.shared.global [%0], [%1], 16;" :: "r"(dst), "l"(src));
}
#define CP_COMMIT() asm volatile("cp.async.commit_group;" ::: "memory")
#define CP_WAIT(n)  asm volatile("cp.async.wait_group %0;" :: "n"(n) : "memory")

__device__ __forceinline__ void ldmx4(uint32_t* r, uint32_t addr) {
    asm volatile("ldmatrix.sync.aligned.m8n8.x4.shared.b16 {%0,%1,%2,%3}, [%4];"
                 : "=r"(r[0]), "=r"(r[1]), "=r"(r[2]), "=r"(r[3]) : "r"(addr));
}
__device__ __forceinline__ void ldmx4t(uint32_t* r, uint32_t addr) {
    asm volatile("ldmatrix.sync.aligned.m8n8.x4.trans.shared.b16 {%0,%1,%2,%3}, [%4];"
                 : "=r"(r[0]), "=r"(r[1]), "=r"(r[2]), "=r"(r[3]) : "r"(addr));
}
// bf16 mma (dense GEMMs)
__device__ __forceinline__ void mma_bf(float* c, const uint32_t* a, const uint32_t* b) {
    asm volatile(
        "mma.sync.aligned.m16n8k16.row.col.f32.bf16.bf16.f32 "
        "{%0,%1,%2,%3}, {%4,%5,%6,%7}, {%8,%9}, {%0,%1,%2,%3};"
        : "+f"(c[0]), "+f"(c[1]), "+f"(c[2]), "+f"(c[3])
        : "r"(a[0]), "r"(a[1]), "r"(a[2]), "r"(a[3]), "r"(b[0]), "r"(b[1]));
}
// fp16 mma (attention)
__device__ __forceinline__ void mma_hf(float* c, const uint32_t* a, const uint32_t* b) {
    asm volatile(
        "mma.sync.aligned.m16n8k16.row.col.f32.f16.f16.f32 "
        "{%0,%1,%2,%3}, {%4,%5,%6,%7}, {%8,%9}, {%0,%1,%2,%3};"
        : "+f"(c[0]), "+f"(c[1]), "+f"(c[2]), "+f"(c[3])
        : "r"(a[0]), "r"(a[1]), "r"(a[2]), "r"(a[3]), "r"(b[0]), "r"(b[1]));
}

// ======================= conversions =======================================
__global__ __launch_bounds__(256) void split3_f32(const float* __restrict__ x,
                                                  __nv_bfloat16* __restrict__ A3) {
    size_t i = ((size_t)blockIdx.x * 256 + threadIdx.x) * 4;
    size_t m = i / DIM, k = i % DIM;
    float4 v = *reinterpret_cast<const float4*>(x + i);
    __nv_bfloat16 h0 = __float2bfloat16(v.x), h1 = __float2bfloat16(v.y);
    __nv_bfloat16 h2 = __float2bfloat16(v.z), h3 = __float2bfloat16(v.w);
    __nv_bfloat162 hA(h0, h1), hB(h2, h3);
    __nv_bfloat162 lA(__float2bfloat16(v.x - __bfloat162float(h0)),
                      __float2bfloat16(v.y - __bfloat162float(h1)));
    __nv_bfloat162 lB(__float2bfloat16(v.z - __bfloat162float(h2)),
                      __float2bfloat16(v.w - __bfloat162float(h3)));
    __nv_bfloat16* row = A3 + m * K3;
    *reinterpret_cast<__nv_bfloat162*>(row + k) = hA;
    *reinterpret_cast<__nv_bfloat162*>(row + k + 2) = hB;
    *reinterpret_cast<__nv_bfloat162*>(row + DIM + k) = hA;
    *reinterpret_cast<__nv_bfloat162*>(row + DIM + k + 2) = hB;
    *reinterpret_cast<__nv_bfloat162*>(row + 2 * DIM + k) = lA;
    *reinterpret_cast<__nv_bfloat162*>(row + 2 * DIM + k + 2) = lB;
}

// all 5 weights in one launch: W[k][n] -> W3[z][n][K3] = [hi|lo|hi]
__global__ __launch_bounds__(1024) void transpose_split3_all(
    const float* __restrict__ W0, const float* __restrict__ W1,
    const float* __restrict__ W2, const float* __restrict__ W3p,
    const float* __restrict__ W4, __nv_bfloat16* __restrict__ out)
{
    __shared__ float t[32][33];
    int z = blockIdx.z;
    const float* W = (z == 0) ? W0 : (z == 1) ? W1 : (z == 2) ? W2 : (z == 3) ? W3p : W4;
    int tx = threadIdx.x, ty = threadIdx.y;
    int k0 = blockIdx.y * 32, n0 = blockIdx.x * 32;
    t[ty][tx] = W[(size_t)(k0 + ty) * DIM + n0 + tx];
    __syncthreads();
    float v = t[tx][ty];
    __nv_bfloat16 h = __float2bfloat16(v);
    __nv_bfloat16 l = __float2bfloat16(v - __bfloat162float(h));
    __nv_bfloat16* row = out + (size_t)z * DIM * K3 + (size_t)(n0 + ty) * K3;
    row[k0 + tx] = h;
    row[DIM + k0 + tx] = l;
    row[2 * DIM + k0 + tx] = h;
}

// qkvg z in {0,1,2} fp32 -> g_qkh [z][hi/lo][bh][s][d] fp16
__global__ __launch_bounds__(256) void qkv_split_heads(const float* __restrict__ qkv,
                                                       __half* __restrict__ outp) {
    size_t i4 = (size_t)blockIdx.x * 256 + threadIdx.x;
    int z = (int)(i4 >> 20);
    size_t r = i4 & 0xFFFFF;
    int m = (int)(r >> 8);
    int col4 = (int)(r & 255);
    int h = col4 >> 4, d4 = col4 & 15;
    int b = m >> 11, s = m & 2047;
    int bh = b * NH + h;
    float4 v = *reinterpret_cast<const float4*>(qkv + ((size_t)z * MTOT * DIM) + (size_t)m * DIM + col4 * 4);
    __half h0 = __float2half_rn(v.x), h1 = __float2half_rn(v.y);
    __half h2 = __float2half_rn(v.z), h3 = __float2half_rn(v.w);
    __half2 hp0(h0, h1), hp1(h2, h3);
    __half2 lp0(__float2half_rn(v.x - __half2float(h0)),
                __float2half_rn(v.y - __half2float(h1)));
    __half2 lp1(__float2half_rn(v.z - __half2float(h2)),
                __float2half_rn(v.w - __half2float(h3)));
    size_t hiBase = ((((size_t)z * 2 + 0) * NBH + bh) * SEQ + s) * HD + d4 * 4;
    size_t loBase = ((((size_t)z * 2 + 1) * NBH + bh) * SEQ + s) * HD + d4 * 4;
    *reinterpret_cast<__half2*>(outp + hiBase) = hp0;
    *reinterpret_cast<__half2*>(outp + hiBase + 2) = hp1;
    *reinterpret_cast<__half2*>(outp + loBase) = lp0;
    *reinterpret_cast<__half2*>(outp + loBase + 2) = lp1;
}

// ======================= HMMA split-bf16 dense GEMM ========================
#define GEMM_SMEM (64 * 1024)
__global__ __launch_bounds__(256, 2) void gemm_hmma(
    const __nv_bfloat16* __restrict__ A3, const __nv_bfloat16* __restrict__ W3base,
    const float* b0, const float* b1, const float* b2, const float* b3,
    float* __restrict__ outBase, int sigmoidZ)
{
    extern __shared__ char smem[];
    const uint32_t sb = smem_u32(smem);
    const int tid = threadIdx.x;
    const int wid = tid >> 5, lane = tid & 31;
    const int wm = wid & 3, wn = wid >> 2;
    const int z = blockIdx.z;
    const int m0 = blockIdx.y * 128, n0 = blockIdx.x * 128;

    const __nv_bfloat16* W3 = W3base + (size_t)z * DIM * K3;
    const float* bias = (z == 0) ? b0 : (z == 1) ? b1 : (z == 2) ? b2 : b3;
    float* out = outBase + (size_t)z * MTOT * DIM;
    const bool doSig = (z == sigmoidZ);

    const char* gA = (const char*)(A3 + (size_t)m0 * K3);
    const char* gB = (const char*)(W3 + (size_t)n0 * K3);

    auto load_stage = [&](int s) {
        const uint32_t base = sb + (s & 1) * 32768;
        const int kb = s * 128;
#pragma unroll
        for (int i = 0; i < 4; i++) {
            int c = tid + 256 * i;
            int row = c >> 3, cb = (c & 7) * 16;
            uint32_t d = swz128(row * 128 + cb);
            size_t src = (size_t)row * (K3 * 2) + kb + cb;
            cp_async16(base + d, gA + src);
            cp_async16(base + 16384 + d, gB + src);
        }
        CP_COMMIT();
    };

    float acc[2][8][4];
#pragma unroll
    for (int mi = 0; mi < 2; mi++)
#pragma unroll
        for (int ni = 0; ni < 8; ni++)
#pragma unroll
            for (int j = 0; j < 4; j++) acc[mi][ni][j] = 0.f;

    load_stage(0);
    load_stage(1);

    for (int s = 0; s < NSTG; s++) {
        if (s == NSTG - 1) { CP_WAIT(0); } else { CP_WAIT(1); }
        __syncthreads();
        const uint32_t abase = sb + (s & 1) * 32768;
        const uint32_t bbase = abase + 16384;
#pragma unroll
        for (int ki = 0; ki < 4; ki++) {
            uint32_t a[2][4];
#pragma unroll
            for (int mi = 0; mi < 2; mi++) {
                int row = wm * 32 + mi * 16 + (lane & 15);
                int kb = ki * 32 + ((lane >> 4) << 4);
                ldmx4(a[mi], abase + swz128(row * 128 + kb));
            }
#pragma unroll
            for (int pi = 0; pi < 4; pi++) {
                int nrow = wn * 64 + pi * 16 + ((lane >> 4) << 3) + (lane & 7);
                int kb = ki * 32 + ((lane >> 3) & 1) * 16;
                uint32_t b[4];
                ldmx4(b, bbase + swz128(nrow * 128 + kb));
#pragma unroll
                for (int mi = 0; mi < 2; mi++) {
                    mma_bf(acc[mi][2 * pi], a[mi], b);
                    mma_bf(acc[mi][2 * pi + 1], a[mi], b + 2);
                }
            }
        }
        __syncthreads();
        if (s + 2 < NSTG) load_stage(s + 2);
    }

    const int rbase = m0 + wm * 32;
    const int cbase = n0 + wn * 64;
#pragma unroll
    for (int mi = 0; mi < 2; mi++) {
#pragma unroll
        for (int ni = 0; ni < 8; ni++) {
            int row = rbase + mi * 16 + (lane >> 2);
            int col = cbase + ni * 8 + (lane & 3) * 2;
            float bx = bias[col], by = bias[col + 1];
            float2 v0 = {acc[mi][ni][0] + bx, acc[mi][ni][1] + by};
            float2 v1 = {acc[mi][ni][2] + bx, acc[mi][ni][3] + by};
            if (doSig) {
                v0.x = 1.f / (1.f + expf(-v0.x)); v0.y = 1.f / (1.f + expf(-v0.y));
                v1.x = 1.f / (1.f + expf(-v1.x)); v1.y = 1.f / (1.f + expf(-v1.y));
            }
            *reinterpret_cast<float2*>(&out[(size_t)row * DIM + col]) = v0;
            *reinterpret_cast<float2*>(&out[(size_t)(row + 8) * DIM + col]) = v1;
        }
    }
}

// ======================= fused flash attention ============================
// Per (bh, 128-q-block): S=QK^T/8+mask -> E=exp (pad->0) stored fp16,
// O = E@V accumulated in regs, epilogue O*rinv*gate -> att. rinv stored.
// smem: QH 0, QL 16K | stage s: KH 32K+s*64K, KL +16K, VH +32K, VL +48K
#define FL_SMEM (160 * 1024)
__global__ __launch_bounds__(256) void flash_attn(
    const __half* __restrict__ qkh, const float* __restrict__ mask,
    const unsigned char* __restrict__ pad, const float* __restrict__ gate,
    __half* __restrict__ E, float* __restrict__ rinv, float* __restrict__ att)
{
    extern __shared__ char smem[];
    const uint32_t sb = smem_u32(smem);
    const int tid = threadIdx.x;
    const int w = tid >> 5, lane = tid & 31;
    const int bhz = blockIdx.z, qb = blockIdx.y;
    const int bb = bhz >> 4, hh = bhz & 15;

    const __half* Qh = qkh + ((size_t)(0 * 2 + 0) * NBH + bhz) * SEQ * HD;
    const __half* Ql = qkh + ((size_t)(0 * 2 + 1) * NBH + bhz) * SEQ * HD;
    const __half* Kh = qkh + ((size_t)(1 * 2 + 0) * NBH + bhz) * SEQ * HD;
    const __half* Kl = qkh + ((size_t)(1 * 2 + 1) * NBH + bhz) * SEQ * HD;
    const __half* Vh = qkh + ((size_t)(2 * 2 + 0) * NBH + bhz) * SEQ * HD;
    const __half* Vl = qkh + ((size_t)(2 * 2 + 1) * NBH + bhz) * SEQ * HD;

    // Q tiles (128 rows x 128B hi+lo)
#pragma unroll
    for (int i = 0; i < 4; i++) {
        int c = tid + 256 * i;
        int row = c >> 3, cb = (c & 7) * 16;
        uint32_t d = swz128(row * 128 + cb);
        size_t src = (size_t)(qb * 128 + row) * (HD * 2) + cb;
        cp_async16(sb + d, (const char*)Qh + src);
        cp_async16(sb + 16384 + d, (const char*)Ql + src);
    }
    auto load_kv = [&](int kb, int st) {
        const uint32_t base = sb + 32768 + st * 65536;
#pragma unroll
        for (int i = 0; i < 4; i++) {
            int c = tid + 256 * i;
            int row = c >> 3, cb = (c & 7) * 16;
            uint32_t d = swz128(row * 128 + cb);
            size_t src = (size_t)(kb * 128 + row) * (HD * 2) + cb;
            cp_async16(base + d, (const char*)Kh + src);
            cp_async16(base + 16384 + d, (const char*)Kl + src);
            cp_async16(base + 32768 + d, (const char*)Vh + src);
            cp_async16(base + 49152 + d, (const char*)Vl + src);
        }
        CP_COMMIT();
    };
    load_kv(0, 0);   // group also covers Q loads
    load_kv(1, 1);

    float O[8][4];
#pragma unroll
    for (int ni = 0; ni < 8; ni++)
#pragma unroll
        for (int j = 0; j < 4; j++) O[ni][j] = 0.f;

    float rs0 = 0.f, rs1 = 0.f;
    const int q_r0 = qb * 128 + w * 16 + (lane >> 2);
    const int q_r1 = q_r0 + 8;
    __half* Eb = E + (size_t)bhz * SEQ * SEQ;

    for (int kb = 0; kb < 16; kb++) {
        if (kb == 15) { CP_WAIT(0); } else { CP_WAIT(1); }
        __syncthreads();
        const uint32_t kbase = sb + 32768 + (kb & 1) * 65536;
        const uint32_t vbase = kbase + 32768;

        // ---- S = Q K^T (3-term fp16) ----
        float acc[16][4];
#pragma unroll
        for (int ni = 0; ni < 16; ni++)
#pragma unroll
            for (int j = 0; j < 4; j++) acc[ni][j] = 0.f;

#pragma unroll
        for (int ki = 0; ki < 4; ki++) {
            uint32_t ah[4], al[4];
            {
                int row = w * 16 + (lane & 15);
                int kbyte = ki * 32 + ((lane >> 4) << 4);
                ldmx4(ah, sb + swz128(row * 128 + kbyte));
                ldmx4(al, sb + 16384 + swz128(row * 128 + kbyte));
            }
#pragma unroll
            for (int pi = 0; pi < 8; pi++) {
                int nrow = pi * 16 + ((lane >> 4) << 3) + (lane & 7);
                int kbyte = ki * 32 + ((lane >> 3) & 1) * 16;
                uint32_t bh4[4], bl4[4];
                ldmx4(bh4, kbase + swz128(nrow * 128 + kbyte));
                ldmx4(bl4, kbase + 16384 + swz128(nrow * 128 + kbyte));
                mma_hf(acc[2 * pi], ah, bh4);
                mma_hf(acc[2 * pi], ah, bl4);
                mma_hf(acc[2 * pi], al, bh4);
                mma_hf(acc[2 * pi + 1], ah, bh4 + 2);
                mma_hf(acc[2 * pi + 1], ah, bl4 + 2);
                mma_hf(acc[2 * pi + 1], al, bh4 + 2);
            }
        }

        // ---- epilogue: exp, rowsum, store E fp16, pack A-fragments ----
        uint32_t e16[8][4];
#pragma unroll
        for (int ni = 0; ni < 16; ni++) {
            int kcol = kb * 128 + ni * 8 + (lane & 3) * 2;
            float2 m0 = *reinterpret_cast<const float2*>(mask + (size_t)q_r0 * SEQ + kcol);
            float2 m1 = *reinterpret_cast<const float2*>(mask + (size_t)q_r1 * SEQ + kcol);
            uchar2 pd = *reinterpret_cast<const uchar2*>(pad + bb * SEQ + kcol);
            float e00 = pd.x ? 0.f : __expf(acc[ni][0] * 0.125f + m0.x);
            float e01 = pd.y ? 0.f : __expf(acc[ni][1] * 0.125f + m0.y);
            float e10 = pd.x ? 0.f : __expf(acc[ni][2] * 0.125f + m1.x);
            float e11 = pd.y ? 0.f : __expf(acc[ni][3] * 0.125f + m1.y);
            rs0 += e00 + e01;
            rs1 += e10 + e11;
            __half2 h0 = __floats2half2_rn(e00, e01);
            __half2 h1 = __floats2half2_rn(e10, e11);
            *reinterpret_cast<__half2*>(Eb + (size_t)q_r0 * SEQ + kcol) = h0;
            *reinterpret_cast<__half2*>(Eb + (size_t)q_r1 * SEQ + kcol) = h1;
            int ki = ni >> 1, hi = (ni & 1) * 2;
            e16[ki][hi + 0] = *reinterpret_cast<uint32_t*>(&h0);
            e16[ki][hi + 1] = *reinterpret_cast<uint32_t*>(&h1);
        }

        // ---- O += E @ V (2-term fp16) ----
#pragma unroll
        for (int ki = 0; ki < 8; ki++) {
#pragma unroll
            for (int pi = 0; pi < 4; pi++) {
                int vrow = ki * 16 + (lane & 15);
                int vbyte = pi * 32 + ((lane >> 4) << 4);
                uint32_t vh4[4], vl4[4];
                ldmx4t(vh4, vbase + swz128(vrow * 128 + vbyte));
                ldmx4t(vl4, vbase + 16384 + swz128(vrow * 128 + vbyte));
                mma_hf(O[2 * pi], e16[ki], vh4);
                mma_hf(O[2 * pi], e16[ki], vl4);
                mma_hf(O[2 * pi + 1], e16[ki], vh4 + 2);
                mma_hf(O[2 * pi + 1], e16[ki], vl4 + 2);
            }
        }
        __syncthreads();
        if (kb + 2 < 16) load_kv(kb + 2, kb & 1);
    }

    // rowsum reduce across quad
#pragma unroll
    for (int o = 1; o < 4; o <<= 1) {
        rs0 += __shfl_xor_sync(0xffffffffu, rs0, o);
        rs1 += __shfl_xor_sync(0xffffffffu, rs1, o);
    }
    float ri0 = 1.f / rs0, ri1 = 1.f / rs1;
    if ((lane & 3) == 0) {
        rinv[(size_t)bhz * SEQ + q_r0] = ri0;
        rinv[(size_t)bhz * SEQ + q_r1] = ri1;
    }

    // O epilogue: * rinv * gate -> att
#pragma unroll
    for (int ni = 0; ni < 8; ni++) {
        int d = ni * 8 + (lane & 3) * 2;
        size_t i0 = ((size_t)bb * SEQ + q_r0) * DIM + hh * HD + d;
        size_t i1 = ((size_t)bb * SEQ + q_r1) * DIM + hh * HD + d;
        float2 g0 = *reinterpret_cast<const float2*>(gate + i0);
        float2 g1 = *reinterpret_cast<const float2*>(gate + i1);
        float2 o0 = {O[ni][0] * ri0 * g0.x, O[ni][1] * ri0 * g0.y};
        float2 o1 = {O[ni][2] * ri1 * g1.x, O[ni][3] * ri1 * g1.y};
        *reinterpret_cast<float2*>(att + i0) = o0;
        *reinterpret_cast<float2*>(att + i1) = o1;
    }
}

// ======================= avg over heads (fp16 E) ===========================
__global__ __launch_bounds__(512) void avg_kernel(
    const __half* __restrict__ E, const float* __restrict__ rinv,
    float* __restrict__ avg)
{
    int bq = blockIdx.x;
    int b = bq >> 11, q = bq & 2047;
    int k4 = threadIdx.x * 4;
    float4 s = {0.f, 0.f, 0.f, 0.f};
#pragma unroll
    for (int h = 0; h < NH; h++) {
        float ri = rinv[(size_t)(b * NH + h) * SEQ + q] * (1.f / NH);
        const __half2* p = reinterpret_cast<const __half2*>(
            E + ((size_t)(b * NH + h) * SEQ + q) * SEQ + k4);
        float2 f0 = __half22float2(p[0]);
        float2 f1 = __half22float2(p[1]);
        s.x += f0.x * ri; s.y += f0.y * ri;
        s.z += f1.x * ri; s.w += f1.y * ri;
    }
    *reinterpret_cast<float4*>(avg + (size_t)bq * SEQ + k4) = s;
}

// ---------------- launch -----------------------------------------------------
extern "C" void kernel_launch(void* const* d_in, const int* in_sizes, int n_in,
                              void* d_out, int out_size)
{
    (void)in_sizes; (void)n_in; (void)out_size;
    const float* x    = (const float*)d_in[0];
    const float* mask = (const float*)d_in[1];
    const unsigned char* pad = (const unsigned char*)d_in[2];
    const float* Wq = (const float*)d_in[3];
    const float* bq = (const float*)d_in[4];
    const float* Wk = (const float*)d_in[5];
    const float* bk = (const float*)d_in[6];
    const float* Wv = (const float*)d_in[7];
    const float* bv = (const float*)d_in[8];
    const float* Wg = (const float*)d_in[9];
    const float* bg = (const float*)d_in[10];
    const float* Wo = (const float*)d_in[11];
    const float* bo = (const float*)d_in[12];
    float* out = (float*)d_out;

    float *qkvg, *att, *rinv;
    __half *E, *qkh;
    __nv_bfloat16 *a3, *w3;
    cudaGetSymbolAddress((void**)&qkvg, g_qkvg);
    cudaGetSymbolAddress((void**)&att, g_att);
    cudaGetSymbolAddress((void**)&E, g_E);
    cudaGetSymbolAddress((void**)&rinv, g_rinv);
    cudaGetSymbolAddress((void**)&a3, g_a3);
    cudaGetSymbolAddress((void**)&w3, g_w3);
    cudaGetSymbolAddress((void**)&qkh, g_qkh);

    static bool attrSet = false;
    if (!attrSet) {
        cudaFuncSetAttribute(gemm_hmma, cudaFuncAttributeMaxDynamicSharedMemorySize, GEMM_SMEM);
        cudaFuncSetAttribute(flash_attn, cudaFuncAttributeMaxDynamicSharedMemorySize, FL_SMEM);
        attrSet = true;
    }

    const float* gate = qkvg + 3ull * MTOT * DIM;

    // 1) conversions
    split3_f32<<<(MTOT * DIM) / 1024, 256>>>(x, a3);
    transpose_split3_all<<<dim3(DIM / 32, DIM / 32, 5), dim3(32, 32)>>>(
        Wq, Wk, Wv, Wg, Wo, w3);

    // 2) q,k,v,gate projections (bf16 HMMA)
    gemm_hmma<<<dim3(DIM / 128, MTOT / 128, 4), 256, GEMM_SMEM>>>(
        a3, w3, bq, bk, bv, bg, qkvg, 3);

    // 3) per-head fp16 hi/lo layout for q,k,v
    qkv_split_heads<<<3 * (MTOT * DIM / 4) / 256, 256>>>(qkvg, qkh);

    // 4) fused flash: scores+exp+E store+PV+gate
    flash_attn<<<dim3(1, SEQ / 128, NBH), 256, FL_SMEM>>>(
        qkh, mask, pad, gate, E, rinv, att);

    // 5) avg over heads
    avg_kernel<<<BB * SEQ, 512>>>(E, rinv, out + (size_t)MTOT * DIM);

    // 6) O projection (bf16 HMMA)
    split3_f32<<<(MTOT * DIM) / 1024, 256>>>(att, a3);
    gemm_hmma<<<dim3(DIM / 128, MTOT / 128, 1), 256, GEMM_SMEM>>>(
        a3, w3 + 4ull * DIM * K3, bo, bo, bo, bo, out, -1);
}

// round 6
// speedup vs baseline: 3.5334x; 1.1748x over previous
#include <cuda_runtime.h>
#include <cuda_bf16.h>
#include <cuda_fp16.h>
#include <math.h>
#include <stdint.h>

// Fixed problem shape
#define BB 2
#define SEQ 2048
#define DIM 1024
#define NH 16
#define HD 64
#define MTOT (BB * SEQ)            // 4096
#define K3 (3 * DIM)               // 3072
#define NSTG 48                    // K3 / 64
#define NBH (BB * NH)              // 32

// ---------------- scratch ----------------------------------------------------
__device__ float g_gate[(size_t)MTOT * DIM];           // sigmoid gate fp32
__device__ __half g_E[(size_t)NBH * SEQ * SEQ];        // unnormalized exp, fp16
__device__ float g_rinv[(size_t)NBH * SEQ];            // 1/rowsum
__device__ __nv_bfloat16 g_a3[(size_t)MTOT * K3];      // [Ah|Ah|Al] (x, then att)
__device__ __nv_bfloat16 g_w3[5ull * DIM * K3];        // [Wh|Wl|Wh] N-major
__device__ __half g_qkh[3ull * 2 * NBH * SEQ * HD];    // q,k,v per-head hi/lo fp16
__device__ __half g_maskh[(size_t)SEQ * SEQ];          // mask fp16

// ======================= helpers ===========================================
__device__ __forceinline__ uint32_t smem_u32(const void* p) {
    uint32_t a;
    asm("{ .reg .u64 t; cvta.to.shared.u64 t, %1; cvt.u32.u64 %0, t; }"
        : "=r"(a) : "l"(p));
    return a;
}
__device__ __forceinline__ uint32_t swz128(uint32_t o) { return o ^ ((o >> 3) & 0x70); }

__device__ __forceinline__ void cp_async16(uint32_t dst, const void* src) {
    asm volatile("cp.async.cg.shared.global [%0], [%1], 16;" :: "r"(dst), "l"(src));
}
#define CP_COMMIT() asm volatile("cp.async.commit_group;" ::: "memory")
#define CP_WAIT(n)  asm volatile("cp.async.wait_group %0;" :: "n"(n) : "memory")

__device__ __forceinline__ void ldmx4(uint32_t* r, uint32_t addr) {
    asm volatile("ldmatrix.sync.aligned.m8n8.x4.shared.b16 {%0,%1,%2,%3}, [%4];"
                 : "=r"(r[0]), "=r"(r[1]), "=r"(r[2]), "=r"(r[3]) : "r"(addr));
}
__device__ __forceinline__ void ldmx4t(uint32_t* r, uint32_t addr) {
    asm volatile("ldmatrix.sync.aligned.m8n8.x4.trans.shared.b16 {%0,%1,%2,%3}, [%4];"
                 : "=r"(r[0]), "=r"(r[1]), "=r"(r[2]), "=r"(r[3]) : "r"(addr));
}
__device__ __forceinline__ void mma_bf(float* c, const uint32_t* a, const uint32_t* b) {
    asm volatile(
        "mma.sync.aligned.m16n8k16.row.col.f32.bf16.bf16.f32 "
        "{%0,%1,%2,%3}, {%4,%5,%6,%7}, {%8,%9}, {%0,%1,%2,%3};"
        : "+f"(c[0]), "+f"(c[1]), "+f"(c[2]), "+f"(c[3])
        : "r"(a[0]), "r"(a[1]), "r"(a[2]), "r"(a[3]), "r"(b[0]), "r"(b[1]));
}
__device__ __forceinline__ void mma_hf(float* c, const uint32_t* a, const uint32_t* b) {
    asm volatile(
        "mma.sync.aligned.m16n8k16.row.col.f32.f16.f16.f32 "
        "{%0,%1,%2,%3}, {%4,%5,%6,%7}, {%8,%9}, {%0,%1,%2,%3};"
        : "+f"(c[0]), "+f"(c[1]), "+f"(c[2]), "+f"(c[3])
        : "r"(a[0]), "r"(a[1]), "r"(a[2]), "r"(a[3]), "r"(b[0]), "r"(b[1]));
}

// ======================= conversions =======================================
__global__ __launch_bounds__(256) void split3_f32(const float* __restrict__ x,
                                                  __nv_bfloat16* __restrict__ A3) {
    size_t i = ((size_t)blockIdx.x * 256 + threadIdx.x) * 4;
    size_t m = i / DIM, k = i % DIM;
    float4 v = *reinterpret_cast<const float4*>(x + i);
    __nv_bfloat16 h0 = __float2bfloat16(v.x), h1 = __float2bfloat16(v.y);
    __nv_bfloat16 h2 = __float2bfloat16(v.z), h3 = __float2bfloat16(v.w);
    __nv_bfloat162 hA(h0, h1), hB(h2, h3);
    __nv_bfloat162 lA(__float2bfloat16(v.x - __bfloat162float(h0)),
                      __float2bfloat16(v.y - __bfloat162float(h1)));
    __nv_bfloat162 lB(__float2bfloat16(v.z - __bfloat162float(h2)),
                      __float2bfloat16(v.w - __bfloat162float(h3)));
    __nv_bfloat16* row = A3 + m * K3;
    *reinterpret_cast<__nv_bfloat162*>(row + k) = hA;
    *reinterpret_cast<__nv_bfloat162*>(row + k + 2) = hB;
    *reinterpret_cast<__nv_bfloat162*>(row + DIM + k) = hA;
    *reinterpret_cast<__nv_bfloat162*>(row + DIM + k + 2) = hB;
    *reinterpret_cast<__nv_bfloat162*>(row + 2 * DIM + k) = lA;
    *reinterpret_cast<__nv_bfloat162*>(row + 2 * DIM + k + 2) = lB;
}

__global__ __launch_bounds__(1024) void transpose_split3_all(
    const float* __restrict__ W0, const float* __restrict__ W1,
    const float* __restrict__ W2, const float* __restrict__ W3p,
    const float* __restrict__ W4, __nv_bfloat16* __restrict__ out)
{
    __shared__ float t[32][33];
    int z = blockIdx.z;
    const float* W = (z == 0) ? W0 : (z == 1) ? W1 : (z == 2) ? W2 : (z == 3) ? W3p : W4;
    int tx = threadIdx.x, ty = threadIdx.y;
    int k0 = blockIdx.y * 32, n0 = blockIdx.x * 32;
    t[ty][tx] = W[(size_t)(k0 + ty) * DIM + n0 + tx];
    __syncthreads();
    float v = t[tx][ty];
    __nv_bfloat16 h = __float2bfloat16(v);
    __nv_bfloat16 l = __float2bfloat16(v - __bfloat162float(h));
    __nv_bfloat16* row = out + (size_t)z * DIM * K3 + (size_t)(n0 + ty) * K3;
    row[k0 + tx] = h;
    row[DIM + k0 + tx] = l;
    row[2 * DIM + k0 + tx] = h;
}

__global__ __launch_bounds__(256) void mask_to_half(const float* __restrict__ m,
                                                    __half* __restrict__ mh) {
    size_t i = ((size_t)blockIdx.x * 256 + threadIdx.x) * 4;
    float4 v = *reinterpret_cast<const float4*>(m + i);
    __half2 a = __floats2half2_rn(v.x, v.y);
    __half2 b = __floats2half2_rn(v.z, v.w);
    *reinterpret_cast<__half2*>(mh + i) = a;
    *reinterpret_cast<__half2*>(mh + i + 2) = b;
}

// ======================= HMMA split-bf16 dense GEMM ========================
// mode 0: z<3 -> qkh fp16 hi/lo per-head (z==0 scaled by 0.125); z==3 -> sigmoid fp32 gate
// mode 1: plain fp32 + bias -> fOut
#define GEMM_SMEM (64 * 1024)
__global__ __launch_bounds__(256, 2) void gemm_hmma(
    const __nv_bfloat16* __restrict__ A3, const __nv_bfloat16* __restrict__ W3base,
    const float* b0, const float* b1, const float* b2, const float* b3,
    float* __restrict__ gateOut, __half* __restrict__ qkhOut,
    float* __restrict__ fOut, int mode)
{
    extern __shared__ char smem[];
    const uint32_t sb = smem_u32(smem);
    const int tid = threadIdx.x;
    const int wid = tid >> 5, lane = tid & 31;
    const int wm = wid & 3, wn = wid >> 2;
    const int z = blockIdx.z;
    const int m0 = blockIdx.y * 128, n0 = blockIdx.x * 128;

    const __nv_bfloat16* W3 = W3base + (size_t)z * DIM * K3;
    const float* bias = (z == 0) ? b0 : (z == 1) ? b1 : (z == 2) ? b2 : b3;

    const char* gA = (const char*)(A3 + (size_t)m0 * K3);
    const char* gB = (const char*)(W3 + (size_t)n0 * K3);

    auto load_stage = [&](int s) {
        const uint32_t base = sb + (s & 1) * 32768;
        const int kb = s * 128;
#pragma unroll
        for (int i = 0; i < 4; i++) {
            int c = tid + 256 * i;
            int row = c >> 3, cb = (c & 7) * 16;
            uint32_t d = swz128(row * 128 + cb);
            size_t src = (size_t)row * (K3 * 2) + kb + cb;
            cp_async16(base + d, gA + src);
            cp_async16(base + 16384 + d, gB + src);
        }
        CP_COMMIT();
    };

    float acc[2][8][4];
#pragma unroll
    for (int mi = 0; mi < 2; mi++)
#pragma unroll
        for (int ni = 0; ni < 8; ni++)
#pragma unroll
            for (int j = 0; j < 4; j++) acc[mi][ni][j] = 0.f;

    load_stage(0);
    load_stage(1);

    for (int s = 0; s < NSTG; s++) {
        if (s == NSTG - 1) { CP_WAIT(0); } else { CP_WAIT(1); }
        __syncthreads();
        const uint32_t abase = sb + (s & 1) * 32768;
        const uint32_t bbase = abase + 16384;
#pragma unroll
        for (int ki = 0; ki < 4; ki++) {
            uint32_t a[2][4];
#pragma unroll
            for (int mi = 0; mi < 2; mi++) {
                int row = wm * 32 + mi * 16 + (lane & 15);
                int kb = ki * 32 + ((lane >> 4) << 4);
                ldmx4(a[mi], abase + swz128(row * 128 + kb));
            }
#pragma unroll
            for (int pi = 0; pi < 4; pi++) {
                int nrow = wn * 64 + pi * 16 + ((lane >> 4) << 3) + (lane & 7);
                int kb = ki * 32 + ((lane >> 3) & 1) * 16;
                uint32_t b[4];
                ldmx4(b, bbase + swz128(nrow * 128 + kb));
#pragma unroll
                for (int mi = 0; mi < 2; mi++) {
                    mma_bf(acc[mi][2 * pi], a[mi], b);
                    mma_bf(acc[mi][2 * pi + 1], a[mi], b + 2);
                }
            }
        }
        __syncthreads();
        if (s + 2 < NSTG) load_stage(s + 2);
    }

    const int rbase = m0 + wm * 32;
    const int cbase = n0 + wn * 64;
#pragma unroll
    for (int mi = 0; mi < 2; mi++) {
#pragma unroll
        for (int ni = 0; ni < 8; ni++) {
            int row = rbase + mi * 16 + (lane >> 2);
            int col = cbase + ni * 8 + (lane & 3) * 2;
            float bx = bias[col], by = bias[col + 1];
            float vx0 = acc[mi][ni][0] + bx, vy0 = acc[mi][ni][1] + by;
            float vx1 = acc[mi][ni][2] + bx, vy1 = acc[mi][ni][3] + by;
            if (mode == 1) {
                *reinterpret_cast<float2*>(&fOut[(size_t)row * DIM + col]) =
                    make_float2(vx0, vy0);
                *reinterpret_cast<float2*>(&fOut[(size_t)(row + 8) * DIM + col]) =
                    make_float2(vx1, vy1);
            } else if (z == 3) {
                float2 g0 = {1.f / (1.f + expf(-vx0)), 1.f / (1.f + expf(-vy0))};
                float2 g1 = {1.f / (1.f + expf(-vx1)), 1.f / (1.f + expf(-vy1))};
                *reinterpret_cast<float2*>(&gateOut[(size_t)row * DIM + col]) = g0;
                *reinterpret_cast<float2*>(&gateOut[(size_t)(row + 8) * DIM + col]) = g1;
            } else {
                if (z == 0) { vx0 *= 0.125f; vy0 *= 0.125f; vx1 *= 0.125f; vy1 *= 0.125f; }
                int h = col >> 6, d = col & 63;
#pragma unroll
                for (int rr = 0; rr < 2; rr++) {
                    int rw = row + rr * 8;
                    float vx = rr ? vx1 : vx0, vy = rr ? vy1 : vy0;
                    int bh = (rw >> 11) * NH + h, s = rw & 2047;
                    __half hx = __float2half_rn(vx), hy = __float2half_rn(vy);
                    __half2 hi2(hx, hy);
                    __half2 lo2(__float2half_rn(vx - __half2float(hx)),
                                __float2half_rn(vy - __half2float(hy)));
                    size_t bi = ((((size_t)z * 2 + 0) * NBH + bh) * SEQ + s) * HD + d;
                    size_t bl = ((((size_t)z * 2 + 1) * NBH + bh) * SEQ + s) * HD + d;
                    *reinterpret_cast<__half2*>(qkhOut + bi) = hi2;
                    *reinterpret_cast<__half2*>(qkhOut + bl) = lo2;
                }
            }
        }
    }
}

// ======================= fused flash attention v2 ==========================
// k-tile 64, 2 stages, 96KB smem, 2 CTAs/SM.
// smem: QH 0 (16K), QL 16K | stage s at 32K+s*32K: KH +0 (8K), KL +8K, VH +16K, VL +24K
#define FL_SMEM (96 * 1024)
#define NKB 32
__global__ __launch_bounds__(256, 2) void flash_attn(
    const __half* __restrict__ qkh, const __half* __restrict__ maskh,
    const unsigned char* __restrict__ pad, const float* __restrict__ gate,
    __half* __restrict__ E, float* __restrict__ rinv,
    __nv_bfloat16* __restrict__ att3)
{
    extern __shared__ char smem[];
    const uint32_t sb = smem_u32(smem);
    const int tid = threadIdx.x;
    const int w = tid >> 5, lane = tid & 31;
    const int bhz = blockIdx.z, qb = blockIdx.y;
    const int bb = bhz >> 4, hh = bhz & 15;

    const __half* Qh = qkh + ((size_t)(0 * 2 + 0) * NBH + bhz) * SEQ * HD;
    const __half* Ql = qkh + ((size_t)(0 * 2 + 1) * NBH + bhz) * SEQ * HD;
    const __half* Kh = qkh + ((size_t)(1 * 2 + 0) * NBH + bhz) * SEQ * HD;
    const __half* Kl = qkh + ((size_t)(1 * 2 + 1) * NBH + bhz) * SEQ * HD;
    const __half* Vh = qkh + ((size_t)(2 * 2 + 0) * NBH + bhz) * SEQ * HD;
    const __half* Vl = qkh + ((size_t)(2 * 2 + 1) * NBH + bhz) * SEQ * HD;

    // Q tiles (128 rows x 128B hi+lo)
#pragma unroll
    for (int i = 0; i < 4; i++) {
        int c = tid + 256 * i;
        int row = c >> 3, cb = (c & 7) * 16;
        uint32_t d = swz128(row * 128 + cb);
        size_t src = (size_t)(qb * 128 + row) * (HD * 2) + cb;
        cp_async16(sb + d, (const char*)Qh + src);
        cp_async16(sb + 16384 + d, (const char*)Ql + src);
    }
    auto load_kv = [&](int kb, int st) {
        const uint32_t base = sb + 32768 + st * 32768;
#pragma unroll
        for (int i = 0; i < 2; i++) {
            int c = tid + 256 * i;
            int row = c >> 3, cb = (c & 7) * 16;
            uint32_t d = swz128(row * 128 + cb);
            size_t src = (size_t)(kb * 64 + row) * (HD * 2) + cb;
            cp_async16(base + d, (const char*)Kh + src);
            cp_async16(base + 8192 + d, (const char*)Kl + src);
            cp_async16(base + 16384 + d, (const char*)Vh + src);
            cp_async16(base + 24576 + d, (const char*)Vl + src);
        }
        CP_COMMIT();
    };
    load_kv(0, 0);   // group also covers Q loads
    load_kv(1, 1);

    float O[8][4];
#pragma unroll
    for (int ni = 0; ni < 8; ni++)
#pragma unroll
        for (int j = 0; j < 4; j++) O[ni][j] = 0.f;

    float rs0 = 0.f, rs1 = 0.f;
    const int q_r0 = qb * 128 + w * 16 + (lane >> 2);
    const int q_r1 = q_r0 + 8;
    __half* Eb = E + (size_t)bhz * SEQ * SEQ;

    for (int kb = 0; kb < NKB; kb++) {
        if (kb == NKB - 1) { CP_WAIT(0); } else { CP_WAIT(1); }
        __syncthreads();
        const uint32_t kbase = sb + 32768 + (kb & 1) * 32768;
        const uint32_t vbase = kbase + 16384;

        // prefetch mask (fp16) for this tile — independent of MMA results
        uint32_t m0r[8], m1r[8];
#pragma unroll
        for (int ni = 0; ni < 8; ni++) {
            int kcol = kb * 64 + ni * 8 + (lane & 3) * 2;
            m0r[ni] = *reinterpret_cast<const uint32_t*>(maskh + (size_t)q_r0 * SEQ + kcol);
            m1r[ni] = *reinterpret_cast<const uint32_t*>(maskh + (size_t)q_r1 * SEQ + kcol);
        }

        // ---- S = Q K^T (3-term fp16) ----
        float acc[8][4];
#pragma unroll
        for (int ni = 0; ni < 8; ni++)
#pragma unroll
            for (int j = 0; j < 4; j++) acc[ni][j] = 0.f;

#pragma unroll
        for (int ki = 0; ki < 4; ki++) {
            uint32_t ah[4], al[4];
            {
                int row = w * 16 + (lane & 15);
                int kbyte = ki * 32 + ((lane >> 4) << 4);
                ldmx4(ah, sb + swz128(row * 128 + kbyte));
                ldmx4(al, sb + 16384 + swz128(row * 128 + kbyte));
            }
#pragma unroll
            for (int pi = 0; pi < 4; pi++) {
                int nrow = pi * 16 + ((lane >> 4) << 3) + (lane & 7);
                int kbyte = ki * 32 + ((lane >> 3) & 1) * 16;
                uint32_t bh4[4], bl4[4];
                ldmx4(bh4, kbase + swz128(nrow * 128 + kbyte));
                ldmx4(bl4, kbase + 8192 + swz128(nrow * 128 + kbyte));
                mma_hf(acc[2 * pi], ah, bh4);
                mma_hf(acc[2 * pi], ah, bl4);
                mma_hf(acc[2 * pi], al, bh4);
                mma_hf(acc[2 * pi + 1], ah, bh4 + 2);
                mma_hf(acc[2 * pi + 1], ah, bl4 + 2);
                mma_hf(acc[2 * pi + 1], al, bh4 + 2);
            }
        }

        // ---- epilogue: exp, rowsum, store E fp16, pack A-fragments ----
        uint32_t e16[4][4];
#pragma unroll
        for (int ni = 0; ni < 8; ni++) {
            int kcol = kb * 64 + ni * 8 + (lane & 3) * 2;
            uchar2 pd = *reinterpret_cast<const uchar2*>(pad + bb * SEQ + kcol);
            float2 m0 = __half22float2(*reinterpret_cast<__half2*>(&m0r[ni]));
            float2 m1 = __half22float2(*reinterpret_cast<__half2*>(&m1r[ni]));
            float e00 = pd.x ? 0.f : __expf(acc[ni][0] + m0.x);
            float e01 = pd.y ? 0.f : __expf(acc[ni][1] + m0.y);
            float e10 = pd.x ? 0.f : __expf(acc[ni][2] + m1.x);
            float e11 = pd.y ? 0.f : __expf(acc[ni][3] + m1.y);
            rs0 += e00 + e01;
            rs1 += e10 + e11;
            __half2 h0 = __floats2half2_rn(e00, e01);
            __half2 h1 = __floats2half2_rn(e10, e11);
            *reinterpret_cast<__half2*>(Eb + (size_t)q_r0 * SEQ + kcol) = h0;
            *reinterpret_cast<__half2*>(Eb + (size_t)q_r1 * SEQ + kcol) = h1;
            int ki = ni >> 1, hi = (ni & 1) * 2;
            e16[ki][hi + 0] = *reinterpret_cast<uint32_t*>(&h0);
            e16[ki][hi + 1] = *reinterpret_cast<uint32_t*>(&h1);
        }

        // ---- O += E @ V (2-term fp16) ----
#pragma unroll
        for (int ki = 0; ki < 4; ki++) {
#pragma unroll
            for (int pi = 0; pi < 4; pi++) {
                int vrow = ki * 16 + (lane & 15);
                int vbyte = pi * 32 + ((lane >> 4) << 4);
                uint32_t vh4[4], vl4[4];
                ldmx4t(vh4, vbase + swz128(vrow * 128 + vbyte));
                ldmx4t(vl4, vbase + 8192 + swz128(vrow * 128 + vbyte));
                mma_hf(O[2 * pi], e16[ki], vh4);
                mma_hf(O[2 * pi], e16[ki], vl4);
                mma_hf(O[2 * pi + 1], e16[ki], vh4 + 2);
                mma_hf(O[2 * pi + 1], e16[ki], vl4 + 2);
            }
        }
        __syncthreads();
        if (kb + 2 < NKB) load_kv(kb + 2, kb & 1);
    }

    // rowsum reduce across quad
#pragma unroll
    for (int o = 1; o < 4; o <<= 1) {
        rs0 += __shfl_xor_sync(0xffffffffu, rs0, o);
        rs1 += __shfl_xor_sync(0xffffffffu, rs1, o);
    }
    float ri0 = 1.f / rs0, ri1 = 1.f / rs1;
    if ((lane & 3) == 0) {
        rinv[(size_t)bhz * SEQ + q_r0] = ri0;
        rinv[(size_t)bhz * SEQ + q_r1] = ri1;
    }

    // epilogue: O * rinv * gate -> att3 (split3 bf16 layout [hi|hi|lo])
#pragma unroll
    for (int ni = 0; ni < 8; ni++) {
        int d = ni * 8 + (lane & 3) * 2;
        int col = hh * HD + d;
#pragma unroll
        for (int rr = 0; rr < 2; rr++) {
            int qr = rr ? q_r1 : q_r0;
            float ri = rr ? ri1 : ri0;
            size_t gi = ((size_t)bb * SEQ + qr) * DIM + col;
            float2 g = *reinterpret_cast<const float2*>(gate + gi);
            float ox = O[ni][rr * 2 + 0] * ri * g.x;
            float oy = O[ni][rr * 2 + 1] * ri * g.y;
            __nv_bfloat16 hx = __float2bfloat16(ox), hy = __float2bfloat16(oy);
            __nv_bfloat162 hi2(hx, hy);
            __nv_bfloat162 lo2(__float2bfloat16(ox - __bfloat162float(hx)),
                               __float2bfloat16(oy - __bfloat162float(hy)));
            __nv_bfloat16* rowp = att3 + ((size_t)bb * SEQ + qr) * K3;
            *reinterpret_cast<__nv_bfloat162*>(rowp + col) = hi2;
            *reinterpret_cast<__nv_bfloat162*>(rowp + DIM + col) = hi2;
            *reinterpret_cast<__nv_bfloat162*>(rowp + 2 * DIM + col) = lo2;
        }
    }
}

// ======================= avg over heads (fp16 E) ===========================
__global__ __launch_bounds__(512) void avg_kernel(
    const __half* __restrict__ E, const float* __restrict__ rinv,
    float* __restrict__ avg)
{
    int bq = blockIdx.x;
    int b = bq >> 11, q = bq & 2047;
    int k4 = threadIdx.x * 4;
    float4 s = {0.f, 0.f, 0.f, 0.f};
#pragma unroll
    for (int h = 0; h < NH; h++) {
        float ri = rinv[(size_t)(b * NH + h) * SEQ + q] * (1.f / NH);
        const __half2* p = reinterpret_cast<const __half2*>(
            E + ((size_t)(b * NH + h) * SEQ + q) * SEQ + k4);
        float2 f0 = __half22float2(p[0]);
        float2 f1 = __half22float2(p[1]);
        s.x += f0.x * ri; s.y += f0.y * ri;
        s.z += f1.x * ri; s.w += f1.y * ri;
    }
    *reinterpret_cast<float4*>(avg + (size_t)bq * SEQ + k4) = s;
}

// ---------------- launch -----------------------------------------------------
extern "C" void kernel_launch(void* const* d_in, const int* in_sizes, int n_in,
                              void* d_out, int out_size)
{
    (void)in_sizes; (void)n_in; (void)out_size;
    const float* x    = (const float*)d_in[0];
    const float* mask = (const float*)d_in[1];
    const unsigned char* pad = (const unsigned char*)d_in[2];
    const float* Wq = (const float*)d_in[3];
    const float* bq = (const float*)d_in[4];
    const float* Wk = (const float*)d_in[5];
    const float* bk = (const float*)d_in[6];
    const float* Wv = (const float*)d_in[7];
    const float* bv = (const float*)d_in[8];
    const float* Wg = (const float*)d_in[9];
    const float* bg = (const float*)d_in[10];
    const float* Wo = (const float*)d_in[11];
    const float* bo = (const float*)d_in[12];
    float* out = (float*)d_out;

    float *gate, *rinv;
    __half *E, *qkh, *maskh;
    __nv_bfloat16 *a3, *w3;
    cudaGetSymbolAddress((void**)&gate, g_gate);
    cudaGetSymbolAddress((void**)&E, g_E);
    cudaGetSymbolAddress((void**)&rinv, g_rinv);
    cudaGetSymbolAddress((void**)&a3, g_a3);
    cudaGetSymbolAddress((void**)&w3, g_w3);
    cudaGetSymbolAddress((void**)&qkh, g_qkh);
    cudaGetSymbolAddress((void**)&maskh, g_maskh);

    static bool attrSet = false;
    if (!attrSet) {
        cudaFuncSetAttribute(gemm_hmma, cudaFuncAttributeMaxDynamicSharedMemorySize, GEMM_SMEM);
        cudaFuncSetAttribute(flash_attn, cudaFuncAttributeMaxDynamicSharedMemorySize, FL_SMEM);
        attrSet = true;
    }

    // 1) conversions
    split3_f32<<<(MTOT * DIM) / 1024, 256>>>(x, a3);
    transpose_split3_all<<<dim3(DIM / 32, DIM / 32, 5), dim3(32, 32)>>>(
        Wq, Wk, Wv, Wg, Wo, w3);
    mask_to_half<<<(SEQ * SEQ) / 1024, 256>>>(mask, maskh);

    // 2) q,k,v,gate projections; q/k/v direct to per-head fp16 hi/lo (q pre-scaled)
    gemm_hmma<<<dim3(DIM / 128, MTOT / 128, 4), 256, GEMM_SMEM>>>(
        a3, w3, bq, bk, bv, bg, gate, qkh, nullptr, 0);

    // 3) fused flash: scores+exp+E store+PV+gate -> att3 (split3 layout)
    flash_attn<<<dim3(1, SEQ / 128, NBH), 256, FL_SMEM>>>(
        qkh, maskh, pad, gate, E, rinv, a3);

    // 4) avg over heads
    avg_kernel<<<BB * SEQ, 512>>>(E, rinv, out + (size_t)MTOT * DIM);

    // 5) O projection
    gemm_hmma<<<dim3(DIM / 128, MTOT / 128, 1), 256, GEMM_SMEM>>>(
        a3, w3 + 4ull * DIM * K3, bo, bo, bo, bo, nullptr, nullptr, out, 1);
}

// round 7
// speedup vs baseline: 3.8551x; 1.0910x over previous
#include <cuda_runtime.h>
#include <cuda_bf16.h>
#include <cuda_fp16.h>
#include <math.h>
#include <stdint.h>

// Fixed problem shape
#define BB 2
#define SEQ 2048
#define DIM 1024
#define NH 16
#define HD 64
#define MTOT (BB * SEQ)            // 4096
#define K3 (3 * DIM)               // 3072
#define NSTG 48                    // K3 / 64
#define NBH (BB * NH)              // 32

// ---------------- scratch ----------------------------------------------------
__device__ float g_gate[(size_t)MTOT * DIM];           // sigmoid gate fp32
__device__ __half g_E[(size_t)NBH * SEQ * SEQ];        // unnormalized exp, fp16
__device__ float g_rinv[(size_t)NBH * SEQ];            // 1/rowsum
__device__ __nv_bfloat16 g_a3[(size_t)MTOT * K3];      // [Ah|Ah|Al] (x, then att)
__device__ __nv_bfloat16 g_w3[5ull * DIM * K3];        // [Wh|Wl|Wh] N-major
__device__ __half g_qkh[3ull * 2 * NBH * SEQ * HD];    // q,k,v per-head hi/lo fp16
__device__ __half g_maskh[(size_t)SEQ * SEQ];          // mask fp16

// ======================= helpers ===========================================
__device__ __forceinline__ uint32_t smem_u32(const void* p) {
    uint32_t a;
    asm("{ .reg .u64 t; cvta.to.shared.u64 t, %1; cvt.u32.u64 %0, t; }"
        : "=r"(a) : "l"(p));
    return a;
}
__device__ __forceinline__ uint32_t swz128(uint32_t o) { return o ^ ((o >> 3) & 0x70); }

__device__ __forceinline__ void cp_async16(uint32_t dst, const void* src) {
    asm volatile("cp.async.cg.shared.global [%0], [%1], 16;" :: "r"(dst), "l"(src));
}
#define CP_COMMIT() asm volatile("cp.async.commit_group;" ::: "memory")
#define CP_WAIT(n)  asm volatile("cp.async.wait_group %0;" :: "n"(n) : "memory")

__device__ __forceinline__ void ldmx4(uint32_t* r, uint32_t addr) {
    asm volatile("ldmatrix.sync.aligned.m8n8.x4.shared.b16 {%0,%1,%2,%3}, [%4];"
                 : "=r"(r[0]), "=r"(r[1]), "=r"(r[2]), "=r"(r[3]) : "r"(addr));
}
__device__ __forceinline__ void ldmx4t(uint32_t* r, uint32_t addr) {
    asm volatile("ldmatrix.sync.aligned.m8n8.x4.trans.shared.b16 {%0,%1,%2,%3}, [%4];"
                 : "=r"(r[0]), "=r"(r[1]), "=r"(r[2]), "=r"(r[3]) : "r"(addr));
}
__device__ __forceinline__ void mma_bf(float* c, const uint32_t* a, const uint32_t* b) {
    asm volatile(
        "mma.sync.aligned.m16n8k16.row.col.f32.bf16.bf16.f32 "
        "{%0,%1,%2,%3}, {%4,%5,%6,%7}, {%8,%9}, {%0,%1,%2,%3};"
        : "+f"(c[0]), "+f"(c[1]), "+f"(c[2]), "+f"(c[3])
        : "r"(a[0]), "r"(a[1]), "r"(a[2]), "r"(a[3]), "r"(b[0]), "r"(b[1]));
}
__device__ __forceinline__ void mma_hf(float* c, const uint32_t* a, const uint32_t* b) {
    asm volatile(
        "mma.sync.aligned.m16n8k16.row.col.f32.f16.f16.f32 "
        "{%0,%1,%2,%3}, {%4,%5,%6,%7}, {%8,%9}, {%0,%1,%2,%3};"
        : "+f"(c[0]), "+f"(c[1]), "+f"(c[2]), "+f"(c[3])
        : "r"(a[0]), "r"(a[1]), "r"(a[2]), "r"(a[3]), "r"(b[0]), "r"(b[1]));
}

// ======================= conversions =======================================
__global__ __launch_bounds__(256) void split3_f32(const float* __restrict__ x,
                                                  __nv_bfloat16* __restrict__ A3) {
    size_t i = ((size_t)blockIdx.x * 256 + threadIdx.x) * 4;
    size_t m = i / DIM, k = i % DIM;
    float4 v = *reinterpret_cast<const float4*>(x + i);
    __nv_bfloat16 h0 = __float2bfloat16(v.x), h1 = __float2bfloat16(v.y);
    __nv_bfloat16 h2 = __float2bfloat16(v.z), h3 = __float2bfloat16(v.w);
    __nv_bfloat162 hA(h0, h1), hB(h2, h3);
    __nv_bfloat162 lA(__float2bfloat16(v.x - __bfloat162float(h0)),
                      __float2bfloat16(v.y - __bfloat162float(h1)));
    __nv_bfloat162 lB(__float2bfloat16(v.z - __bfloat162float(h2)),
                      __float2bfloat16(v.w - __bfloat162float(h3)));
    __nv_bfloat16* row = A3 + m * K3;
    *reinterpret_cast<__nv_bfloat162*>(row + k) = hA;
    *reinterpret_cast<__nv_bfloat162*>(row + k + 2) = hB;
    *reinterpret_cast<__nv_bfloat162*>(row + DIM + k) = hA;
    *reinterpret_cast<__nv_bfloat162*>(row + DIM + k + 2) = hB;
    *reinterpret_cast<__nv_bfloat162*>(row + 2 * DIM + k) = lA;
    *reinterpret_cast<__nv_bfloat162*>(row + 2 * DIM + k + 2) = lB;
}

__global__ __launch_bounds__(1024) void transpose_split3_all(
    const float* __restrict__ W0, const float* __restrict__ W1,
    const float* __restrict__ W2, const float* __restrict__ W3p,
    const float* __restrict__ W4, __nv_bfloat16* __restrict__ out)
{
    __shared__ float t[32][33];
    int z = blockIdx.z;
    const float* W = (z == 0) ? W0 : (z == 1) ? W1 : (z == 2) ? W2 : (z == 3) ? W3p : W4;
    int tx = threadIdx.x, ty = threadIdx.y;
    int k0 = blockIdx.y * 32, n0 = blockIdx.x * 32;
    t[ty][tx] = W[(size_t)(k0 + ty) * DIM + n0 + tx];
    __syncthreads();
    float v = t[tx][ty];
    __nv_bfloat16 h = __float2bfloat16(v);
    __nv_bfloat16 l = __float2bfloat16(v - __bfloat162float(h));
    __nv_bfloat16* row = out + (size_t)z * DIM * K3 + (size_t)(n0 + ty) * K3;
    row[k0 + tx] = h;
    row[DIM + k0 + tx] = l;
    row[2 * DIM + k0 + tx] = h;
}

__global__ __launch_bounds__(256) void mask_to_half(const float* __restrict__ m,
                                                    __half* __restrict__ mh) {
    size_t i = ((size_t)blockIdx.x * 256 + threadIdx.x) * 4;
    float4 v = *reinterpret_cast<const float4*>(m + i);
    __half2 a = __floats2half2_rn(v.x, v.y);
    __half2 b = __floats2half2_rn(v.z, v.w);
    *reinterpret_cast<__half2*>(mh + i) = a;
    *reinterpret_cast<__half2*>(mh + i + 2) = b;
}

// ======================= HMMA split-bf16 dense GEMM (3-stage) ==============
// mode 0: z<3 -> qkh fp16 hi/lo per-head (z==0 scaled by 0.125); z==3 -> sigmoid gate
// mode 1: plain fp32 + bias -> fOut
#define GEMM_SMEM (96 * 1024)
__global__ __launch_bounds__(256, 2) void gemm_hmma(
    const __nv_bfloat16* __restrict__ A3, const __nv_bfloat16* __restrict__ W3base,
    const float* b0, const float* b1, const float* b2, const float* b3,
    float* __restrict__ gateOut, __half* __restrict__ qkhOut,
    float* __restrict__ fOut, int mode)
{
    extern __shared__ char smem[];
    const uint32_t sb = smem_u32(smem);
    const int tid = threadIdx.x;
    const int wid = tid >> 5, lane = tid & 31;
    const int wm = wid & 3, wn = wid >> 2;
    const int z = blockIdx.z;
    const int m0 = blockIdx.y * 128, n0 = blockIdx.x * 128;

    const __nv_bfloat16* W3 = W3base + (size_t)z * DIM * K3;
    const float* bias = (z == 0) ? b0 : (z == 1) ? b1 : (z == 2) ? b2 : b3;

    const char* gA = (const char*)(A3 + (size_t)m0 * K3);
    const char* gB = (const char*)(W3 + (size_t)n0 * K3);

    auto load_stage = [&](int s) {
        const uint32_t base = sb + (s % 3) * 32768;
        const int kb = s * 128;
#pragma unroll
        for (int i = 0; i < 4; i++) {
            int c = tid + 256 * i;
            int row = c >> 3, cb = (c & 7) * 16;
            uint32_t d = swz128(row * 128 + cb);
            size_t src = (size_t)row * (K3 * 2) + kb + cb;
            cp_async16(base + d, gA + src);
            cp_async16(base + 16384 + d, gB + src);
        }
        CP_COMMIT();
    };

    float acc[2][8][4];
#pragma unroll
    for (int mi = 0; mi < 2; mi++)
#pragma unroll
        for (int ni = 0; ni < 8; ni++)
#pragma unroll
            for (int j = 0; j < 4; j++) acc[mi][ni][j] = 0.f;

    load_stage(0);
    load_stage(1);
    load_stage(2);

    for (int s = 0; s < NSTG; s++) {
        if (s >= NSTG - 1)      { CP_WAIT(0); }
        else if (s == NSTG - 2) { CP_WAIT(1); }
        else                    { CP_WAIT(2); }
        __syncthreads();
        const uint32_t abase = sb + (s % 3) * 32768;
        const uint32_t bbase = abase + 16384;
#pragma unroll
        for (int ki = 0; ki < 4; ki++) {
            uint32_t a[2][4];
#pragma unroll
            for (int mi = 0; mi < 2; mi++) {
                int row = wm * 32 + mi * 16 + (lane & 15);
                int kb = ki * 32 + ((lane >> 4) << 4);
                ldmx4(a[mi], abase + swz128(row * 128 + kb));
            }
#pragma unroll
            for (int pi = 0; pi < 4; pi++) {
                int nrow = wn * 64 + pi * 16 + ((lane >> 4) << 3) + (lane & 7);
                int kb = ki * 32 + ((lane >> 3) & 1) * 16;
                uint32_t b[4];
                ldmx4(b, bbase + swz128(nrow * 128 + kb));
#pragma unroll
                for (int mi = 0; mi < 2; mi++) {
                    mma_bf(acc[mi][2 * pi], a[mi], b);
                    mma_bf(acc[mi][2 * pi + 1], a[mi], b + 2);
                }
            }
        }
        __syncthreads();
        if (s + 3 < NSTG) load_stage(s + 3);
    }

    const int rbase = m0 + wm * 32;
    const int cbase = n0 + wn * 64;
#pragma unroll
    for (int mi = 0; mi < 2; mi++) {
#pragma unroll
        for (int ni = 0; ni < 8; ni++) {
            int row = rbase + mi * 16 + (lane >> 2);
            int col = cbase + ni * 8 + (lane & 3) * 2;
            float bx = bias[col], by = bias[col + 1];
            float vx0 = acc[mi][ni][0] + bx, vy0 = acc[mi][ni][1] + by;
            float vx1 = acc[mi][ni][2] + bx, vy1 = acc[mi][ni][3] + by;
            if (mode == 1) {
                *reinterpret_cast<float2*>(&fOut[(size_t)row * DIM + col]) =
                    make_float2(vx0, vy0);
                *reinterpret_cast<float2*>(&fOut[(size_t)(row + 8) * DIM + col]) =
                    make_float2(vx1, vy1);
            } else if (z == 3) {
                float2 g0 = {1.f / (1.f + expf(-vx0)), 1.f / (1.f + expf(-vy0))};
                float2 g1 = {1.f / (1.f + expf(-vx1)), 1.f / (1.f + expf(-vy1))};
                *reinterpret_cast<float2*>(&gateOut[(size_t)row * DIM + col]) = g0;
                *reinterpret_cast<float2*>(&gateOut[(size_t)(row + 8) * DIM + col]) = g1;
            } else {
                if (z == 0) { vx0 *= 0.125f; vy0 *= 0.125f; vx1 *= 0.125f; vy1 *= 0.125f; }
                int h = col >> 6, d = col & 63;
#pragma unroll
                for (int rr = 0; rr < 2; rr++) {
                    int rw = row + rr * 8;
                    float vx = rr ? vx1 : vx0, vy = rr ? vy1 : vy0;
                    int bh = (rw >> 11) * NH + h, s = rw & 2047;
                    __half hx = __float2half_rn(vx), hy = __float2half_rn(vy);
                    __half2 hi2(hx, hy);
                    __half2 lo2(__float2half_rn(vx - __half2float(hx)),
                                __float2half_rn(vy - __half2float(hy)));
                    size_t bi = ((((size_t)z * 2 + 0) * NBH + bh) * SEQ + s) * HD + d;
                    size_t bl = ((((size_t)z * 2 + 1) * NBH + bh) * SEQ + s) * HD + d;
                    *reinterpret_cast<__half2*>(qkhOut + bi) = hi2;
                    *reinterpret_cast<__half2*>(qkhOut + bl) = lo2;
                }
            }
        }
    }
}

// ======================= fused flash attention v3 ==========================
// k-tile 64, 2 stages + 16KB E staging => 112KB smem, 2 CTAs/SM.
// smem: QH 0 (16K), QL 16K | stage s at 32K+s*32K | E staging 96K (16K)
#define FL_SMEM (112 * 1024)
#define STG_OFF (96 * 1024)
#define NKB 32
__global__ __launch_bounds__(256, 2) void flash_attn(
    const __half* __restrict__ qkh, const __half* __restrict__ maskh,
    const unsigned char* __restrict__ pad, const float* __restrict__ gate,
    __half* __restrict__ E, float* __restrict__ rinv,
    __nv_bfloat16* __restrict__ att3)
{
    extern __shared__ char smem[];
    const uint32_t sb = smem_u32(smem);
    const int tid = threadIdx.x;
    const int w = tid >> 5, lane = tid & 31;
    const int bhz = blockIdx.z, qb = blockIdx.y;
    const int bb = bhz >> 4, hh = bhz & 15;

    const __half* Qh = qkh + ((size_t)(0 * 2 + 0) * NBH + bhz) * SEQ * HD;
    const __half* Ql = qkh + ((size_t)(0 * 2 + 1) * NBH + bhz) * SEQ * HD;
    const __half* Kh = qkh + ((size_t)(1 * 2 + 0) * NBH + bhz) * SEQ * HD;
    const __half* Kl = qkh + ((size_t)(1 * 2 + 1) * NBH + bhz) * SEQ * HD;
    const __half* Vh = qkh + ((size_t)(2 * 2 + 0) * NBH + bhz) * SEQ * HD;
    const __half* Vl = qkh + ((size_t)(2 * 2 + 1) * NBH + bhz) * SEQ * HD;

#pragma unroll
    for (int i = 0; i < 4; i++) {
        int c = tid + 256 * i;
        int row = c >> 3, cb = (c & 7) * 16;
        uint32_t d = swz128(row * 128 + cb);
        size_t src = (size_t)(qb * 128 + row) * (HD * 2) + cb;
        cp_async16(sb + d, (const char*)Qh + src);
        cp_async16(sb + 16384 + d, (const char*)Ql + src);
    }
    auto load_kv = [&](int kb, int st) {
        const uint32_t base = sb + 32768 + st * 32768;
#pragma unroll
        for (int i = 0; i < 2; i++) {
            int c = tid + 256 * i;
            int row = c >> 3, cb = (c & 7) * 16;
            uint32_t d = swz128(row * 128 + cb);
            size_t src = (size_t)(kb * 64 + row) * (HD * 2) + cb;
            cp_async16(base + d, (const char*)Kh + src);
            cp_async16(base + 8192 + d, (const char*)Kl + src);
            cp_async16(base + 16384 + d, (const char*)Vh + src);
            cp_async16(base + 24576 + d, (const char*)Vl + src);
        }
        CP_COMMIT();
    };
    load_kv(0, 0);
    load_kv(1, 1);

    float O[8][4];
#pragma unroll
    for (int ni = 0; ni < 8; ni++)
#pragma unroll
        for (int j = 0; j < 4; j++) O[ni][j] = 0.f;

    float rs0 = 0.f, rs1 = 0.f;
    const int r0l = w * 16 + (lane >> 2);          // local row
    const int q_r0 = qb * 128 + r0l;
    const int q_r1 = q_r0 + 8;
    __half* Eb = E + (size_t)bhz * SEQ * SEQ;

    for (int kb = 0; kb < NKB; kb++) {
        if (kb == NKB - 1) { CP_WAIT(0); } else { CP_WAIT(1); }
        __syncthreads();
        const uint32_t kbase = sb + 32768 + (kb & 1) * 32768;
        const uint32_t vbase = kbase + 16384;

        // prefetch mask (fp16) — independent of MMA results
        uint32_t m0r[8], m1r[8];
#pragma unroll
        for (int ni = 0; ni < 8; ni++) {
            int kcol = kb * 64 + ni * 8 + (lane & 3) * 2;
            m0r[ni] = *reinterpret_cast<const uint32_t*>(maskh + (size_t)q_r0 * SEQ + kcol);
            m1r[ni] = *reinterpret_cast<const uint32_t*>(maskh + (size_t)q_r1 * SEQ + kcol);
        }

        // ---- S = Q K^T (3-term fp16) ----
        float acc[8][4];
#pragma unroll
        for (int ni = 0; ni < 8; ni++)
#pragma unroll
            for (int j = 0; j < 4; j++) acc[ni][j] = 0.f;

#pragma unroll
        for (int ki = 0; ki < 4; ki++) {
            uint32_t ah[4], al[4];
            {
                int row = w * 16 + (lane & 15);
                int kbyte = ki * 32 + ((lane >> 4) << 4);
                ldmx4(ah, sb + swz128(row * 128 + kbyte));
                ldmx4(al, sb + 16384 + swz128(row * 128 + kbyte));
            }
#pragma unroll
            for (int pi = 0; pi < 4; pi++) {
                int nrow = pi * 16 + ((lane >> 4) << 3) + (lane & 7);
                int kbyte = ki * 32 + ((lane >> 3) & 1) * 16;
                uint32_t bh4[4], bl4[4];
                ldmx4(bh4, kbase + swz128(nrow * 128 + kbyte));
                ldmx4(bl4, kbase + 8192 + swz128(nrow * 128 + kbyte));
                mma_hf(acc[2 * pi], ah, bh4);
                mma_hf(acc[2 * pi], ah, bl4);
                mma_hf(acc[2 * pi], al, bh4);
                mma_hf(acc[2 * pi + 1], ah, bh4 + 2);
                mma_hf(acc[2 * pi + 1], ah, bl4 + 2);
                mma_hf(acc[2 * pi + 1], al, bh4 + 2);
            }
        }

        // ---- epilogue: exp, rowsum, stage E in smem, pack A-fragments ----
        uint32_t e16[4][4];
#pragma unroll
        for (int ni = 0; ni < 8; ni++) {
            int kc2 = ni * 8 + (lane & 3) * 2;     // local col
            int kcol = kb * 64 + kc2;
            uchar2 pd = *reinterpret_cast<const uchar2*>(pad + bb * SEQ + kcol);
            float2 m0 = __half22float2(*reinterpret_cast<__half2*>(&m0r[ni]));
            float2 m1 = __half22float2(*reinterpret_cast<__half2*>(&m1r[ni]));
            float e00 = pd.x ? 0.f : __expf(acc[ni][0] + m0.x);
            float e01 = pd.y ? 0.f : __expf(acc[ni][1] + m0.y);
            float e10 = pd.x ? 0.f : __expf(acc[ni][2] + m1.x);
            float e11 = pd.y ? 0.f : __expf(acc[ni][3] + m1.y);
            rs0 += e00 + e01;
            rs1 += e10 + e11;
            __half2 h0 = __floats2half2_rn(e00, e01);
            __half2 h1 = __floats2half2_rn(e10, e11);
            // stage into smem (swizzled); 128 rows x 64 cols fp16 = 128B/row
            *reinterpret_cast<__half2*>(smem + STG_OFF + swz128(r0l * 128 + kc2 * 2)) = h0;
            *reinterpret_cast<__half2*>(smem + STG_OFF + swz128((r0l + 8) * 128 + kc2 * 2)) = h1;
            int ki = ni >> 1, hi = (ni & 1) * 2;
            e16[ki][hi + 0] = *reinterpret_cast<uint32_t*>(&h0);
            e16[ki][hi + 1] = *reinterpret_cast<uint32_t*>(&h1);
        }
        __syncthreads();

        // cooperative coalesced E store (16KB tile)
#pragma unroll
        for (int i = 0; i < 4; i++) {
            int c = tid + 256 * i;            // 1024 chunks of 16B
            int row = c >> 3, cb = (c & 7) * 16;
            uint4 v = *reinterpret_cast<uint4*>(smem + STG_OFF + swz128(row * 128 + cb));
            *reinterpret_cast<uint4*>(
                (char*)(Eb + (size_t)(qb * 128 + row) * SEQ + kb * 64) + cb) = v;
        }

        // ---- O += E @ V (2-term fp16) ----
#pragma unroll
        for (int ki = 0; ki < 4; ki++) {
#pragma unroll
            for (int pi = 0; pi < 4; pi++) {
                int vrow = ki * 16 + (lane & 15);
                int vbyte = pi * 32 + ((lane >> 4) << 4);
                uint32_t vh4[4], vl4[4];
                ldmx4t(vh4, vbase + swz128(vrow * 128 + vbyte));
                ldmx4t(vl4, vbase + 8192 + swz128(vrow * 128 + vbyte));
                mma_hf(O[2 * pi], e16[ki], vh4);
                mma_hf(O[2 * pi], e16[ki], vl4);
                mma_hf(O[2 * pi + 1], e16[ki], vh4 + 2);
                mma_hf(O[2 * pi + 1], e16[ki], vl4 + 2);
            }
        }
        __syncthreads();
        if (kb + 2 < NKB) load_kv(kb + 2, kb & 1);
    }

#pragma unroll
    for (int o = 1; o < 4; o <<= 1) {
        rs0 += __shfl_xor_sync(0xffffffffu, rs0, o);
        rs1 += __shfl_xor_sync(0xffffffffu, rs1, o);
    }
    float ri0 = 1.f / rs0, ri1 = 1.f / rs1;
    if ((lane & 3) == 0) {
        rinv[(size_t)bhz * SEQ + q_r0] = ri0;
        rinv[(size_t)bhz * SEQ + q_r1] = ri1;
    }

    // epilogue: O * rinv * gate -> att3 (split3 bf16 layout [hi|hi|lo])
#pragma unroll
    for (int ni = 0; ni < 8; ni++) {
        int d = ni * 8 + (lane & 3) * 2;
        int col = hh * HD + d;
#pragma unroll
        for (int rr = 0; rr < 2; rr++) {
            int qr = rr ? q_r1 : q_r0;
            float ri = rr ? ri1 : ri0;
            size_t gi = ((size_t)bb * SEQ + qr) * DIM + col;
            float2 g = *reinterpret_cast<const float2*>(gate + gi);
            float ox = O[ni][rr * 2 + 0] * ri * g.x;
            float oy = O[ni][rr * 2 + 1] * ri * g.y;
            __nv_bfloat16 hx = __float2bfloat16(ox), hy = __float2bfloat16(oy);
            __nv_bfloat162 hi2(hx, hy);
            __nv_bfloat162 lo2(__float2bfloat16(ox - __bfloat162float(hx)),
                               __float2bfloat16(oy - __bfloat162float(hy)));
            __nv_bfloat16* rowp = att3 + ((size_t)bb * SEQ + qr) * K3;
            *reinterpret_cast<__nv_bfloat162*>(rowp + col) = hi2;
            *reinterpret_cast<__nv_bfloat162*>(rowp + DIM + col) = hi2;
            *reinterpret_cast<__nv_bfloat162*>(rowp + 2 * DIM + col) = lo2;
        }
    }
}

// ======================= avg over heads (fp16 E) ===========================
__global__ __launch_bounds__(512) void avg_kernel(
    const __half* __restrict__ E, const float* __restrict__ rinv,
    float* __restrict__ avg)
{
    int bq = blockIdx.x;
    int b = bq >> 11, q = bq & 2047;
    int k4 = threadIdx.x * 4;
    float4 s = {0.f, 0.f, 0.f, 0.f};
#pragma unroll
    for (int h = 0; h < NH; h++) {
        float ri = rinv[(size_t)(b * NH + h) * SEQ + q] * (1.f / NH);
        const __half2* p = reinterpret_cast<const __half2*>(
            E + ((size_t)(b * NH + h) * SEQ + q) * SEQ + k4);
        float2 f0 = __half22float2(p[0]);
        float2 f1 = __half22float2(p[1]);
        s.x += f0.x * ri; s.y += f0.y * ri;
        s.z += f1.x * ri; s.w += f1.y * ri;
    }
    *reinterpret_cast<float4*>(avg + (size_t)bq * SEQ + k4) = s;
}

// ---------------- launch -----------------------------------------------------
extern "C" void kernel_launch(void* const* d_in, const int* in_sizes, int n_in,
                              void* d_out, int out_size)
{
    (void)in_sizes; (void)n_in; (void)out_size;
    const float* x    = (const float*)d_in[0];
    const float* mask = (const float*)d_in[1];
    const unsigned char* pad = (const unsigned char*)d_in[2];
    const float* Wq = (const float*)d_in[3];
    const float* bq = (const float*)d_in[4];
    const float* Wk = (const float*)d_in[5];
    const float* bk = (const float*)d_in[6];
    const float* Wv = (const float*)d_in[7];
    const float* bv = (const float*)d_in[8];
    const float* Wg = (const float*)d_in[9];
    const float* bg = (const float*)d_in[10];
    const float* Wo = (const float*)d_in[11];
    const float* bo = (const float*)d_in[12];
    float* out = (float*)d_out;

    float *gate, *rinv;
    __half *E, *qkh, *maskh;
    __nv_bfloat16 *a3, *w3;
    cudaGetSymbolAddress((void**)&gate, g_gate);
    cudaGetSymbolAddress((void**)&E, g_E);
    cudaGetSymbolAddress((void**)&rinv, g_rinv);
    cudaGetSymbolAddress((void**)&a3, g_a3);
    cudaGetSymbolAddress((void**)&w3, g_w3);
    cudaGetSymbolAddress((void**)&qkh, g_qkh);
    cudaGetSymbolAddress((void**)&maskh, g_maskh);

    static bool init0 = false;
    static cudaStream_t s2;
    static cudaEvent_t ev0, ev1, ev2, ev3;
    if (!init0) {
        cudaFuncSetAttribute(gemm_hmma, cudaFuncAttributeMaxDynamicSharedMemorySize, GEMM_SMEM);
        cudaFuncSetAttribute(flash_attn, cudaFuncAttributeMaxDynamicSharedMemorySize, FL_SMEM);
        cudaStreamCreateWithFlags(&s2, cudaStreamNonBlocking);
        cudaEventCreateWithFlags(&ev0, cudaEventDisableTiming);
        cudaEventCreateWithFlags(&ev1, cudaEventDisableTiming);
        cudaEventCreateWithFlags(&ev2, cudaEventDisableTiming);
        cudaEventCreateWithFlags(&ev3, cudaEventDisableTiming);
        init0 = true;
    }

    // fork: mask conversion on s2, overlapped with projections
    cudaEventRecord(ev0, 0);
    cudaStreamWaitEvent(s2, ev0, 0);
    mask_to_half<<<(SEQ * SEQ) / 1024, 256, 0, s2>>>(mask, maskh);
    cudaEventRecord(ev1, s2);

    // main: conversions + QKVG projections
    split3_f32<<<(MTOT * DIM) / 1024, 256>>>(x, a3);
    transpose_split3_all<<<dim3(DIM / 32, DIM / 32, 5), dim3(32, 32)>>>(
        Wq, Wk, Wv, Wg, Wo, w3);
    gemm_hmma<<<dim3(DIM / 128, MTOT / 128, 4), 256, GEMM_SMEM>>>(
        a3, w3, bq, bk, bv, bg, gate, qkh, nullptr, 0);

    // join mask, then flash
    cudaStreamWaitEvent(0, ev1, 0);
    flash_attn<<<dim3(1, SEQ / 128, NBH), 256, FL_SMEM>>>(
        qkh, maskh, pad, gate, E, rinv, a3);

    // fork: avg on s2 || O-projection on main
    cudaEventRecord(ev2, 0);
    cudaStreamWaitEvent(s2, ev2, 0);
    avg_kernel<<<BB * SEQ, 512, 0, s2>>>(E, rinv, out + (size_t)MTOT * DIM);
    cudaEventRecord(ev3, s2);

    gemm_hmma<<<dim3(DIM / 128, MTOT / 128, 1), 256, GEMM_SMEM>>>(
        a3, w3 + 4ull * DIM * K3, bo, bo, bo, bo, nullptr, nullptr, out, 1);

    // join avg back into main stream
    cudaStreamWaitEvent(0, ev3, 0);
}

// round 8
// speedup vs baseline: 4.9592x; 1.2864x over previous
#include <cuda_runtime.h>
#include <cuda_bf16.h>
#include <cuda_fp16.h>
#include <math.h>
#include <stdint.h>

// Fixed problem shape
#define BB 2
#define SEQ 2048
#define DIM 1024
#define NH 16
#define HD 64
#define MTOT (BB * SEQ)            // 4096
#define K2 (2 * DIM)               // 2048 (2-term fp16 split layout)
#define NSTG2 32                   // K2 / 64
#define NBH (BB * NH)              // 32

// ---------------- scratch ----------------------------------------------------
__device__ float g_gate[(size_t)MTOT * DIM];           // sigmoid gate fp32
__device__ __half g_E[(size_t)NBH * SEQ * SEQ];        // unnormalized exp, fp16
__device__ float g_rinv[(size_t)NBH * SEQ];            // 1/rowsum
__device__ __half g_a2[(size_t)MTOT * K2];             // [Ah|Al] fp16 (x, then att)
__device__ __half g_w2[5ull * DIM * K2];               // [Wh|Wh] fp16 N-major
__device__ __half g_qkh[3ull * 2 * NBH * SEQ * HD];    // q,k,v per-head hi/lo fp16
__device__ __half g_maskh[(size_t)SEQ * SEQ];          // mask fp16

// ======================= helpers ===========================================
__device__ __forceinline__ uint32_t smem_u32(const void* p) {
    uint32_t a;
    asm("{ .reg .u64 t; cvta.to.shared.u64 t, %1; cvt.u32.u64 %0, t; }"
        : "=r"(a) : "l"(p));
    return a;
}
__device__ __forceinline__ uint32_t swz128(uint32_t o) { return o ^ ((o >> 3) & 0x70); }

__device__ __forceinline__ void cp_async16(uint32_t dst, const void* src) {
    asm volatile("cp.async.cg.shared.global [%0], [%1], 16;" :: "r"(dst), "l"(src));
}
#define CP_COMMIT() asm volatile("cp.async.commit_group;" ::: "memory")
#define CP_WAIT(n)  asm volatile("cp.async.wait_group %0;" :: "n"(n) : "memory")

__device__ __forceinline__ void ldmx4(uint32_t* r, uint32_t addr) {
    asm volatile("ldmatrix.sync.aligned.m8n8.x4.shared.b16 {%0,%1,%2,%3}, [%4];"
                 : "=r"(r[0]), "=r"(r[1]), "=r"(r[2]), "=r"(r[3]) : "r"(addr));
}
__device__ __forceinline__ void ldmx4t(uint32_t* r, uint32_t addr) {
    asm volatile("ldmatrix.sync.aligned.m8n8.x4.trans.shared.b16 {%0,%1,%2,%3}, [%4];"
                 : "=r"(r[0]), "=r"(r[1]), "=r"(r[2]), "=r"(r[3]) : "r"(addr));
}
__device__ __forceinline__ void mma_hf(float* c, const uint32_t* a, const uint32_t* b) {
    asm volatile(
        "mma.sync.aligned.m16n8k16.row.col.f32.f16.f16.f32 "
        "{%0,%1,%2,%3}, {%4,%5,%6,%7}, {%8,%9}, {%0,%1,%2,%3};"
        : "+f"(c[0]), "+f"(c[1]), "+f"(c[2]), "+f"(c[3])
        : "r"(a[0]), "r"(a[1]), "r"(a[2]), "r"(a[3]), "r"(b[0]), "r"(b[1]));
}

// ======================= conversions =======================================
// x fp32 [M,DIM] -> A2 fp16 [M,K2] rows = [hi | lo]
__global__ __launch_bounds__(256) void split2_f32(const float* __restrict__ x,
                                                  __half* __restrict__ A2) {
    size_t i = ((size_t)blockIdx.x * 256 + threadIdx.x) * 4;
    size_t m = i / DIM, k = i % DIM;
    float4 v = *reinterpret_cast<const float4*>(x + i);
    __half h0 = __float2half_rn(v.x), h1 = __float2half_rn(v.y);
    __half h2 = __float2half_rn(v.z), h3 = __float2half_rn(v.w);
    __half2 hA(h0, h1), hB(h2, h3);
    __half2 lA(__float2half_rn(v.x - __half2float(h0)),
               __float2half_rn(v.y - __half2float(h1)));
    __half2 lB(__float2half_rn(v.z - __half2float(h2)),
               __float2half_rn(v.w - __half2float(h3)));
    __half* row = A2 + m * K2;
    *reinterpret_cast<__half2*>(row + k) = hA;
    *reinterpret_cast<__half2*>(row + k + 2) = hB;
    *reinterpret_cast<__half2*>(row + DIM + k) = lA;
    *reinterpret_cast<__half2*>(row + DIM + k + 2) = lB;
}

// W[k][n] fp32 -> W2[z][n][K2] = [Wh | Wh] fp16 (duplicated)
__global__ __launch_bounds__(1024) void transpose_split2_all(
    const float* __restrict__ W0, const float* __restrict__ W1,
    const float* __restrict__ W2p, const float* __restrict__ W3p,
    const float* __restrict__ W4, __half* __restrict__ out)
{
    __shared__ float t[32][33];
    int z = blockIdx.z;
    const float* W = (z == 0) ? W0 : (z == 1) ? W1 : (z == 2) ? W2p : (z == 3) ? W3p : W4;
    int tx = threadIdx.x, ty = threadIdx.y;
    int k0 = blockIdx.y * 32, n0 = blockIdx.x * 32;
    t[ty][tx] = W[(size_t)(k0 + ty) * DIM + n0 + tx];
    __syncthreads();
    float v = t[tx][ty];
    __half h = __float2half_rn(v);
    __half* row = out + (size_t)z * DIM * K2 + (size_t)(n0 + ty) * K2;
    row[k0 + tx] = h;
    row[DIM + k0 + tx] = h;
}

__global__ __launch_bounds__(256) void mask_to_half(const float* __restrict__ m,
                                                    __half* __restrict__ mh) {
    size_t i = ((size_t)blockIdx.x * 256 + threadIdx.x) * 4;
    float4 v = *reinterpret_cast<const float4*>(m + i);
    __half2 a = __floats2half2_rn(v.x, v.y);
    __half2 b = __floats2half2_rn(v.z, v.w);
    *reinterpret_cast<__half2*>(mh + i) = a;
    *reinterpret_cast<__half2*>(mh + i + 2) = b;
}

// ======================= HMMA 2-term fp16 dense GEMM (3-stage) =============
// mode 0: z<3 -> qkh per-head (z==0 scaled 0.125, hi+lo; z==1,2 hi only);
//         z==3 -> sigmoid fp32 gate
// mode 1: plain fp32 + bias -> fOut
#define GEMM_SMEM (96 * 1024)
__global__ __launch_bounds__(256, 2) void gemm_hmma(
    const __half* __restrict__ A2, const __half* __restrict__ W2base,
    const float* b0, const float* b1, const float* b2, const float* b3,
    float* __restrict__ gateOut, __half* __restrict__ qkhOut,
    float* __restrict__ fOut, int mode)
{
    extern __shared__ char smem[];
    const uint32_t sb = smem_u32(smem);
    const int tid = threadIdx.x;
    const int wid = tid >> 5, lane = tid & 31;
    const int wm = wid & 3, wn = wid >> 2;
    const int z = blockIdx.z;
    const int m0 = blockIdx.y * 128, n0 = blockIdx.x * 128;

    const __half* W2 = W2base + (size_t)z * DIM * K2;
    const float* bias = (z == 0) ? b0 : (z == 1) ? b1 : (z == 2) ? b2 : b3;

    const char* gA = (const char*)(A2 + (size_t)m0 * K2);
    const char* gB = (const char*)(W2 + (size_t)n0 * K2);

    auto load_stage = [&](int s) {
        const uint32_t base = sb + (s % 3) * 32768;
        const int kb = s * 128;
#pragma unroll
        for (int i = 0; i < 4; i++) {
            int c = tid + 256 * i;
            int row = c >> 3, cb = (c & 7) * 16;
            uint32_t d = swz128(row * 128 + cb);
            size_t src = (size_t)row * (K2 * 2) + kb + cb;
            cp_async16(base + d, gA + src);
            cp_async16(base + 16384 + d, gB + src);
        }
        CP_COMMIT();
    };

    float acc[2][8][4];
#pragma unroll
    for (int mi = 0; mi < 2; mi++)
#pragma unroll
        for (int ni = 0; ni < 8; ni++)
#pragma unroll
            for (int j = 0; j < 4; j++) acc[mi][ni][j] = 0.f;

    load_stage(0);
    load_stage(1);
    load_stage(2);

    for (int s = 0; s < NSTG2; s++) {
        if (s >= NSTG2 - 1)      { CP_WAIT(0); }
        else if (s == NSTG2 - 2) { CP_WAIT(1); }
        else                     { CP_WAIT(2); }
        __syncthreads();
        const uint32_t abase = sb + (s % 3) * 32768;
        const uint32_t bbase = abase + 16384;
#pragma unroll
        for (int ki = 0; ki < 4; ki++) {
            uint32_t a[2][4];
#pragma unroll
            for (int mi = 0; mi < 2; mi++) {
                int row = wm * 32 + mi * 16 + (lane & 15);
                int kb = ki * 32 + ((lane >> 4) << 4);
                ldmx4(a[mi], abase + swz128(row * 128 + kb));
            }
#pragma unroll
            for (int pi = 0; pi < 4; pi++) {
                int nrow = wn * 64 + pi * 16 + ((lane >> 4) << 3) + (lane & 7);
                int kb = ki * 32 + ((lane >> 3) & 1) * 16;
                uint32_t b[4];
                ldmx4(b, bbase + swz128(nrow * 128 + kb));
#pragma unroll
                for (int mi = 0; mi < 2; mi++) {
                    mma_hf(acc[mi][2 * pi], a[mi], b);
                    mma_hf(acc[mi][2 * pi + 1], a[mi], b + 2);
                }
            }
        }
        __syncthreads();
        if (s + 3 < NSTG2) load_stage(s + 3);
    }

    const int rbase = m0 + wm * 32;
    const int cbase = n0 + wn * 64;
#pragma unroll
    for (int mi = 0; mi < 2; mi++) {
#pragma unroll
        for (int ni = 0; ni < 8; ni++) {
            int row = rbase + mi * 16 + (lane >> 2);
            int col = cbase + ni * 8 + (lane & 3) * 2;
            float bx = bias[col], by = bias[col + 1];
            float vx0 = acc[mi][ni][0] + bx, vy0 = acc[mi][ni][1] + by;
            float vx1 = acc[mi][ni][2] + bx, vy1 = acc[mi][ni][3] + by;
            if (mode == 1) {
                *reinterpret_cast<float2*>(&fOut[(size_t)row * DIM + col]) =
                    make_float2(vx0, vy0);
                *reinterpret_cast<float2*>(&fOut[(size_t)(row + 8) * DIM + col]) =
                    make_float2(vx1, vy1);
            } else if (z == 3) {
                float2 g0 = {1.f / (1.f + expf(-vx0)), 1.f / (1.f + expf(-vy0))};
                float2 g1 = {1.f / (1.f + expf(-vx1)), 1.f / (1.f + expf(-vy1))};
                *reinterpret_cast<float2*>(&gateOut[(size_t)row * DIM + col]) = g0;
                *reinterpret_cast<float2*>(&gateOut[(size_t)(row + 8) * DIM + col]) = g1;
            } else {
                if (z == 0) { vx0 *= 0.125f; vy0 *= 0.125f; vx1 *= 0.125f; vy1 *= 0.125f; }
                int h = col >> 6, d = col & 63;
#pragma unroll
                for (int rr = 0; rr < 2; rr++) {
                    int rw = row + rr * 8;
                    float vx = rr ? vx1 : vx0, vy = rr ? vy1 : vy0;
                    int bh = (rw >> 11) * NH + h, s = rw & 2047;
                    __half hx = __float2half_rn(vx), hy = __float2half_rn(vy);
                    __half2 hi2(hx, hy);
                    size_t bi = ((((size_t)z * 2 + 0) * NBH + bh) * SEQ + s) * HD + d;
                    *reinterpret_cast<__half2*>(qkhOut + bi) = hi2;
                    if (z == 0) {   // only Q needs the lo term
                        __half2 lo2(__float2half_rn(vx - __half2float(hx)),
                                    __float2half_rn(vy - __half2float(hy)));
                        size_t bl = ((((size_t)z * 2 + 1) * NBH + bh) * SEQ + s) * HD + d;
                        *reinterpret_cast<__half2*>(qkhOut + bl) = lo2;
                    }
                }
            }
        }
    }
}

// ======================= fused flash attention v4 ==========================
// QK 2-term (Qhi,Qlo @ Khi), PV 1-term (Vhi). k-tile 64, 3 stages.
// smem: QH 0 (16K), QL 16K | stage s at 32K+s*16K: KH +0 (8K), VH +8K
//       | E staging 80K (16K). Total 96K, 2 CTAs/SM.
#define FL_SMEM (96 * 1024)
#define STG_OFF (80 * 1024)
#define NKB 32
__global__ __launch_bounds__(256, 2) void flash_attn(
    const __half* __restrict__ qkh, const __half* __restrict__ maskh,
    const unsigned char* __restrict__ pad, const float* __restrict__ gate,
    __half* __restrict__ E, float* __restrict__ rinv,
    __half* __restrict__ att2)
{
    extern __shared__ char smem[];
    const uint32_t sb = smem_u32(smem);
    const int tid = threadIdx.x;
    const int w = tid >> 5, lane = tid & 31;
    const int bhz = blockIdx.z, qb = blockIdx.y;
    const int bb = bhz >> 4, hh = bhz & 15;

    const __half* Qh = qkh + ((size_t)(0 * 2 + 0) * NBH + bhz) * SEQ * HD;
    const __half* Ql = qkh + ((size_t)(0 * 2 + 1) * NBH + bhz) * SEQ * HD;
    const __half* Kh = qkh + ((size_t)(1 * 2 + 0) * NBH + bhz) * SEQ * HD;
    const __half* Vh = qkh + ((size_t)(2 * 2 + 0) * NBH + bhz) * SEQ * HD;

#pragma unroll
    for (int i = 0; i < 4; i++) {
        int c = tid + 256 * i;
        int row = c >> 3, cb = (c & 7) * 16;
        uint32_t d = swz128(row * 128 + cb);
        size_t src = (size_t)(qb * 128 + row) * (HD * 2) + cb;
        cp_async16(sb + d, (const char*)Qh + src);
        cp_async16(sb + 16384 + d, (const char*)Ql + src);
    }
    auto load_kv = [&](int kb, int st) {
        const uint32_t base = sb + 32768 + st * 16384;
#pragma unroll
        for (int i = 0; i < 2; i++) {
            int c = tid + 256 * i;
            int row = c >> 3, cb = (c & 7) * 16;
            uint32_t d = swz128(row * 128 + cb);
            size_t src = (size_t)(kb * 64 + row) * (HD * 2) + cb;
            cp_async16(base + d, (const char*)Kh + src);
            cp_async16(base + 8192 + d, (const char*)Vh + src);
        }
        CP_COMMIT();
    };
    load_kv(0, 0);     // group 0 also covers Q loads
    load_kv(1, 1);
    load_kv(2, 2);

    float O[8][4];
#pragma unroll
    for (int ni = 0; ni < 8; ni++)
#pragma unroll
        for (int j = 0; j < 4; j++) O[ni][j] = 0.f;

    float rs0 = 0.f, rs1 = 0.f;
    const int r0l = w * 16 + (lane >> 2);
    const int q_r0 = qb * 128 + r0l;
    const int q_r1 = q_r0 + 8;
    __half* Eb = E + (size_t)bhz * SEQ * SEQ;

    for (int kb = 0; kb < NKB; kb++) {
        if (kb >= NKB - 1)      { CP_WAIT(0); }
        else if (kb == NKB - 2) { CP_WAIT(1); }
        else                    { CP_WAIT(2); }
        __syncthreads();
        const uint32_t kbase = sb + 32768 + (kb % 3) * 16384;
        const uint32_t vbase = kbase + 8192;

        // prefetch mask (fp16) — independent of MMA results
        uint32_t m0r[8], m1r[8];
#pragma unroll
        for (int ni = 0; ni < 8; ni++) {
            int kcol = kb * 64 + ni * 8 + (lane & 3) * 2;
            m0r[ni] = *reinterpret_cast<const uint32_t*>(maskh + (size_t)q_r0 * SEQ + kcol);
            m1r[ni] = *reinterpret_cast<const uint32_t*>(maskh + (size_t)q_r1 * SEQ + kcol);
        }

        // ---- S = Q K^T (2-term fp16: (Qh+Ql) @ Kh) ----
        float acc[8][4];
#pragma unroll
        for (int ni = 0; ni < 8; ni++)
#pragma unroll
            for (int j = 0; j < 4; j++) acc[ni][j] = 0.f;

#pragma unroll
        for (int ki = 0; ki < 4; ki++) {
            uint32_t ah[4], al[4];
            {
                int row = w * 16 + (lane & 15);
                int kbyte = ki * 32 + ((lane >> 4) << 4);
                ldmx4(ah, sb + swz128(row * 128 + kbyte));
                ldmx4(al, sb + 16384 + swz128(row * 128 + kbyte));
            }
#pragma unroll
            for (int pi = 0; pi < 4; pi++) {
                int nrow = pi * 16 + ((lane >> 4) << 3) + (lane & 7);
                int kbyte = ki * 32 + ((lane >> 3) & 1) * 16;
                uint32_t bh4[4];
                ldmx4(bh4, kbase + swz128(nrow * 128 + kbyte));
                mma_hf(acc[2 * pi], ah, bh4);
                mma_hf(acc[2 * pi], al, bh4);
                mma_hf(acc[2 * pi + 1], ah, bh4 + 2);
                mma_hf(acc[2 * pi + 1], al, bh4 + 2);
            }
        }

        // ---- epilogue: exp, rowsum, stage E in smem, pack A-fragments ----
        uint32_t e16[4][4];
#pragma unroll
        for (int ni = 0; ni < 8; ni++) {
            int kc2 = ni * 8 + (lane & 3) * 2;
            int kcol = kb * 64 + kc2;
            uchar2 pd = *reinterpret_cast<const uchar2*>(pad + bb * SEQ + kcol);
            float2 m0 = __half22float2(*reinterpret_cast<__half2*>(&m0r[ni]));
            float2 m1 = __half22float2(*reinterpret_cast<__half2*>(&m1r[ni]));
            float e00 = pd.x ? 0.f : __expf(acc[ni][0] + m0.x);
            float e01 = pd.y ? 0.f : __expf(acc[ni][1] + m0.y);
            float e10 = pd.x ? 0.f : __expf(acc[ni][2] + m1.x);
            float e11 = pd.y ? 0.f : __expf(acc[ni][3] + m1.y);
            rs0 += e00 + e01;
            rs1 += e10 + e11;
            __half2 h0 = __floats2half2_rn(e00, e01);
            __half2 h1 = __floats2half2_rn(e10, e11);
            *reinterpret_cast<__half2*>(smem + STG_OFF + swz128(r0l * 128 + kc2 * 2)) = h0;
            *reinterpret_cast<__half2*>(smem + STG_OFF + swz128((r0l + 8) * 128 + kc2 * 2)) = h1;
            int ki = ni >> 1, hi = (ni & 1) * 2;
            e16[ki][hi + 0] = *reinterpret_cast<uint32_t*>(&h0);
            e16[ki][hi + 1] = *reinterpret_cast<uint32_t*>(&h1);
        }
        __syncthreads();

        // cooperative coalesced E store (16KB tile)
#pragma unroll
        for (int i = 0; i < 4; i++) {
            int c = tid + 256 * i;
            int row = c >> 3, cb = (c & 7) * 16;
            uint4 v = *reinterpret_cast<uint4*>(smem + STG_OFF + swz128(row * 128 + cb));
            *reinterpret_cast<uint4*>(
                (char*)(Eb + (size_t)(qb * 128 + row) * SEQ + kb * 64) + cb) = v;
        }

        // ---- O += E @ V (1-term fp16) ----
#pragma unroll
        for (int ki = 0; ki < 4; ki++) {
#pragma unroll
            for (int pi = 0; pi < 4; pi++) {
                int vrow = ki * 16 + (lane & 15);
                int vbyte = pi * 32 + ((lane >> 4) << 4);
                uint32_t vh4[4];
                ldmx4t(vh4, vbase + swz128(vrow * 128 + vbyte));
                mma_hf(O[2 * pi], e16[ki], vh4);
                mma_hf(O[2 * pi + 1], e16[ki], vh4 + 2);
            }
        }
        __syncthreads();
        if (kb + 3 < NKB) load_kv(kb + 3, (kb + 3) % 3);
    }

#pragma unroll
    for (int o = 1; o < 4; o <<= 1) {
        rs0 += __shfl_xor_sync(0xffffffffu, rs0, o);
        rs1 += __shfl_xor_sync(0xffffffffu, rs1, o);
    }
    float ri0 = 1.f / rs0, ri1 = 1.f / rs1;
    if ((lane & 3) == 0) {
        rinv[(size_t)bhz * SEQ + q_r0] = ri0;
        rinv[(size_t)bhz * SEQ + q_r1] = ri1;
    }

    // epilogue: O * rinv * gate -> att2 (split2 fp16 layout [hi|lo])
#pragma unroll
    for (int ni = 0; ni < 8; ni++) {
        int d = ni * 8 + (lane & 3) * 2;
        int col = hh * HD + d;
#pragma unroll
        for (int rr = 0; rr < 2; rr++) {
            int qr = rr ? q_r1 : q_r0;
            float ri = rr ? ri1 : ri0;
            size_t gi = ((size_t)bb * SEQ + qr) * DIM + col;
            float2 g = *reinterpret_cast<const float2*>(gate + gi);
            float ox = O[ni][rr * 2 + 0] * ri * g.x;
            float oy = O[ni][rr * 2 + 1] * ri * g.y;
            __half hx = __float2half_rn(ox), hy = __float2half_rn(oy);
            __half2 hi2(hx, hy);
            __half2 lo2(__float2half_rn(ox - __half2float(hx)),
                        __float2half_rn(oy - __half2float(hy)));
            __half* rowp = att2 + ((size_t)bb * SEQ + qr) * K2;
            *reinterpret_cast<__half2*>(rowp + col) = hi2;
            *reinterpret_cast<__half2*>(rowp + DIM + col) = lo2;
        }
    }
}

// ======================= avg over heads (fp16 E) ===========================
__global__ __launch_bounds__(512) void avg_kernel(
    const __half* __restrict__ E, const float* __restrict__ rinv,
    float* __restrict__ avg)
{
    int bq = blockIdx.x;
    int b = bq >> 11, q = bq & 2047;
    int k4 = threadIdx.x * 4;
    float4 s = {0.f, 0.f, 0.f, 0.f};
#pragma unroll
    for (int h = 0; h < NH; h++) {
        float ri = rinv[(size_t)(b * NH + h) * SEQ + q] * (1.f / NH);
        const __half2* p = reinterpret_cast<const __half2*>(
            E + ((size_t)(b * NH + h) * SEQ + q) * SEQ + k4);
        float2 f0 = __half22float2(p[0]);
        float2 f1 = __half22float2(p[1]);
        s.x += f0.x * ri; s.y += f0.y * ri;
        s.z += f1.x * ri; s.w += f1.y * ri;
    }
    *reinterpret_cast<float4*>(avg + (size_t)bq * SEQ + k4) = s;
}

// ---------------- launch -----------------------------------------------------
extern "C" void kernel_launch(void* const* d_in, const int* in_sizes, int n_in,
                              void* d_out, int out_size)
{
    (void)in_sizes; (void)n_in; (void)out_size;
    const float* x    = (const float*)d_in[0];
    const float* mask = (const float*)d_in[1];
    const unsigned char* pad = (const unsigned char*)d_in[2];
    const float* Wq = (const float*)d_in[3];
    const float* bq = (const float*)d_in[4];
    const float* Wk = (const float*)d_in[5];
    const float* bk = (const float*)d_in[6];
    const float* Wv = (const float*)d_in[7];
    const float* bv = (const float*)d_in[8];
    const float* Wg = (const float*)d_in[9];
    const float* bg = (const float*)d_in[10];
    const float* Wo = (const float*)d_in[11];
    const float* bo = (const float*)d_in[12];
    float* out = (float*)d_out;

    float *gate, *rinv;
    __half *E, *qkh, *maskh, *a2, *w2;
    cudaGetSymbolAddress((void**)&gate, g_gate);
    cudaGetSymbolAddress((void**)&E, g_E);
    cudaGetSymbolAddress((void**)&rinv, g_rinv);
    cudaGetSymbolAddress((void**)&a2, g_a2);
    cudaGetSymbolAddress((void**)&w2, g_w2);
    cudaGetSymbolAddress((void**)&qkh, g_qkh);
    cudaGetSymbolAddress((void**)&maskh, g_maskh);

    static bool init0 = false;
    static cudaStream_t s2;
    static cudaEvent_t ev0, ev1, ev2, ev3;
    if (!init0) {
        cudaFuncSetAttribute(gemm_hmma, cudaFuncAttributeMaxDynamicSharedMemorySize, GEMM_SMEM);
        cudaFuncSetAttribute(flash_attn, cudaFuncAttributeMaxDynamicSharedMemorySize, FL_SMEM);
        cudaStreamCreateWithFlags(&s2, cudaStreamNonBlocking);
        cudaEventCreateWithFlags(&ev0, cudaEventDisableTiming);
        cudaEventCreateWithFlags(&ev1, cudaEventDisableTiming);
        cudaEventCreateWithFlags(&ev2, cudaEventDisableTiming);
        cudaEventCreateWithFlags(&ev3, cudaEventDisableTiming);
        init0 = true;
    }

    // fork: mask conversion on s2, overlapped with projections
    cudaEventRecord(ev0, 0);
    cudaStreamWaitEvent(s2, ev0, 0);
    mask_to_half<<<(SEQ * SEQ) / 1024, 256, 0, s2>>>(mask, maskh);
    cudaEventRecord(ev1, s2);

    // main: conversions + QKVG projections
    split2_f32<<<(MTOT * DIM) / 1024, 256>>>(x, a2);
    transpose_split2_all<<<dim3(DIM / 32, DIM / 32, 5), dim3(32, 32)>>>(
        Wq, Wk, Wv, Wg, Wo, w2);
    gemm_hmma<<<dim3(DIM / 128, MTOT / 128, 4), 256, GEMM_SMEM>>>(
        a2, w2, bq, bk, bv, bg, gate, qkh, nullptr, 0);

    // join mask, then flash
    cudaStreamWaitEvent(0, ev1, 0);
    flash_attn<<<dim3(1, SEQ / 128, NBH), 256, FL_SMEM>>>(
        qkh, maskh, pad, gate, E, rinv, a2);

    // fork: avg on s2 || O-projection on main
    cudaEventRecord(ev2, 0);
    cudaStreamWaitEvent(s2, ev2, 0);
    avg_kernel<<<BB * SEQ, 512, 0, s2>>>(E, rinv, out + (size_t)MTOT * DIM);
    cudaEventRecord(ev3, s2);

    gemm_hmma<<<dim3(DIM / 128, MTOT / 128, 1), 256, GEMM_SMEM>>>(
        a2, w2 + 4ull * DIM * K2, bo, bo, bo, bo, nullptr, nullptr, out, 1);

    // join avg back into main stream
    cudaStreamWaitEvent(0, ev3, 0);
}

// round 9
// speedup vs baseline: 5.2610x; 1.0609x over previous
#include <cuda_runtime.h>
#include <cuda_bf16.h>
#include <cuda_fp16.h>
#include <math.h>
#include <stdint.h>

// Fixed problem shape
#define BB 2
#define SEQ 2048
#define DIM 1024
#define NH 16
#define HD 64
#define MTOT (BB * SEQ)            // 4096
#define K2 (2 * DIM)               // 2048 (2-term fp16 split layout)
#define NSTG2 32                   // K2 / 64
#define NBH (BB * NH)              // 32

// ---------------- scratch ----------------------------------------------------
__device__ float g_gate[(size_t)MTOT * DIM];           // sigmoid gate fp32
__device__ __half g_E[(size_t)NBH * SEQ * SEQ];        // unnormalized exp, fp16
__device__ float g_rinv[(size_t)NBH * SEQ];            // 1/rowsum
__device__ __half g_a2[(size_t)MTOT * K2];             // [Ah|Al] fp16 (x, then att)
__device__ __half g_w2[5ull * DIM * K2];               // [Wh|Wh] fp16 N-major
__device__ __half g_qkh[3ull * 2 * NBH * SEQ * HD];    // q,k,v per-head hi/lo fp16
__device__ __half g_maskh[(size_t)SEQ * SEQ];          // mask fp16

// ======================= helpers ===========================================
__device__ __forceinline__ uint32_t smem_u32(const void* p) {
    uint32_t a;
    asm("{ .reg .u64 t; cvta.to.shared.u64 t, %1; cvt.u32.u64 %0, t; }"
        : "=r"(a) : "l"(p));
    return a;
}
__device__ __forceinline__ uint32_t swz128(uint32_t o) { return o ^ ((o >> 3) & 0x70); }

__device__ __forceinline__ void cp_async16(uint32_t dst, const void* src) {
    asm volatile("cp.async.cg.shared.global [%0], [%1], 16;" :: "r"(dst), "l"(src));
}
#define CP_COMMIT() asm volatile("cp.async.commit_group;" ::: "memory")
#define CP_WAIT(n)  asm volatile("cp.async.wait_group %0;" :: "n"(n) : "memory")

__device__ __forceinline__ void ldmx4(uint32_t* r, uint32_t addr) {
    asm volatile("ldmatrix.sync.aligned.m8n8.x4.shared.b16 {%0,%1,%2,%3}, [%4];"
                 : "=r"(r[0]), "=r"(r[1]), "=r"(r[2]), "=r"(r[3]) : "r"(addr));
}
__device__ __forceinline__ void ldmx4t(uint32_t* r, uint32_t addr) {
    asm volatile("ldmatrix.sync.aligned.m8n8.x4.trans.shared.b16 {%0,%1,%2,%3}, [%4];"
                 : "=r"(r[0]), "=r"(r[1]), "=r"(r[2]), "=r"(r[3]) : "r"(addr));
}
__device__ __forceinline__ void mma_hf(float* c, const uint32_t* a, const uint32_t* b) {
    asm volatile(
        "mma.sync.aligned.m16n8k16.row.col.f32.f16.f16.f32 "
        "{%0,%1,%2,%3}, {%4,%5,%6,%7}, {%8,%9}, {%0,%1,%2,%3};"
        : "+f"(c[0]), "+f"(c[1]), "+f"(c[2]), "+f"(c[3])
        : "r"(a[0]), "r"(a[1]), "r"(a[2]), "r"(a[3]), "r"(b[0]), "r"(b[1]));
}

// ======================= conversions =======================================
// x fp32 [M,DIM] -> A2 fp16 [M,K2] rows = [hi | lo]
__global__ __launch_bounds__(256) void split2_f32(const float* __restrict__ x,
                                                  __half* __restrict__ A2) {
    size_t i = ((size_t)blockIdx.x * 256 + threadIdx.x) * 4;
    size_t m = i / DIM, k = i % DIM;
    float4 v = *reinterpret_cast<const float4*>(x + i);
    __half h0 = __float2half_rn(v.x), h1 = __float2half_rn(v.y);
    __half h2 = __float2half_rn(v.z), h3 = __float2half_rn(v.w);
    __half2 hA(h0, h1), hB(h2, h3);
    __half2 lA(__float2half_rn(v.x - __half2float(h0)),
               __float2half_rn(v.y - __half2float(h1)));
    __half2 lB(__float2half_rn(v.z - __half2float(h2)),
               __float2half_rn(v.w - __half2float(h3)));
    __half* row = A2 + m * K2;
    *reinterpret_cast<__half2*>(row + k) = hA;
    *reinterpret_cast<__half2*>(row + k + 2) = hB;
    *reinterpret_cast<__half2*>(row + DIM + k) = lA;
    *reinterpret_cast<__half2*>(row + DIM + k + 2) = lB;
}

// W[k][n] fp32 -> W2[z][n][K2] = [Wh | Wh] fp16 (duplicated)
__global__ __launch_bounds__(1024) void transpose_split2_all(
    const float* __restrict__ W0, const float* __restrict__ W1,
    const float* __restrict__ W2p, const float* __restrict__ W3p,
    const float* __restrict__ W4, __half* __restrict__ out)
{
    __shared__ float t[32][33];
    int z = blockIdx.z;
    const float* W = (z == 0) ? W0 : (z == 1) ? W1 : (z == 2) ? W2p : (z == 3) ? W3p : W4;
    int tx = threadIdx.x, ty = threadIdx.y;
    int k0 = blockIdx.y * 32, n0 = blockIdx.x * 32;
    t[ty][tx] = W[(size_t)(k0 + ty) * DIM + n0 + tx];
    __syncthreads();
    float v = t[tx][ty];
    __half h = __float2half_rn(v);
    __half* row = out + (size_t)z * DIM * K2 + (size_t)(n0 + ty) * K2;
    row[k0 + tx] = h;
    row[DIM + k0 + tx] = h;
}

__global__ __launch_bounds__(256) void mask_to_half(const float* __restrict__ m,
                                                    __half* __restrict__ mh) {
    size_t i = ((size_t)blockIdx.x * 256 + threadIdx.x) * 4;
    float4 v = *reinterpret_cast<const float4*>(m + i);
    __half2 a = __floats2half2_rn(v.x, v.y);
    __half2 b = __floats2half2_rn(v.z, v.w);
    *reinterpret_cast<__half2*>(mh + i) = a;
    *reinterpret_cast<__half2*>(mh + i + 2) = b;
}

// ======================= HMMA fp16 dense GEMM (3-stage, per-z K terms) =====
// mode 0: z==0 Q (2-term, scaled 0.125, hi+lo out), z==1 K (1-term, hi out),
//         z==2 V (2-term, hi out), z==3 gate (1-term, sigmoid fp32)
// mode 1: plain fp32 + bias -> fOut (2-term)
#define GEMM_SMEM (96 * 1024)
__global__ __launch_bounds__(256, 2) void gemm_hmma(
    const __half* __restrict__ A2, const __half* __restrict__ W2base,
    const float* b0, const float* b1, const float* b2, const float* b3,
    float* __restrict__ gateOut, __half* __restrict__ qkhOut,
    float* __restrict__ fOut, int mode)
{
    extern __shared__ char smem[];
    const uint32_t sb = smem_u32(smem);
    const int tid = threadIdx.x;
    const int wid = tid >> 5, lane = tid & 31;
    const int wm = wid & 3, wn = wid >> 2;
    const int z = blockIdx.z;
    const int m0 = blockIdx.y * 128, n0 = blockIdx.x * 128;

    // per-z K-half count: Q,V,O-proj 2-term; K,gate 1-term
    const int nstg = (mode == 1 || z == 0 || z == 2) ? NSTG2 : (NSTG2 / 2);

    const __half* W2 = W2base + (size_t)z * DIM * K2;
    const float* bias = (z == 0) ? b0 : (z == 1) ? b1 : (z == 2) ? b2 : b3;

    const char* gA = (const char*)(A2 + (size_t)m0 * K2);
    const char* gB = (const char*)(W2 + (size_t)n0 * K2);

    auto load_stage = [&](int s) {
        const uint32_t base = sb + (s % 3) * 32768;
        const int kb = s * 128;
#pragma unroll
        for (int i = 0; i < 4; i++) {
            int c = tid + 256 * i;
            int row = c >> 3, cb = (c & 7) * 16;
            uint32_t d = swz128(row * 128 + cb);
            size_t src = (size_t)row * (K2 * 2) + kb + cb;
            cp_async16(base + d, gA + src);
            cp_async16(base + 16384 + d, gB + src);
        }
        CP_COMMIT();
    };

    float acc[2][8][4];
#pragma unroll
    for (int mi = 0; mi < 2; mi++)
#pragma unroll
        for (int ni = 0; ni < 8; ni++)
#pragma unroll
            for (int j = 0; j < 4; j++) acc[mi][ni][j] = 0.f;

    load_stage(0);
    load_stage(1);
    load_stage(2);

    for (int s = 0; s < nstg; s++) {
        if (s >= nstg - 1)      { CP_WAIT(0); }
        else if (s == nstg - 2) { CP_WAIT(1); }
        else                    { CP_WAIT(2); }
        __syncthreads();
        const uint32_t abase = sb + (s % 3) * 32768;
        const uint32_t bbase = abase + 16384;
#pragma unroll
        for (int ki = 0; ki < 4; ki++) {
            uint32_t a[2][4];
#pragma unroll
            for (int mi = 0; mi < 2; mi++) {
                int row = wm * 32 + mi * 16 + (lane & 15);
                int kb = ki * 32 + ((lane >> 4) << 4);
                ldmx4(a[mi], abase + swz128(row * 128 + kb));
            }
#pragma unroll
            for (int pi = 0; pi < 4; pi++) {
                int nrow = wn * 64 + pi * 16 + ((lane >> 4) << 3) + (lane & 7);
                int kb = ki * 32 + ((lane >> 3) & 1) * 16;
                uint32_t b[4];
                ldmx4(b, bbase + swz128(nrow * 128 + kb));
#pragma unroll
                for (int mi = 0; mi < 2; mi++) {
                    mma_hf(acc[mi][2 * pi], a[mi], b);
                    mma_hf(acc[mi][2 * pi + 1], a[mi], b + 2);
                }
            }
        }
        __syncthreads();
        if (s + 3 < nstg) load_stage(s + 3);
    }

    const int rbase = m0 + wm * 32;
    const int cbase = n0 + wn * 64;
#pragma unroll
    for (int mi = 0; mi < 2; mi++) {
#pragma unroll
        for (int ni = 0; ni < 8; ni++) {
            int row = rbase + mi * 16 + (lane >> 2);
            int col = cbase + ni * 8 + (lane & 3) * 2;
            float bx = bias[col], by = bias[col + 1];
            float vx0 = acc[mi][ni][0] + bx, vy0 = acc[mi][ni][1] + by;
            float vx1 = acc[mi][ni][2] + bx, vy1 = acc[mi][ni][3] + by;
            if (mode == 1) {
                *reinterpret_cast<float2*>(&fOut[(size_t)row * DIM + col]) =
                    make_float2(vx0, vy0);
                *reinterpret_cast<float2*>(&fOut[(size_t)(row + 8) * DIM + col]) =
                    make_float2(vx1, vy1);
            } else if (z == 3) {
                float2 g0 = {1.f / (1.f + expf(-vx0)), 1.f / (1.f + expf(-vy0))};
                float2 g1 = {1.f / (1.f + expf(-vx1)), 1.f / (1.f + expf(-vy1))};
                *reinterpret_cast<float2*>(&gateOut[(size_t)row * DIM + col]) = g0;
                *reinterpret_cast<float2*>(&gateOut[(size_t)(row + 8) * DIM + col]) = g1;
            } else {
                if (z == 0) { vx0 *= 0.125f; vy0 *= 0.125f; vx1 *= 0.125f; vy1 *= 0.125f; }
                int h = col >> 6, d = col & 63;
#pragma unroll
                for (int rr = 0; rr < 2; rr++) {
                    int rw = row + rr * 8;
                    float vx = rr ? vx1 : vx0, vy = rr ? vy1 : vy0;
                    int bh = (rw >> 11) * NH + h, s = rw & 2047;
                    __half hx = __float2half_rn(vx), hy = __float2half_rn(vy);
                    __half2 hi2(hx, hy);
                    size_t bi = ((((size_t)z * 2 + 0) * NBH + bh) * SEQ + s) * HD + d;
                    *reinterpret_cast<__half2*>(qkhOut + bi) = hi2;
                    if (z == 0) {   // only Q needs the lo term
                        __half2 lo2(__float2half_rn(vx - __half2float(hx)),
                                    __float2half_rn(vy - __half2float(hy)));
                        size_t bl = ((((size_t)z * 2 + 1) * NBH + bh) * SEQ + s) * HD + d;
                        *reinterpret_cast<__half2*>(qkhOut + bl) = lo2;
                    }
                }
            }
        }
    }
}

// ======================= fused flash attention v4 ==========================
// QK 2-term (Qhi,Qlo @ Khi), PV 1-term (Vhi). k-tile 64, 3 stages.
// smem: QH 0 (16K), QL 16K | stage s at 32K+s*16K: KH +0 (8K), VH +8K
//       | E staging 80K (16K). Total 96K, 2 CTAs/SM.
#define FL_SMEM (96 * 1024)
#define STG_OFF (80 * 1024)
#define NKB 32
__global__ __launch_bounds__(256, 2) void flash_attn(
    const __half* __restrict__ qkh, const __half* __restrict__ maskh,
    const unsigned char* __restrict__ pad, const float* __restrict__ gate,
    __half* __restrict__ E, float* __restrict__ rinv,
    __half* __restrict__ att2)
{
    extern __shared__ char smem[];
    const uint32_t sb = smem_u32(smem);
    const int tid = threadIdx.x;
    const int w = tid >> 5, lane = tid & 31;
    const int bhz = blockIdx.z, qb = blockIdx.y;
    const int bb = bhz >> 4, hh = bhz & 15;

    const __half* Qh = qkh + ((size_t)(0 * 2 + 0) * NBH + bhz) * SEQ * HD;
    const __half* Ql = qkh + ((size_t)(0 * 2 + 1) * NBH + bhz) * SEQ * HD;
    const __half* Kh = qkh + ((size_t)(1 * 2 + 0) * NBH + bhz) * SEQ * HD;
    const __half* Vh = qkh + ((size_t)(2 * 2 + 0) * NBH + bhz) * SEQ * HD;

#pragma unroll
    for (int i = 0; i < 4; i++) {
        int c = tid + 256 * i;
        int row = c >> 3, cb = (c & 7) * 16;
        uint32_t d = swz128(row * 128 + cb);
        size_t src = (size_t)(qb * 128 + row) * (HD * 2) + cb;
        cp_async16(sb + d, (const char*)Qh + src);
        cp_async16(sb + 16384 + d, (const char*)Ql + src);
    }
    auto load_kv = [&](int kb, int st) {
        const uint32_t base = sb + 32768 + st * 16384;
#pragma unroll
        for (int i = 0; i < 2; i++) {
            int c = tid + 256 * i;
            int row = c >> 3, cb = (c & 7) * 16;
            uint32_t d = swz128(row * 128 + cb);
            size_t src = (size_t)(kb * 64 + row) * (HD * 2) + cb;
            cp_async16(base + d, (const char*)Kh + src);
            cp_async16(base + 8192 + d, (const char*)Vh + src);
        }
        CP_COMMIT();
    };
    load_kv(0, 0);     // group 0 also covers Q loads
    load_kv(1, 1);
    load_kv(2, 2);

    float O[8][4];
#pragma unroll
    for (int ni = 0; ni < 8; ni++)
#pragma unroll
        for (int j = 0; j < 4; j++) O[ni][j] = 0.f;

    float rs0 = 0.f, rs1 = 0.f;
    const int r0l = w * 16 + (lane >> 2);
    const int q_r0 = qb * 128 + r0l;
    const int q_r1 = q_r0 + 8;
    __half* Eb = E + (size_t)bhz * SEQ * SEQ;

    for (int kb = 0; kb < NKB; kb++) {
        if (kb >= NKB - 1)      { CP_WAIT(0); }
        else if (kb == NKB - 2) { CP_WAIT(1); }
        else                    { CP_WAIT(2); }
        __syncthreads();
        const uint32_t kbase = sb + 32768 + (kb % 3) * 16384;
        const uint32_t vbase = kbase + 8192;

        // prefetch mask (fp16) — independent of MMA results
        uint32_t m0r[8], m1r[8];
#pragma unroll
        for (int ni = 0; ni < 8; ni++) {
            int kcol = kb * 64 + ni * 8 + (lane & 3) * 2;
            m0r[ni] = *reinterpret_cast<const uint32_t*>(maskh + (size_t)q_r0 * SEQ + kcol);
            m1r[ni] = *reinterpret_cast<const uint32_t*>(maskh + (size_t)q_r1 * SEQ + kcol);
        }

        // ---- S = Q K^T (2-term fp16: (Qh+Ql) @ Kh) ----
        float acc[8][4];
#pragma unroll
        for (int ni = 0; ni < 8; ni++)
#pragma unroll
            for (int j = 0; j < 4; j++) acc[ni][j] = 0.f;

#pragma unroll
        for (int ki = 0; ki < 4; ki++) {
            uint32_t ah[4], al[4];
            {
                int row = w * 16 + (lane & 15);
                int kbyte = ki * 32 + ((lane >> 4) << 4);
                ldmx4(ah, sb + swz128(row * 128 + kbyte));
                ldmx4(al, sb + 16384 + swz128(row * 128 + kbyte));
            }
#pragma unroll
            for (int pi = 0; pi < 4; pi++) {
                int nrow = pi * 16 + ((lane >> 4) << 3) + (lane & 7);
                int kbyte = ki * 32 + ((lane >> 3) & 1) * 16;
                uint32_t bh4[4];
                ldmx4(bh4, kbase + swz128(nrow * 128 + kbyte));
                mma_hf(acc[2 * pi], ah, bh4);
                mma_hf(acc[2 * pi], al, bh4);
                mma_hf(acc[2 * pi + 1], ah, bh4 + 2);
                mma_hf(acc[2 * pi + 1], al, bh4 + 2);
            }
        }

        // ---- epilogue: exp, rowsum, stage E in smem, pack A-fragments ----
        uint32_t e16[4][4];
#pragma unroll
        for (int ni = 0; ni < 8; ni++) {
            int kc2 = ni * 8 + (lane & 3) * 2;
            int kcol = kb * 64 + kc2;
            uchar2 pd = *reinterpret_cast<const uchar2*>(pad + bb * SEQ + kcol);
            float2 m0 = __half22float2(*reinterpret_cast<__half2*>(&m0r[ni]));
            float2 m1 = __half22float2(*reinterpret_cast<__half2*>(&m1r[ni]));
            float e00 = pd.x ? 0.f : __expf(acc[ni][0] + m0.x);
            float e01 = pd.y ? 0.f : __expf(acc[ni][1] + m0.y);
            float e10 = pd.x ? 0.f : __expf(acc[ni][2] + m1.x);
            float e11 = pd.y ? 0.f : __expf(acc[ni][3] + m1.y);
            rs0 += e00 + e01;
            rs1 += e10 + e11;
            __half2 h0 = __floats2half2_rn(e00, e01);
            __half2 h1 = __floats2half2_rn(e10, e11);
            *reinterpret_cast<__half2*>(smem + STG_OFF + swz128(r0l * 128 + kc2 * 2)) = h0;
            *reinterpret_cast<__half2*>(smem + STG_OFF + swz128((r0l + 8) * 128 + kc2 * 2)) = h1;
            int ki = ni >> 1, hi = (ni & 1) * 2;
            e16[ki][hi + 0] = *reinterpret_cast<uint32_t*>(&h0);
            e16[ki][hi + 1] = *reinterpret_cast<uint32_t*>(&h1);
        }
        __syncthreads();

        // cooperative coalesced E store (16KB tile)
#pragma unroll
        for (int i = 0; i < 4; i++) {
            int c = tid + 256 * i;
            int row = c >> 3, cb = (c & 7) * 16;
            uint4 v = *reinterpret_cast<uint4*>(smem + STG_OFF + swz128(row * 128 + cb));
            *reinterpret_cast<uint4*>(
                (char*)(Eb + (size_t)(qb * 128 + row) * SEQ + kb * 64) + cb) = v;
        }

        // ---- O += E @ V (1-term fp16) ----
#pragma unroll
        for (int ki = 0; ki < 4; ki++) {
#pragma unroll
            for (int pi = 0; pi < 4; pi++) {
                int vrow = ki * 16 + (lane & 15);
                int vbyte = pi * 32 + ((lane >> 4) << 4);
                uint32_t vh4[4];
                ldmx4t(vh4, vbase + swz128(vrow * 128 + vbyte));
                mma_hf(O[2 * pi], e16[ki], vh4);
                mma_hf(O[2 * pi + 1], e16[ki], vh4 + 2);
            }
        }
        __syncthreads();
        if (kb + 3 < NKB) load_kv(kb + 3, (kb + 3) % 3);
    }

#pragma unroll
    for (int o = 1; o < 4; o <<= 1) {
        rs0 += __shfl_xor_sync(0xffffffffu, rs0, o);
        rs1 += __shfl_xor_sync(0xffffffffu, rs1, o);
    }
    float ri0 = 1.f / rs0, ri1 = 1.f / rs1;
    if ((lane & 3) == 0) {
        rinv[(size_t)bhz * SEQ + q_r0] = ri0;
        rinv[(size_t)bhz * SEQ + q_r1] = ri1;
    }

    // epilogue: O * rinv * gate -> att2 (split2 fp16 layout [hi|lo])
#pragma unroll
    for (int ni = 0; ni < 8; ni++) {
        int d = ni * 8 + (lane & 3) * 2;
        int col = hh * HD + d;
#pragma unroll
        for (int rr = 0; rr < 2; rr++) {
            int qr = rr ? q_r1 : q_r0;
            float ri = rr ? ri1 : ri0;
            size_t gi = ((size_t)bb * SEQ + qr) * DIM + col;
            float2 g = *reinterpret_cast<const float2*>(gate + gi);
            float ox = O[ni][rr * 2 + 0] * ri * g.x;
            float oy = O[ni][rr * 2 + 1] * ri * g.y;
            __half hx = __float2half_rn(ox), hy = __float2half_rn(oy);
            __half2 hi2(hx, hy);
            __half2 lo2(__float2half_rn(ox - __half2float(hx)),
                        __float2half_rn(oy - __half2float(hy)));
            __half* rowp = att2 + ((size_t)bb * SEQ + qr) * K2;
            *reinterpret_cast<__half2*>(rowp + col) = hi2;
            *reinterpret_cast<__half2*>(rowp + DIM + col) = lo2;
        }
    }
}

// ======================= avg over heads (fp16 E) ===========================
__global__ __launch_bounds__(512) void avg_kernel(
    const __half* __restrict__ E, const float* __restrict__ rinv,
    float* __restrict__ avg)
{
    int bq = blockIdx.x;
    int b = bq >> 11, q = bq & 2047;
    int k4 = threadIdx.x * 4;
    float4 s = {0.f, 0.f, 0.f, 0.f};
#pragma unroll
    for (int h = 0; h < NH; h++) {
        float ri = rinv[(size_t)(b * NH + h) * SEQ + q] * (1.f / NH);
        const __half2* p = reinterpret_cast<const __half2*>(
            E + ((size_t)(b * NH + h) * SEQ + q) * SEQ + k4);
        float2 f0 = __half22float2(p[0]);
        float2 f1 = __half22float2(p[1]);
        s.x += f0.x * ri; s.y += f0.y * ri;
        s.z += f1.x * ri; s.w += f1.y * ri;
    }
    *reinterpret_cast<float4*>(avg + (size_t)bq * SEQ + k4) = s;
}

// ---------------- launch -----------------------------------------------------
extern "C" void kernel_launch(void* const* d_in, const int* in_sizes, int n_in,
                              void* d_out, int out_size)
{
    (void)in_sizes; (void)n_in; (void)out_size;
    const float* x    = (const float*)d_in[0];
    const float* mask = (const float*)d_in[1];
    const unsigned char* pad = (const unsigned char*)d_in[2];
    const float* Wq = (const float*)d_in[3];
    const float* bq = (const float*)d_in[4];
    const float* Wk = (const float*)d_in[5];
    const float* bk = (const float*)d_in[6];
    const float* Wv = (const float*)d_in[7];
    const float* bv = (const float*)d_in[8];
    const float* Wg = (const float*)d_in[9];
    const float* bg = (const float*)d_in[10];
    const float* Wo = (const float*)d_in[11];
    const float* bo = (const float*)d_in[12];
    float* out = (float*)d_out;

    float *gate, *rinv;
    __half *E, *qkh, *maskh, *a2, *w2;
    cudaGetSymbolAddress((void**)&gate, g_gate);
    cudaGetSymbolAddress((void**)&E, g_E);
    cudaGetSymbolAddress((void**)&rinv, g_rinv);
    cudaGetSymbolAddress((void**)&a2, g_a2);
    cudaGetSymbolAddress((void**)&w2, g_w2);
    cudaGetSymbolAddress((void**)&qkh, g_qkh);
    cudaGetSymbolAddress((void**)&maskh, g_maskh);

    static bool init0 = false;
    static cudaStream_t s2;
    static cudaEvent_t ev0, evT, ev1, ev2, ev3;
    if (!init0) {
        cudaFuncSetAttribute(gemm_hmma, cudaFuncAttributeMaxDynamicSharedMemorySize, GEMM_SMEM);
        cudaFuncSetAttribute(flash_attn, cudaFuncAttributeMaxDynamicSharedMemorySize, FL_SMEM);
        cudaStreamCreateWithFlags(&s2, cudaStreamNonBlocking);
        cudaEventCreateWithFlags(&ev0, cudaEventDisableTiming);
        cudaEventCreateWithFlags(&evT, cudaEventDisableTiming);
        cudaEventCreateWithFlags(&ev1, cudaEventDisableTiming);
        cudaEventCreateWithFlags(&ev2, cudaEventDisableTiming);
        cudaEventCreateWithFlags(&ev3, cudaEventDisableTiming);
        init0 = true;
    }

    // fork: weight transpose + mask conversion on s2 || x split on main
    cudaEventRecord(ev0, 0);
    cudaStreamWaitEvent(s2, ev0, 0);
    transpose_split2_all<<<dim3(DIM / 32, DIM / 32, 5), dim3(32, 32), 0, s2>>>(
        Wq, Wk, Wv, Wg, Wo, w2);
    cudaEventRecord(evT, s2);
    mask_to_half<<<(SEQ * SEQ) / 1024, 256, 0, s2>>>(mask, maskh);
    cudaEventRecord(ev1, s2);

    split2_f32<<<(MTOT * DIM) / 1024, 256>>>(x, a2);

    // QKVG projections need w2 (evT) + a2
    cudaStreamWaitEvent(0, evT, 0);
    gemm_hmma<<<dim3(DIM / 128, MTOT / 128, 4), 256, GEMM_SMEM>>>(
        a2, w2, bq, bk, bv, bg, gate, qkh, nullptr, 0);

    // join mask, then flash
    cudaStreamWaitEvent(0, ev1, 0);
    flash_attn<<<dim3(1, SEQ / 128, NBH), 256, FL_SMEM>>>(
        qkh, maskh, pad, gate, E, rinv, a2);

    // fork: avg on s2 || O-projection on main
    cudaEventRecord(ev2, 0);
    cudaStreamWaitEvent(s2, ev2, 0);
    avg_kernel<<<BB * SEQ, 512, 0, s2>>>(E, rinv, out + (size_t)MTOT * DIM);
    cudaEventRecord(ev3, s2);

    gemm_hmma<<<dim3(DIM / 128, MTOT / 128, 1), 256, GEMM_SMEM>>>(
        a2, w2 + 4ull * DIM * K2, bo, bo, bo, bo, nullptr, nullptr, out, 1);

    // join avg back into main stream
    cudaStreamWaitEvent(0, ev3, 0);
}

// round 10
// speedup vs baseline: 5.4823x; 1.0421x over previous
#include <cuda_runtime.h>
#include <cuda_bf16.h>
#include <cuda_fp16.h>
#include <math.h>
#include <stdint.h>

// Fixed problem shape
#define BB 2
#define SEQ 2048
#define DIM 1024
#define NH 16
#define HD 64
#define MTOT (BB * SEQ)            // 4096
#define K2 (2 * DIM)               // 2048 (2-term fp16 split layout)
#define NSTG2 32                   // K2 / 64
#define NBH (BB * NH)              // 32
#define LOG2E 1.44269504f

// ---------------- scratch ----------------------------------------------------
__device__ float g_gate[(size_t)MTOT * DIM];           // sigmoid gate fp32
__device__ __half g_E[(size_t)NBH * SEQ * SEQ];        // unnormalized exp, fp16
__device__ float g_rinv[(size_t)NBH * SEQ];            // 1/rowsum
__device__ __half g_a2[(size_t)MTOT * K2];             // [Ah|Al] fp16 (x, then att)
__device__ __half g_w2[5ull * DIM * K2];               // [Wh|Wh] fp16 N-major
__device__ __half g_qkh[3ull * 2 * NBH * SEQ * HD];    // q,k,v per-head hi/lo fp16
__device__ __half g_maskh[(size_t)SEQ * SEQ];          // mask * log2e, fp16

// ======================= helpers ===========================================
__device__ __forceinline__ uint32_t smem_u32(const void* p) {
    uint32_t a;
    asm("{ .reg .u64 t; cvta.to.shared.u64 t, %1; cvt.u32.u64 %0, t; }"
        : "=r"(a) : "l"(p));
    return a;
}
__device__ __forceinline__ uint32_t swz128(uint32_t o) { return o ^ ((o >> 3) & 0x70); }

__device__ __forceinline__ void cp_async16(uint32_t dst, const void* src) {
    asm volatile("cp.async.cg.shared.global [%0], [%1], 16;" :: "r"(dst), "l"(src));
}
#define CP_COMMIT() asm volatile("cp.async.commit_group;" ::: "memory")
#define CP_WAIT(n)  asm volatile("cp.async.wait_group %0;" :: "n"(n) : "memory")

__device__ __forceinline__ void ldmx4(uint32_t* r, uint32_t addr) {
    asm volatile("ldmatrix.sync.aligned.m8n8.x4.shared.b16 {%0,%1,%2,%3}, [%4];"
                 : "=r"(r[0]), "=r"(r[1]), "=r"(r[2]), "=r"(r[3]) : "r"(addr));
}
__device__ __forceinline__ void ldmx4t(uint32_t* r, uint32_t addr) {
    asm volatile("ldmatrix.sync.aligned.m8n8.x4.trans.shared.b16 {%0,%1,%2,%3}, [%4];"
                 : "=r"(r[0]), "=r"(r[1]), "=r"(r[2]), "=r"(r[3]) : "r"(addr));
}
__device__ __forceinline__ void mma_hf(float* c, const uint32_t* a, const uint32_t* b) {
    asm volatile(
        "mma.sync.aligned.m16n8k16.row.col.f32.f16.f16.f32 "
        "{%0,%1,%2,%3}, {%4,%5,%6,%7}, {%8,%9}, {%0,%1,%2,%3};"
        : "+f"(c[0]), "+f"(c[1]), "+f"(c[2]), "+f"(c[3])
        : "r"(a[0]), "r"(a[1]), "r"(a[2]), "r"(a[3]), "r"(b[0]), "r"(b[1]));
}
__device__ __forceinline__ uint32_t h2ex2(uint32_t s) {
    uint32_t r;
    asm("ex2.approx.f16x2 %0, %1;" : "=r"(r) : "r"(s));
    return r;
}

// ======================= conversions =======================================
// x fp32 [M,DIM] -> A2 fp16 [M,K2] rows = [hi | lo]
__global__ __launch_bounds__(256) void split2_f32(const float* __restrict__ x,
                                                  __half* __restrict__ A2) {
    size_t i = ((size_t)blockIdx.x * 256 + threadIdx.x) * 4;
    size_t m = i / DIM, k = i % DIM;
    float4 v = *reinterpret_cast<const float4*>(x + i);
    __half h0 = __float2half_rn(v.x), h1 = __float2half_rn(v.y);
    __half h2 = __float2half_rn(v.z), h3 = __float2half_rn(v.w);
    __half2 hA(h0, h1), hB(h2, h3);
    __half2 lA(__float2half_rn(v.x - __half2float(h0)),
               __float2half_rn(v.y - __half2float(h1)));
    __half2 lB(__float2half_rn(v.z - __half2float(h2)),
               __float2half_rn(v.w - __half2float(h3)));
    __half* row = A2 + m * K2;
    *reinterpret_cast<__half2*>(row + k) = hA;
    *reinterpret_cast<__half2*>(row + k + 2) = hB;
    *reinterpret_cast<__half2*>(row + DIM + k) = lA;
    *reinterpret_cast<__half2*>(row + DIM + k + 2) = lB;
}

// W[k][n] fp32 -> W2[z][n][K2] = [Wh | Wh] fp16 (duplicated)
__global__ __launch_bounds__(1024) void transpose_split2_all(
    const float* __restrict__ W0, const float* __restrict__ W1,
    const float* __restrict__ W2p, const float* __restrict__ W3p,
    const float* __restrict__ W4, __half* __restrict__ out)
{
    __shared__ float t[32][33];
    int z = blockIdx.z;
    const float* W = (z == 0) ? W0 : (z == 1) ? W1 : (z == 2) ? W2p : (z == 3) ? W3p : W4;
    int tx = threadIdx.x, ty = threadIdx.y;
    int k0 = blockIdx.y * 32, n0 = blockIdx.x * 32;
    t[ty][tx] = W[(size_t)(k0 + ty) * DIM + n0 + tx];
    __syncthreads();
    float v = t[tx][ty];
    __half h = __float2half_rn(v);
    __half* row = out + (size_t)z * DIM * K2 + (size_t)(n0 + ty) * K2;
    row[k0 + tx] = h;
    row[DIM + k0 + tx] = h;
}

// mask -> fp16, pre-multiplied by log2(e)
__global__ __launch_bounds__(256) void mask_to_half(const float* __restrict__ m,
                                                    __half* __restrict__ mh) {
    size_t i = ((size_t)blockIdx.x * 256 + threadIdx.x) * 4;
    float4 v = *reinterpret_cast<const float4*>(m + i);
    __half2 a = __floats2half2_rn(v.x * LOG2E, v.y * LOG2E);
    __half2 b = __floats2half2_rn(v.z * LOG2E, v.w * LOG2E);
    *reinterpret_cast<__half2*>(mh + i) = a;
    *reinterpret_cast<__half2*>(mh + i + 2) = b;
}

// ======================= HMMA fp16 dense GEMM (3-stage, per-z K terms) =====
// mode 0: z==0 Q (2-term, scaled 0.125*log2e, hi+lo out), z==1 K (1-term, hi),
//         z==2 V (2-term, hi out), z==3 gate (1-term, sigmoid fp32)
// mode 1: plain fp32 + bias -> fOut (2-term)
#define GEMM_SMEM (96 * 1024)
__global__ __launch_bounds__(256, 2) void gemm_hmma(
    const __half* __restrict__ A2, const __half* __restrict__ W2base,
    const float* b0, const float* b1, const float* b2, const float* b3,
    float* __restrict__ gateOut, __half* __restrict__ qkhOut,
    float* __restrict__ fOut, int mode)
{
    extern __shared__ char smem[];
    const uint32_t sb = smem_u32(smem);
    const int tid = threadIdx.x;
    const int wid = tid >> 5, lane = tid & 31;
    const int wm = wid & 3, wn = wid >> 2;
    const int z = blockIdx.z;
    const int m0 = blockIdx.y * 128, n0 = blockIdx.x * 128;

    // per-z K-half count: Q,V,O-proj 2-term; K,gate 1-term
    const int nstg = (mode == 1 || z == 0 || z == 2) ? NSTG2 : (NSTG2 / 2);

    const __half* W2 = W2base + (size_t)z * DIM * K2;
    const float* bias = (z == 0) ? b0 : (z == 1) ? b1 : (z == 2) ? b2 : b3;

    const char* gA = (const char*)(A2 + (size_t)m0 * K2);
    const char* gB = (const char*)(W2 + (size_t)n0 * K2);

    auto load_stage = [&](int s) {
        const uint32_t base = sb + (s % 3) * 32768;
        const int kb = s * 128;
#pragma unroll
        for (int i = 0; i < 4; i++) {
            int c = tid + 256 * i;
            int row = c >> 3, cb = (c & 7) * 16;
            uint32_t d = swz128(row * 128 + cb);
            size_t src = (size_t)row * (K2 * 2) + kb + cb;
            cp_async16(base + d, gA + src);
            cp_async16(base + 16384 + d, gB + src);
        }
        CP_COMMIT();
    };

    float acc[2][8][4];
#pragma unroll
    for (int mi = 0; mi < 2; mi++)
#pragma unroll
        for (int ni = 0; ni < 8; ni++)
#pragma unroll
            for (int j = 0; j < 4; j++) acc[mi][ni][j] = 0.f;

    load_stage(0);
    load_stage(1);
    load_stage(2);

    for (int s = 0; s < nstg; s++) {
        if (s >= nstg - 1)      { CP_WAIT(0); }
        else if (s == nstg - 2) { CP_WAIT(1); }
        else                    { CP_WAIT(2); }
        __syncthreads();
        const uint32_t abase = sb + (s % 3) * 32768;
        const uint32_t bbase = abase + 16384;
#pragma unroll
        for (int ki = 0; ki < 4; ki++) {
            uint32_t a[2][4];
#pragma unroll
            for (int mi = 0; mi < 2; mi++) {
                int row = wm * 32 + mi * 16 + (lane & 15);
                int kb = ki * 32 + ((lane >> 4) << 4);
                ldmx4(a[mi], abase + swz128(row * 128 + kb));
            }
#pragma unroll
            for (int pi = 0; pi < 4; pi++) {
                int nrow = wn * 64 + pi * 16 + ((lane >> 4) << 3) + (lane & 7);
                int kb = ki * 32 + ((lane >> 3) & 1) * 16;
                uint32_t b[4];
                ldmx4(b, bbase + swz128(nrow * 128 + kb));
#pragma unroll
                for (int mi = 0; mi < 2; mi++) {
                    mma_hf(acc[mi][2 * pi], a[mi], b);
                    mma_hf(acc[mi][2 * pi + 1], a[mi], b + 2);
                }
            }
        }
        __syncthreads();
        if (s + 3 < nstg) load_stage(s + 3);
    }

    const int rbase = m0 + wm * 32;
    const int cbase = n0 + wn * 64;
#pragma unroll
    for (int mi = 0; mi < 2; mi++) {
#pragma unroll
        for (int ni = 0; ni < 8; ni++) {
            int row = rbase + mi * 16 + (lane >> 2);
            int col = cbase + ni * 8 + (lane & 3) * 2;
            float bx = bias[col], by = bias[col + 1];
            float vx0 = acc[mi][ni][0] + bx, vy0 = acc[mi][ni][1] + by;
            float vx1 = acc[mi][ni][2] + bx, vy1 = acc[mi][ni][3] + by;
            if (mode == 1) {
                *reinterpret_cast<float2*>(&fOut[(size_t)row * DIM + col]) =
                    make_float2(vx0, vy0);
                *reinterpret_cast<float2*>(&fOut[(size_t)(row + 8) * DIM + col]) =
                    make_float2(vx1, vy1);
            } else if (z == 3) {
                float2 g0 = {1.f / (1.f + expf(-vx0)), 1.f / (1.f + expf(-vy0))};
                float2 g1 = {1.f / (1.f + expf(-vx1)), 1.f / (1.f + expf(-vy1))};
                *reinterpret_cast<float2*>(&gateOut[(size_t)row * DIM + col]) = g0;
                *reinterpret_cast<float2*>(&gateOut[(size_t)(row + 8) * DIM + col]) = g1;
            } else {
                if (z == 0) {   // fold 1/8 and log2(e) into q
                    const float sc = 0.125f * LOG2E;
                    vx0 *= sc; vy0 *= sc; vx1 *= sc; vy1 *= sc;
                }
                int h = col >> 6, d = col & 63;
#pragma unroll
                for (int rr = 0; rr < 2; rr++) {
                    int rw = row + rr * 8;
                    float vx = rr ? vx1 : vx0, vy = rr ? vy1 : vy0;
                    int bh = (rw >> 11) * NH + h, s = rw & 2047;
                    __half hx = __float2half_rn(vx), hy = __float2half_rn(vy);
                    __half2 hi2(hx, hy);
                    size_t bi = ((((size_t)z * 2 + 0) * NBH + bh) * SEQ + s) * HD + d;
                    *reinterpret_cast<__half2*>(qkhOut + bi) = hi2;
                    if (z == 0) {   // only Q needs the lo term
                        __half2 lo2(__float2half_rn(vx - __half2float(hx)),
                                    __float2half_rn(vy - __half2float(hy)));
                        size_t bl = ((((size_t)z * 2 + 1) * NBH + bh) * SEQ + s) * HD + d;
                        *reinterpret_cast<__half2*>(qkhOut + bl) = lo2;
                    }
                }
            }
        }
    }
}

// ======================= fused flash attention v5 ==========================
// QK 2-term in log2 domain, E = ex2.approx.f16x2(S + mask), PV 1-term.
// k-tile 64, 3 stages. smem: QH 0 (16K), QL 16K | stages 32K+s*16K |
// E staging 80K (16K). Total 96K, 2 CTAs/SM. 2 barriers per k-tile.
#define FL_SMEM (96 * 1024)
#define STG_OFF (80 * 1024)
#define NKB 32
__global__ __launch_bounds__(256, 2) void flash_attn(
    const __half* __restrict__ qkh, const __half* __restrict__ maskh,
    const unsigned char* __restrict__ pad, const float* __restrict__ gate,
    __half* __restrict__ E, float* __restrict__ rinv,
    __half* __restrict__ att2)
{
    extern __shared__ char smem[];
    const uint32_t sb = smem_u32(smem);
    const int tid = threadIdx.x;
    const int w = tid >> 5, lane = tid & 31;
    const int bhz = blockIdx.z, qb = blockIdx.y;
    const int bb = bhz >> 4, hh = bhz & 15;

    const __half* Qh = qkh + ((size_t)(0 * 2 + 0) * NBH + bhz) * SEQ * HD;
    const __half* Ql = qkh + ((size_t)(0 * 2 + 1) * NBH + bhz) * SEQ * HD;
    const __half* Kh = qkh + ((size_t)(1 * 2 + 0) * NBH + bhz) * SEQ * HD;
    const __half* Vh = qkh + ((size_t)(2 * 2 + 0) * NBH + bhz) * SEQ * HD;

#pragma unroll
    for (int i = 0; i < 4; i++) {
        int c = tid + 256 * i;
        int row = c >> 3, cb = (c & 7) * 16;
        uint32_t d = swz128(row * 128 + cb);
        size_t src = (size_t)(qb * 128 + row) * (HD * 2) + cb;
        cp_async16(sb + d, (const char*)Qh + src);
        cp_async16(sb + 16384 + d, (const char*)Ql + src);
    }
    auto load_kv = [&](int kb, int st) {
        const uint32_t base = sb + 32768 + st * 16384;
#pragma unroll
        for (int i = 0; i < 2; i++) {
            int c = tid + 256 * i;
            int row = c >> 3, cb = (c & 7) * 16;
            uint32_t d = swz128(row * 128 + cb);
            size_t src = (size_t)(kb * 64 + row) * (HD * 2) + cb;
            cp_async16(base + d, (const char*)Kh + src);
            cp_async16(base + 8192 + d, (const char*)Vh + src);
        }
        CP_COMMIT();
    };
    load_kv(0, 0);     // group 0 also covers Q loads
    load_kv(1, 1);
    load_kv(2, 2);

    float O[8][4];
#pragma unroll
    for (int ni = 0; ni < 8; ni++)
#pragma unroll
        for (int j = 0; j < 4; j++) O[ni][j] = 0.f;

    float rs0 = 0.f, rs1 = 0.f;
    const int r0l = w * 16 + (lane >> 2);
    const int q_r0 = qb * 128 + r0l;
    const int q_r1 = q_r0 + 8;
    __half* Eb = E + (size_t)bhz * SEQ * SEQ;

    for (int kb = 0; kb < NKB; kb++) {
        if (kb >= NKB - 1)      { CP_WAIT(0); }
        else if (kb == NKB - 2) { CP_WAIT(1); }
        else                    { CP_WAIT(2); }
        __syncthreads();
        const uint32_t kbase = sb + 32768 + (kb % 3) * 16384;
        const uint32_t vbase = kbase + 8192;

        // prefetch mask (fp16, pre-scaled by log2e) — independent of MMAs
        uint32_t m0r[8], m1r[8];
#pragma unroll
        for (int ni = 0; ni < 8; ni++) {
            int kcol = kb * 64 + ni * 8 + (lane & 3) * 2;
            m0r[ni] = *reinterpret_cast<const uint32_t*>(maskh + (size_t)q_r0 * SEQ + kcol);
            m1r[ni] = *reinterpret_cast<const uint32_t*>(maskh + (size_t)q_r1 * SEQ + kcol);
        }

        // ---- S = Q K^T (2-term fp16, log2 domain) ----
        float acc[8][4];
#pragma unroll
        for (int ni = 0; ni < 8; ni++)
#pragma unroll
            for (int j = 0; j < 4; j++) acc[ni][j] = 0.f;

#pragma unroll
        for (int ki = 0; ki < 4; ki++) {
            uint32_t ah[4], al[4];
            {
                int row = w * 16 + (lane & 15);
                int kbyte = ki * 32 + ((lane >> 4) << 4);
                ldmx4(ah, sb + swz128(row * 128 + kbyte));
                ldmx4(al, sb + 16384 + swz128(row * 128 + kbyte));
            }
#pragma unroll
            for (int pi = 0; pi < 4; pi++) {
                int nrow = pi * 16 + ((lane >> 4) << 3) + (lane & 7);
                int kbyte = ki * 32 + ((lane >> 3) & 1) * 16;
                uint32_t bh4[4];
                ldmx4(bh4, kbase + swz128(nrow * 128 + kbyte));
                mma_hf(acc[2 * pi], ah, bh4);
                mma_hf(acc[2 * pi], al, bh4);
                mma_hf(acc[2 * pi + 1], ah, bh4 + 2);
                mma_hf(acc[2 * pi + 1], al, bh4 + 2);
            }
        }

        // ---- epilogue: E = ex2(S + mask), pad->0, rowsum, stage, pack ----
        uint32_t e16[4][4];
#pragma unroll
        for (int ni = 0; ni < 8; ni++) {
            int kc2 = ni * 8 + (lane & 3) * 2;
            int kcol = kb * 64 + kc2;
            uchar2 pd = *reinterpret_cast<const uchar2*>(pad + bb * SEQ + kcol);
            uint32_t zm = (pd.x ? 0u : 0xFFFFu) | (pd.y ? 0u : 0xFFFF0000u);
            __half2 s0 = __floats2half2_rn(acc[ni][0], acc[ni][1]);
            __half2 s1 = __floats2half2_rn(acc[ni][2], acc[ni][3]);
            s0 = __hadd2(s0, *reinterpret_cast<__half2*>(&m0r[ni]));
            s1 = __hadd2(s1, *reinterpret_cast<__half2*>(&m1r[ni]));
            uint32_t e0 = h2ex2(*reinterpret_cast<uint32_t*>(&s0)) & zm;
            uint32_t e1 = h2ex2(*reinterpret_cast<uint32_t*>(&s1)) & zm;
            float2 f0 = __half22float2(*reinterpret_cast<__half2*>(&e0));
            float2 f1 = __half22float2(*reinterpret_cast<__half2*>(&e1));
            rs0 += f0.x + f0.y;
            rs1 += f1.x + f1.y;
            *reinterpret_cast<uint32_t*>(smem + STG_OFF + swz128(r0l * 128 + kc2 * 2)) = e0;
            *reinterpret_cast<uint32_t*>(smem + STG_OFF + swz128((r0l + 8) * 128 + kc2 * 2)) = e1;
            int ki = ni >> 1, hi = (ni & 1) * 2;
            e16[ki][hi + 0] = e0;
            e16[ki][hi + 1] = e1;
        }

        // ---- O += E @ V (1-term fp16) — register fragments, no smem dep ----
#pragma unroll
        for (int ki = 0; ki < 4; ki++) {
#pragma unroll
            for (int pi = 0; pi < 4; pi++) {
                int vrow = ki * 16 + (lane & 15);
                int vbyte = pi * 32 + ((lane >> 4) << 4);
                uint32_t vh4[4];
                ldmx4t(vh4, vbase + swz128(vrow * 128 + vbyte));
                mma_hf(O[2 * pi], e16[ki], vh4);
                mma_hf(O[2 * pi + 1], e16[ki], vh4 + 2);
            }
        }
        __syncthreads();   // staging writes complete across warps

        // cooperative coalesced E store (16KB tile)
#pragma unroll
        for (int i = 0; i < 4; i++) {
            int c = tid + 256 * i;
            int row = c >> 3, cb = (c & 7) * 16;
            uint4 v = *reinterpret_cast<uint4*>(smem + STG_OFF + swz128(row * 128 + cb));
            *reinterpret_cast<uint4*>(
                (char*)(Eb + (size_t)(qb * 128 + row) * SEQ + kb * 64) + cb) = v;
        }
        if (kb + 3 < NKB) load_kv(kb + 3, (kb + 3) % 3);
    }

#pragma unroll
    for (int o = 1; o < 4; o <<= 1) {
        rs0 += __shfl_xor_sync(0xffffffffu, rs0, o);
        rs1 += __shfl_xor_sync(0xffffffffu, rs1, o);
    }
    float ri0 = 1.f / rs0, ri1 = 1.f / rs1;
    if ((lane & 3) == 0) {
        rinv[(size_t)bhz * SEQ + q_r0] = ri0;
        rinv[(size_t)bhz * SEQ + q_r1] = ri1;
    }

    // epilogue: O * rinv * gate -> att2 (split2 fp16 layout [hi|lo])
#pragma unroll
    for (int ni = 0; ni < 8; ni++) {
        int d = ni * 8 + (lane & 3) * 2;
        int col = hh * HD + d;
#pragma unroll
        for (int rr = 0; rr < 2; rr++) {
            int qr = rr ? q_r1 : q_r0;
            float ri = rr ? ri1 : ri0;
            size_t gi = ((size_t)bb * SEQ + qr) * DIM + col;
            float2 g = *reinterpret_cast<const float2*>(gate + gi);
            float ox = O[ni][rr * 2 + 0] * ri * g.x;
            float oy = O[ni][rr * 2 + 1] * ri * g.y;
            __half hx = __float2half_rn(ox), hy = __float2half_rn(oy);
            __half2 hi2(hx, hy);
            __half2 lo2(__float2half_rn(ox - __half2float(hx)),
                        __float2half_rn(oy - __half2float(hy)));
            __half* rowp = att2 + ((size_t)bb * SEQ + qr) * K2;
            *reinterpret_cast<__half2*>(rowp + col) = hi2;
            *reinterpret_cast<__half2*>(rowp + DIM + col) = lo2;
        }
    }
}

// ======================= avg over heads (fp16 E) ===========================
__global__ __launch_bounds__(512) void avg_kernel(
    const __half* __restrict__ E, const float* __restrict__ rinv,
    float* __restrict__ avg)
{
    int bq = blockIdx.x;
    int b = bq >> 11, q = bq & 2047;
    int k4 = threadIdx.x * 4;
    float4 s = {0.f, 0.f, 0.f, 0.f};
#pragma unroll
    for (int h = 0; h < NH; h++) {
        float ri = rinv[(size_t)(b * NH + h) * SEQ + q] * (1.f / NH);
        const __half2* p = reinterpret_cast<const __half2*>(
            E + ((size_t)(b * NH + h) * SEQ + q) * SEQ + k4);
        float2 f0 = __half22float2(p[0]);
        float2 f1 = __half22float2(p[1]);
        s.x += f0.x * ri; s.y += f0.y * ri;
        s.z += f1.x * ri; s.w += f1.y * ri;
    }
    *reinterpret_cast<float4*>(avg + (size_t)bq * SEQ + k4) = s;
}

// ---------------- launch -----------------------------------------------------
extern "C" void kernel_launch(void* const* d_in, const int* in_sizes, int n_in,
                              void* d_out, int out_size)
{
    (void)in_sizes; (void)n_in; (void)out_size;
    const float* x    = (const float*)d_in[0];
    const float* mask = (const float*)d_in[1];
    const unsigned char* pad = (const unsigned char*)d_in[2];
    const float* Wq = (const float*)d_in[3];
    const float* bq = (const float*)d_in[4];
    const float* Wk = (const float*)d_in[5];
    const float* bk = (const float*)d_in[6];
    const float* Wv = (const float*)d_in[7];
    const float* bv = (const float*)d_in[8];
    const float* Wg = (const float*)d_in[9];
    const float* bg = (const float*)d_in[10];
    const float* Wo = (const float*)d_in[11];
    const float* bo = (const float*)d_in[12];
    float* out = (float*)d_out;

    float *gate, *rinv;
    __half *E, *qkh, *maskh, *a2, *w2;
    cudaGetSymbolAddress((void**)&gate, g_gate);
    cudaGetSymbolAddress((void**)&E, g_E);
    cudaGetSymbolAddress((void**)&rinv, g_rinv);
    cudaGetSymbolAddress((void**)&a2, g_a2);
    cudaGetSymbolAddress((void**)&w2, g_w2);
    cudaGetSymbolAddress((void**)&qkh, g_qkh);
    cudaGetSymbolAddress((void**)&maskh, g_maskh);

    static bool init0 = false;
    static cudaStream_t s2;
    static cudaEvent_t ev0, evT, ev1, ev2, ev3;
    if (!init0) {
        cudaFuncSetAttribute(gemm_hmma, cudaFuncAttributeMaxDynamicSharedMemorySize, GEMM_SMEM);
        cudaFuncSetAttribute(flash_attn, cudaFuncAttributeMaxDynamicSharedMemorySize, FL_SMEM);
        cudaStreamCreateWithFlags(&s2, cudaStreamNonBlocking);
        cudaEventCreateWithFlags(&ev0, cudaEventDisableTiming);
        cudaEventCreateWithFlags(&evT, cudaEventDisableTiming);
        cudaEventCreateWithFlags(&ev1, cudaEventDisableTiming);
        cudaEventCreateWithFlags(&ev2, cudaEventDisableTiming);
        cudaEventCreateWithFlags(&ev3, cudaEventDisableTiming);
        init0 = true;
    }

    // fork: weight transpose + mask conversion on s2 || x split on main
    cudaEventRecord(ev0, 0);
    cudaStreamWaitEvent(s2, ev0, 0);
    transpose_split2_all<<<dim3(DIM / 32, DIM / 32, 5), dim3(32, 32), 0, s2>>>(
        Wq, Wk, Wv, Wg, Wo, w2);
    cudaEventRecord(evT, s2);
    mask_to_half<<<(SEQ * SEQ) / 1024, 256, 0, s2>>>(mask, maskh);
    cudaEventRecord(ev1, s2);

    split2_f32<<<(MTOT * DIM) / 1024, 256>>>(x, a2);

    // QKVG projections need w2 (evT) + a2
    cudaStreamWaitEvent(0, evT, 0);
    gemm_hmma<<<dim3(DIM / 128, MTOT / 128, 4), 256, GEMM_SMEM>>>(
        a2, w2, bq, bk, bv, bg, gate, qkh, nullptr, 0);

    // join mask, then flash
    cudaStreamWaitEvent(0, ev1, 0);
    flash_attn<<<dim3(1, SEQ / 128, NBH), 256, FL_SMEM>>>(
        qkh, maskh, pad, gate, E, rinv, a2);

    // fork: avg on s2 || O-projection on main
    cudaEventRecord(ev2, 0);
    cudaStreamWaitEvent(s2, ev2, 0);
    avg_kernel<<<BB * SEQ, 512, 0, s2>>>(E, rinv, out + (size_t)MTOT * DIM);
    cudaEventRecord(ev3, s2);

    gemm_hmma<<<dim3(DIM / 128, MTOT / 128, 1), 256, GEMM_SMEM>>>(
        a2, w2 + 4ull * DIM * K2, bo, bo, bo, bo, nullptr, nullptr, out, 1);

    // join avg back into main stream
    cudaStreamWaitEvent(0, ev3, 0);
}